// round 7
// baseline (speedup 1.0000x reference)
#include <cuda_runtime.h>
#include <cuda_bf16.h>
#include <cstdint>
#include <math.h>

#define Bb   2
#define Ss   1024
#define Vv   32000
#define Dd   256
#define Mm   256
#define Ww   8
#define HLh  1024
#define HCh  1024
#define Rr   (Bb*Ss)          // 2048
#define F1   (Mm+Dd)          // 512
#define F2   (Ww*Dd)          // 2048

// ======================= helpers ===========================================
__device__ __forceinline__ uint32_t smem_u32(const void* p) {
    uint32_t a;
    asm("{ .reg .u64 t; cvta.to.shared.u64 t, %1; cvt.u32.u64 %0, t; }" : "=r"(a) : "l"(p));
    return a;
}
#define CP_ASYNC16(dst, src) \
    asm volatile("cp.async.cg.shared.global [%0], [%1], 16;" :: "r"(dst), "l"(src))
#define CP_COMMIT() asm volatile("cp.async.commit_group;" ::: "memory")
#define CP_WAIT(n)  asm volatile("cp.async.wait_group %0;" :: "n"(n) : "memory")

__device__ __forceinline__ void ldmx4(uint32_t* r, uint32_t addr) {
    asm volatile("ldmatrix.sync.aligned.m8n8.x4.shared.b16 {%0,%1,%2,%3}, [%4];"
        : "=r"(r[0]), "=r"(r[1]), "=r"(r[2]), "=r"(r[3]) : "r"(addr));
}
__device__ __forceinline__ void mma16816(float* c, const uint32_t* a, const uint32_t* b) {
    asm volatile(
        "mma.sync.aligned.m16n8k16.row.col.f32.bf16.bf16.f32 "
        "{%0,%1,%2,%3}, {%4,%5,%6,%7}, {%8,%9}, {%0,%1,%2,%3};"
        : "+f"(c[0]), "+f"(c[1]), "+f"(c[2]), "+f"(c[3])
        : "r"(a[0]), "r"(a[1]), "r"(a[2]), "r"(a[3]), "r"(b[0]), "r"(b[1]));
}

// ======================= scratch ===========================================
__device__ float g_x[Rr*Dd];
__device__ float g_u[Rr*Mm];
__device__ float g_feat[Rr*F1];
__device__ float g_locin[Rr*F2];
__device__ float g_lin[(size_t)Rr*Vv];
__device__ float g_loc[(size_t)Rr*Vv];
__device__ float g_stats[Rr*6];
__device__ float g_gate[Rr];
__device__ __nv_bfloat16 g_feat_hi[Rr*F1],  g_feat_lo[Rr*F1];
__device__ __nv_bfloat16 g_locin_hi[Rr*F2], g_locin_lo[Rr*F2];
__device__ __nv_bfloat16 g_h_hi[Rr*HLh],    g_h_lo[Rr*HLh];
__device__ __nv_bfloat16 g_h2_hi[Rr*HCh],   g_h2_lo[Rr*HCh];
__device__ __nv_bfloat16 g_w1t_hi[HLh*F1],  g_w1t_lo[HLh*F1];
__device__ __nv_bfloat16 g_lw1t_hi[HCh*F2], g_lw1t_lo[HCh*F2];
__device__ __nv_bfloat16 g_w2t_hi[(size_t)Vv*HLh],  g_w2t_lo[(size_t)Vv*HLh];
__device__ __nv_bfloat16 g_lw2t_hi[(size_t)Vv*HCh], g_lw2t_lo[(size_t)Vv*HCh];

// ======================= small kernels =====================================
__global__ void gather_embed_kernel(const int* __restrict__ tok,
                                    const float* __restrict__ emb) {
    int r = blockIdx.x, d = threadIdx.x;
    float v = emb[(size_t)tok[r] * Dd + d];
    g_x[r*Dd + d] = v;
    g_feat[(size_t)r*F1 + Mm + d] = v;
}

__global__ void scan_kernel(const float* __restrict__ decays) {
    int b = blockIdx.x, m = threadIdx.x;
    float a = decays[m], s = 0.f;
    for (int t = 0; t < Ss; t++) {
        int r = b*Ss + t;
        s = a*s + g_u[(size_t)r*Mm + m];
        g_feat[(size_t)r*F1 + m] = s;
    }
}

__global__ void build_loc_kernel() {
    int idx = blockIdx.x * blockDim.x + threadIdx.x;
    if (idx >= Rr*Ww*Dd) return;
    int d = idx % Dd, w = (idx / Dd) % Ww, r = idx / (Ww*Dd);
    int s = r % Ss, b = r / Ss;
    int ss = s - (Ww-1) + w;
    g_locin[idx] = (ss >= 0) ? g_x[((size_t)(b*Ss + ss))*Dd + d] : 0.f;
}

__global__ void conv_split_kernel(const float* __restrict__ in,
                                  __nv_bfloat16* __restrict__ hi,
                                  __nv_bfloat16* __restrict__ lo, int n4) {
    int i = blockIdx.x * blockDim.x + threadIdx.x;
    if (i >= n4) return;
    float4 v = ((const float4*)in)[i];
    __nv_bfloat16 h0 = __float2bfloat16(v.x), h1 = __float2bfloat16(v.y);
    __nv_bfloat16 h2 = __float2bfloat16(v.z), h3 = __float2bfloat16(v.w);
    __nv_bfloat162 H0 = {h0, h1}, H1 = {h2, h3};
    __nv_bfloat162 L0 = {__float2bfloat16(v.x - __bfloat162float(h0)),
                         __float2bfloat16(v.y - __bfloat162float(h1))};
    __nv_bfloat162 L1 = {__float2bfloat16(v.z - __bfloat162float(h2)),
                         __float2bfloat16(v.w - __bfloat162float(h3))};
    ((__nv_bfloat162*)hi)[2*i]   = H0;  ((__nv_bfloat162*)hi)[2*i+1] = H1;
    ((__nv_bfloat162*)lo)[2*i]   = L0;  ((__nv_bfloat162*)lo)[2*i+1] = L1;
}

// transpose+split: W[K,N] fp32 row-major -> Wt hi/lo [N,K] bf16
__global__ void wtconv_kernel(const float* __restrict__ W,
                              __nv_bfloat16* __restrict__ hi,
                              __nv_bfloat16* __restrict__ lo, int K, int N) {
    __shared__ float t[32][33];
    int n0 = blockIdx.x * 32, k0 = blockIdx.y * 32;
    int tx = threadIdx.x & 31, ty = threadIdx.x >> 5;
#pragma unroll
    for (int r = 0; r < 4; r++)
        t[ty + 8*r][tx] = W[(size_t)(k0 + ty + 8*r) * N + n0 + tx];
    __syncthreads();
#pragma unroll
    for (int r = 0; r < 4; r++) {
        int n = n0 + ty + 8*r, k = k0 + tx;
        float v = t[tx][ty + 8*r];
        __nv_bfloat16 h = __float2bfloat16(v);
        hi[(size_t)n*K + k] = h;
        lo[(size_t)n*K + k] = __float2bfloat16(v - __bfloat162float(h));
    }
}

// ============ HMMA GEMM, CTA 128x128 (hidden layers, ReLU+split out) =======
#define STAGES 3
#define ROWB   80
#define ABYTES (128*ROWB)
#define STAGEB (2*ABYTES)

__global__ void __launch_bounds__(256, 2) hmma_kernel(
        const __nv_bfloat16* __restrict__ Ahi, const __nv_bfloat16* __restrict__ Alo,
        const __nv_bfloat16* __restrict__ Bhi, const __nv_bfloat16* __restrict__ Blo,
        const float* __restrict__ bias,
        __nv_bfloat16* __restrict__ Chi, __nv_bfloat16* __restrict__ Clo,
        int K, int Ntot) {
    extern __shared__ char smem[];
    const uint32_t sb = smem_u32(smem);
    const int tid = threadIdx.x;
    const int wid = tid >> 5, lid = tid & 31;
    const int wm = wid & 3, wn = wid >> 2;          // 4 M x 2 N
    const int mBase = blockIdx.x * 128;
    const int nBase = blockIdx.y * 128;

    const int KC = K / 32;
    const int NC = 3 * KC;

    float acc[2][8][4];
#pragma unroll
    for (int i = 0; i < 2; i++)
#pragma unroll
        for (int j = 0; j < 8; j++)
#pragma unroll
            for (int q = 0; q < 4; q++) acc[i][j][q] = 0.f;

    auto load_tile = [&](int c, int s) {
        int pass = c / KC, kc = c - pass * KC;
        const __nv_bfloat16* Ap = (pass == 1) ? Alo : Ahi;
        const __nv_bfloat16* Bp = (pass == 2) ? Blo : Bhi;
        int kof = kc * 32;
        uint32_t ab = sb + s * STAGEB;
        uint32_t bb = ab + ABYTES;
#pragma unroll
        for (int i = 0; i < 2; i++) {
            int id = tid + i * 256;
            int row = id >> 2, q = id & 3;
            CP_ASYNC16(ab + row*ROWB + q*16,
                       Ap + (size_t)(mBase + row) * K + kof + q*8);
        }
#pragma unroll
        for (int i = 0; i < 2; i++) {
            int id = tid + i * 256;
            int row = id >> 2, q = id & 3;
            CP_ASYNC16(bb + row*ROWB + q*16,
                       Bp + (size_t)(nBase + row) * K + kof + q*8);
        }
    };

#pragma unroll
    for (int s = 0; s < STAGES - 1; s++) { load_tile(s, s); CP_COMMIT(); }

    const int aRow = (lid & 7) + ((lid >> 3) & 1) * 8;
    const int aKb  = (lid >> 4) * 16;
    const int bRow = (lid & 7) + ((lid >> 4) & 1) * 8;
    const int bKb  = ((lid >> 3) & 1) * 16;

    for (int c = 0; c < NC; c++) {
        CP_WAIT(STAGES - 2);
        __syncthreads();
        if (c + STAGES - 1 < NC) load_tile(c + STAGES - 1, (c + STAGES - 1) % STAGES);
        CP_COMMIT();

        uint32_t ab = sb + (c % STAGES) * STAGEB;
        uint32_t bb = ab + ABYTES;
#pragma unroll
        for (int ks = 0; ks < 2; ks++) {
            uint32_t afr[2][4], bfr[4][4];
#pragma unroll
            for (int i = 0; i < 2; i++)
                ldmx4(afr[i], ab + (wm*32 + i*16 + aRow)*ROWB + ks*32 + aKb);
#pragma unroll
            for (int t = 0; t < 4; t++)
                ldmx4(bfr[t], bb + (wn*64 + t*16 + bRow)*ROWB + ks*32 + bKb);
#pragma unroll
            for (int i = 0; i < 2; i++)
#pragma unroll
                for (int j = 0; j < 8; j++)
                    mma16816(acc[i][j], afr[i], bfr[j >> 1] + (j & 1) * 2);
        }
        __syncthreads();
    }
    CP_WAIT(0);

    const int r0 = lid >> 2;
    const int c0 = (lid & 3) * 2;
#pragma unroll
    for (int i = 0; i < 2; i++) {
#pragma unroll
        for (int j = 0; j < 8; j++) {
            int col = nBase + wn*64 + j*8 + c0;
            int rowA = mBase + wm*32 + i*16 + r0;
            float2 bv = *(const float2*)(bias + col);
            float v0 = fmaxf(acc[i][j][0] + bv.x, 0.f);
            float v1 = fmaxf(acc[i][j][1] + bv.y, 0.f);
            float v2 = fmaxf(acc[i][j][2] + bv.x, 0.f);
            float v3 = fmaxf(acc[i][j][3] + bv.y, 0.f);
            __nv_bfloat16 h0 = __float2bfloat16(v0), h1 = __float2bfloat16(v1);
            __nv_bfloat16 h2 = __float2bfloat16(v2), h3 = __float2bfloat16(v3);
            *(__nv_bfloat162*)(Chi + (size_t)rowA * Ntot + col) = __nv_bfloat162{h0, h1};
            *(__nv_bfloat162*)(Chi + (size_t)(rowA+8) * Ntot + col) = __nv_bfloat162{h2, h3};
            *(__nv_bfloat162*)(Clo + (size_t)rowA * Ntot + col) =
                __nv_bfloat162{__float2bfloat16(v0 - __bfloat162float(h0)),
                               __float2bfloat16(v1 - __bfloat162float(h1))};
            *(__nv_bfloat162*)(Clo + (size_t)(rowA+8) * Ntot + col) =
                __nv_bfloat162{__float2bfloat16(v2 - __bfloat162float(h2)),
                               __float2bfloat16(v3 - __bfloat162float(h3))};
        }
    }
}

// ============ HMMA GEMM, CTA 128x256, warp tile 64x64 (logit layers) =======
// 8 warps: wm = wid>>2 (2 x M64), wn = wid&3 (4 x N64). 1 CTA/SM, 4 stages.
#define STG2    4
#define A2BYTES (128*ROWB)            // 10240
#define B2BYTES (256*ROWB)            // 20480
#define STAGE2B (A2BYTES + B2BYTES)   // 30720

__global__ void __launch_bounds__(256, 1) hmma256_kernel(
        const __nv_bfloat16* __restrict__ Ahi, const __nv_bfloat16* __restrict__ Alo,
        const __nv_bfloat16* __restrict__ Bhi, const __nv_bfloat16* __restrict__ Blo,
        const float* __restrict__ bias,
        float* __restrict__ Cf,
        int K, int Ntot) {
    extern __shared__ char smem[];
    const uint32_t sb = smem_u32(smem);
    const int tid = threadIdx.x;
    const int wid = tid >> 5, lid = tid & 31;
    const int wm = wid >> 2, wn = wid & 3;          // 2 M x 4 N
    const int mBase = blockIdx.x * 128;
    const int nBase = blockIdx.y * 256;

    const int KC = K / 32;
    const int NC = 3 * KC;

    float acc[4][8][4];
#pragma unroll
    for (int i = 0; i < 4; i++)
#pragma unroll
        for (int j = 0; j < 8; j++)
#pragma unroll
            for (int q = 0; q < 4; q++) acc[i][j][q] = 0.f;

    auto load_tile = [&](int c, int s) {
        int pass = c / KC, kc = c - pass * KC;
        const __nv_bfloat16* Ap = (pass == 1) ? Alo : Ahi;
        const __nv_bfloat16* Bp = (pass == 2) ? Blo : Bhi;
        int kof = kc * 32;
        uint32_t ab = sb + s * STAGE2B;
        uint32_t bb = ab + A2BYTES;
#pragma unroll
        for (int i = 0; i < 2; i++) {                 // A: 128 rows
            int id = tid + i * 256;
            int row = id >> 2, q = id & 3;
            CP_ASYNC16(ab + row*ROWB + q*16,
                       Ap + (size_t)(mBase + row) * K + kof + q*8);
        }
#pragma unroll
        for (int i = 0; i < 4; i++) {                 // B: 256 rows
            int id = tid + i * 256;
            int row = id >> 2, q = id & 3;
            CP_ASYNC16(bb + row*ROWB + q*16,
                       Bp + (size_t)(nBase + row) * K + kof + q*8);
        }
    };

#pragma unroll
    for (int s = 0; s < STG2 - 1; s++) { load_tile(s, s); CP_COMMIT(); }

    const int aRow = (lid & 7) + ((lid >> 3) & 1) * 8;
    const int aKb  = (lid >> 4) * 16;
    const int bRow = (lid & 7) + ((lid >> 4) & 1) * 8;
    const int bKb  = ((lid >> 3) & 1) * 16;

    for (int c = 0; c < NC; c++) {
        CP_WAIT(STG2 - 2);
        __syncthreads();
        if (c + STG2 - 1 < NC) load_tile(c + STG2 - 1, (c + STG2 - 1) % STG2);
        CP_COMMIT();

        uint32_t ab = sb + (c % STG2) * STAGE2B;
        uint32_t bb = ab + A2BYTES;
#pragma unroll
        for (int ks = 0; ks < 2; ks++) {
            uint32_t afr[4][4], bfr[4][4];
#pragma unroll
            for (int i = 0; i < 4; i++)
                ldmx4(afr[i], ab + (wm*64 + i*16 + aRow)*ROWB + ks*32 + aKb);
#pragma unroll
            for (int t = 0; t < 4; t++)
                ldmx4(bfr[t], bb + (wn*64 + t*16 + bRow)*ROWB + ks*32 + bKb);
#pragma unroll
            for (int i = 0; i < 4; i++)
#pragma unroll
                for (int j = 0; j < 8; j++)
                    mma16816(acc[i][j], afr[i], bfr[j >> 1] + (j & 1) * 2);
        }
        __syncthreads();
    }
    CP_WAIT(0);

    const int r0 = lid >> 2;
    const int c0 = (lid & 3) * 2;
#pragma unroll
    for (int i = 0; i < 4; i++) {
#pragma unroll
        for (int j = 0; j < 8; j++) {
            int col = nBase + wn*64 + j*8 + c0;
            int rowA = mBase + wm*64 + i*16 + r0;
            float2 bv = *(const float2*)(bias + col);
            *(float2*)(Cf + (size_t)rowA * Ntot + col) =
                make_float2(acc[i][j][0] + bv.x, acc[i][j][1] + bv.y);
            *(float2*)(Cf + (size_t)(rowA + 8) * Ntot + col) =
                make_float2(acc[i][j][2] + bv.x, acc[i][j][3] + bv.y);
        }
    }
}

// ======================= fp32 SGEMM (small u GEMM only) ====================
#define BM 128
#define BNs 128
#define BKs 8
__global__ void __launch_bounds__(256) sgemm_kernel(
        const float* __restrict__ A, const float* __restrict__ Bm,
        float* __restrict__ C, int K, int N) {
    __shared__ float As[BKs][BM];
    __shared__ float Bs2[BKs][BNs];
    int tid = threadIdx.x;
    int tx = tid & 15, ty = tid >> 4;
    int mBase = blockIdx.y * BM, nBase = blockIdx.x * BNs;
    int aM = tid >> 1, aK = (tid & 1) * 4;
    int bK = tid >> 5, bN = (tid & 31) * 4;
    const float* Aptr = A + (size_t)(mBase + aM) * K + aK;
    const float* Bptr = Bm + (size_t)bK * N + nBase + bN;
    float acc[8][8];
#pragma unroll
    for (int i = 0; i < 8; i++)
#pragma unroll
        for (int j = 0; j < 8; j++) acc[i][j] = 0.f;
    for (int kt = 0; kt < K; kt += BKs) {
        float4 av = *(const float4*)Aptr;  Aptr += BKs;
        float4 bv = *(const float4*)Bptr;  Bptr += (size_t)BKs * N;
        As[aK+0][aM] = av.x; As[aK+1][aM] = av.y;
        As[aK+2][aM] = av.z; As[aK+3][aM] = av.w;
        *(float4*)&Bs2[bK][bN] = bv;
        __syncthreads();
        float ar[8], br[8];
#pragma unroll
        for (int k = 0; k < BKs; k++) {
#pragma unroll
            for (int i = 0; i < 8; i++) ar[i] = As[k][ty*8 + i];
#pragma unroll
            for (int j = 0; j < 8; j++) br[j] = Bs2[k][tx*8 + j];
#pragma unroll
            for (int i = 0; i < 8; i++)
#pragma unroll
                for (int j = 0; j < 8; j++)
                    acc[i][j] = fmaf(ar[i], br[j], acc[i][j]);
        }
        __syncthreads();
    }
#pragma unroll
    for (int i = 0; i < 8; i++) {
        float* Crow = C + (size_t)(mBase + ty*8 + i) * N + nBase + tx*8;
#pragma unroll
        for (int j = 0; j < 8; j++) Crow[j] = acc[i][j];
    }
}

// ======================= stats / gate / mix ================================
__global__ void stats_kernel() {
    int r = blockIdx.x, br = blockIdx.y;
    const float* z = (br ? g_loc : g_lin) + (size_t)r * Vv;
    int tid = threadIdx.x;
    float s = 0.f, sq = 0.f, mx = -3.4e38f;
    for (int i = tid; i < Vv; i += 256) {
        float v = z[i];
        s += v; sq += v*v; mx = fmaxf(mx, v);
    }
    __shared__ float ss[256], ssq[256], smx[256];
    ss[tid] = s; ssq[tid] = sq; smx[tid] = mx;
    __syncthreads();
    for (int off = 128; off > 0; off >>= 1) {
        if (tid < off) {
            ss[tid] += ss[tid+off];
            ssq[tid] += ssq[tid+off];
            smx[tid] = fmaxf(smx[tid], smx[tid+off]);
        }
        __syncthreads();
    }
    if (tid == 0) {
        float mean = ss[0] / (float)Vv;
        float var = fmaxf(ssq[0] / (float)Vv - mean*mean, 0.f);
        float* st = g_stats + (size_t)r*6 + br*3;
        st[0] = mean; st[1] = smx[0]; st[2] = sqrtf(var);
    }
}

__global__ void gate_kernel(const float* __restrict__ gw, const float* __restrict__ gb) {
    int r = blockIdx.x * blockDim.x + threadIdx.x;
    if (r >= Rr) return;
    const float* st = g_stats + (size_t)r*6;
    float acc = gb[0];
#pragma unroll
    for (int k = 0; k < 6; k++) acc += st[k] * gw[k];
    g_gate[r] = 1.f / (1.f + expf(-acc));
}

__global__ void mix_kernel(float* __restrict__ out) {
    int r = blockIdx.y;
    int c = blockIdx.x * blockDim.x + threadIdx.x;
    size_t i = (size_t)r * Vv + c;
    float g = g_gate[r];
    out[i] = g * g_lin[i] + (1.f - g) * g_loc[i];
}

// ======================= launch ============================================
extern "C" void kernel_launch(void* const* d_in, const int* in_sizes, int n_in,
                              void* d_out, int out_size) {
    const int*   tokens  = (const int*)  d_in[0];
    const float* emb     = (const float*)d_in[1];
    const float* in_proj = (const float*)d_in[2];
    const float* decays  = (const float*)d_in[3];
    const float* w1      = (const float*)d_in[4];
    const float* b1      = (const float*)d_in[5];
    const float* w2      = (const float*)d_in[6];
    const float* b2      = (const float*)d_in[7];
    const float* lw1     = (const float*)d_in[8];
    const float* lb1     = (const float*)d_in[9];
    const float* lw2     = (const float*)d_in[10];
    const float* lb2     = (const float*)d_in[11];
    const float* gate_w  = (const float*)d_in[12];
    const float* gate_b  = (const float*)d_in[13];
    float* out = (float*)d_out;

    float *gx, *gu, *gfeat, *glocin, *glin, *gloc;
    cudaGetSymbolAddress((void**)&gx,     g_x);
    cudaGetSymbolAddress((void**)&gu,     g_u);
    cudaGetSymbolAddress((void**)&gfeat,  g_feat);
    cudaGetSymbolAddress((void**)&glocin, g_locin);
    cudaGetSymbolAddress((void**)&glin,   g_lin);
    cudaGetSymbolAddress((void**)&gloc,   g_loc);
    __nv_bfloat16 *fh, *fl, *lih, *lil, *hh, *hl, *h2h, *h2l;
    __nv_bfloat16 *w1h, *w1l, *lw1h, *lw1l, *w2h, *w2l, *lw2h, *lw2l;
    cudaGetSymbolAddress((void**)&fh,   g_feat_hi);
    cudaGetSymbolAddress((void**)&fl,   g_feat_lo);
    cudaGetSymbolAddress((void**)&lih,  g_locin_hi);
    cudaGetSymbolAddress((void**)&lil,  g_locin_lo);
    cudaGetSymbolAddress((void**)&hh,   g_h_hi);
    cudaGetSymbolAddress((void**)&hl,   g_h_lo);
    cudaGetSymbolAddress((void**)&h2h,  g_h2_hi);
    cudaGetSymbolAddress((void**)&h2l,  g_h2_lo);
    cudaGetSymbolAddress((void**)&w1h,  g_w1t_hi);
    cudaGetSymbolAddress((void**)&w1l,  g_w1t_lo);
    cudaGetSymbolAddress((void**)&lw1h, g_lw1t_hi);
    cudaGetSymbolAddress((void**)&lw1l, g_lw1t_lo);
    cudaGetSymbolAddress((void**)&w2h,  g_w2t_hi);
    cudaGetSymbolAddress((void**)&w2l,  g_w2t_lo);
    cudaGetSymbolAddress((void**)&lw2h, g_lw2t_hi);
    cudaGetSymbolAddress((void**)&lw2l, g_lw2t_lo);

    constexpr int SMEMB  = STAGES * STAGEB;   // 61440
    constexpr int SMEMB2 = STG2 * STAGE2B;    // 122880
    cudaFuncSetAttribute(hmma_kernel,    cudaFuncAttributeMaxDynamicSharedMemorySize, SMEMB);
    cudaFuncSetAttribute(hmma256_kernel, cudaFuncAttributeMaxDynamicSharedMemorySize, SMEMB2);

    // 1) embedding gather
    gather_embed_kernel<<<Rr, Dd>>>(tokens, emb);
    // 2) u = x @ in_proj
    sgemm_kernel<<<dim3(Mm/BNs, Rr/BM), 256>>>(gx, in_proj, gu, Dd, Mm);
    // 3) decay scan
    scan_kernel<<<Bb, Mm>>>(decays);
    // 4) window features
    build_loc_kernel<<<(Rr*Ww*Dd + 255)/256, 256>>>();
    // 5) split conversions of activations
    conv_split_kernel<<<(Rr*F1/4 + 255)/256, 256>>>(gfeat,  fh,  fl,  Rr*F1/4);
    conv_split_kernel<<<(Rr*F2/4 + 255)/256, 256>>>(glocin, lih, lil, Rr*F2/4);
    // 6) weight transpose+split conversions
    wtconv_kernel<<<dim3(HLh/32, F1/32),  256>>>(w1,  w1h,  w1l,  F1,  HLh);
    wtconv_kernel<<<dim3(HCh/32, F2/32),  256>>>(lw1, lw1h, lw1l, F2,  HCh);
    wtconv_kernel<<<dim3(Vv/32,  HLh/32), 256>>>(w2,  w2h,  w2l,  HLh, Vv);
    wtconv_kernel<<<dim3(Vv/32,  HCh/32), 256>>>(lw2, lw2h, lw2l, HCh, Vv);
    // 7) h = relu(feat @ w1 + b1) -> split bf16
    hmma_kernel<<<dim3(Rr/128, HLh/128), 256, SMEMB>>>(
        fh, fl, w1h, w1l, b1, hh, hl, F1, HLh);
    // 8) h2 = relu(loc @ lw1 + lb1) -> split bf16
    hmma_kernel<<<dim3(Rr/128, HCh/128), 256, SMEMB>>>(
        lih, lil, lw1h, lw1l, lb1, h2h, h2l, F2, HCh);
    // 9) lin_logits = h @ w2 + b2     (128x256 tiles)
    hmma256_kernel<<<dim3(Rr/128, Vv/256), 256, SMEMB2>>>(
        hh, hl, w2h, w2l, b2, glin, HLh, Vv);
    // 10) loc_logits = h2 @ lw2 + lb2
    hmma256_kernel<<<dim3(Rr/128, Vv/256), 256, SMEMB2>>>(
        h2h, h2l, lw2h, lw2l, lb2, gloc, HCh, Vv);
    // 11) stats, gate, mix
    stats_kernel<<<dim3(Rr, 2), 256>>>();
    gate_kernel<<<(Rr + 255)/256, 256>>>(gate_w, gate_b);
    mix_kernel<<<dim3(Vv/256, Rr), 256>>>(out);
}

// round 9
// speedup vs baseline: 1.0033x; 1.0033x over previous
#include <cuda_runtime.h>
#include <cuda_bf16.h>
#include <cstdint>
#include <math.h>

#define Bb   2
#define Ss   1024
#define Vv   32000
#define Dd   256
#define Mm   256
#define Ww   8
#define HLh  1024
#define HCh  1024
#define Rr   (Bb*Ss)          // 2048
#define F1   (Mm+Dd)          // 512
#define F2   (Ww*Dd)          // 2048

// ======================= helpers ===========================================
__device__ __forceinline__ uint32_t smem_u32(const void* p) {
    uint32_t a;
    asm("{ .reg .u64 t; cvta.to.shared.u64 t, %1; cvt.u32.u64 %0, t; }" : "=r"(a) : "l"(p));
    return a;
}
#define CP_ASYNC16(dst, src) \
    asm volatile("cp.async.cg.shared.global [%0], [%1], 16;" :: "r"(dst), "l"(src))
#define CP_COMMIT() asm volatile("cp.async.commit_group;" ::: "memory")
#define CP_WAIT(n)  asm volatile("cp.async.wait_group %0;" :: "n"(n) : "memory")

__device__ __forceinline__ void ldmx4(uint32_t* r, uint32_t addr) {
    asm volatile("ldmatrix.sync.aligned.m8n8.x4.shared.b16 {%0,%1,%2,%3}, [%4];"
        : "=r"(r[0]), "=r"(r[1]), "=r"(r[2]), "=r"(r[3]) : "r"(addr));
}
__device__ __forceinline__ void mma16816(float* c, const uint32_t* a, const uint32_t* b) {
    asm volatile(
        "mma.sync.aligned.m16n8k16.row.col.f32.bf16.bf16.f32 "
        "{%0,%1,%2,%3}, {%4,%5,%6,%7}, {%8,%9}, {%0,%1,%2,%3};"
        : "+f"(c[0]), "+f"(c[1]), "+f"(c[2]), "+f"(c[3])
        : "r"(a[0]), "r"(a[1]), "r"(a[2]), "r"(a[3]), "r"(b[0]), "r"(b[1]));
}

// ======================= scratch ===========================================
__device__ float g_x[Rr*Dd];
__device__ float g_u[Rr*Mm];
__device__ float g_feat[Rr*F1];
__device__ float g_locin[Rr*F2];
__device__ float g_lin[(size_t)Rr*Vv];
__device__ float g_loc[(size_t)Rr*Vv];
__device__ float g_stats[Rr*6];
__device__ float g_gate[Rr];
__device__ __nv_bfloat16 g_feat_hi[Rr*F1],  g_feat_lo[Rr*F1];
__device__ __nv_bfloat16 g_locin_hi[Rr*F2], g_locin_lo[Rr*F2];
__device__ __nv_bfloat16 g_h_hi[Rr*HLh],    g_h_lo[Rr*HLh];
__device__ __nv_bfloat16 g_h2_hi[Rr*HCh],   g_h2_lo[Rr*HCh];
__device__ __nv_bfloat16 g_w1t_hi[HLh*F1],  g_w1t_lo[HLh*F1];
__device__ __nv_bfloat16 g_lw1t_hi[HCh*F2], g_lw1t_lo[HCh*F2];
__device__ __nv_bfloat16 g_w2t_hi[(size_t)Vv*HLh],  g_w2t_lo[(size_t)Vv*HLh];
__device__ __nv_bfloat16 g_lw2t_hi[(size_t)Vv*HCh], g_lw2t_lo[(size_t)Vv*HCh];

// ======================= small kernels =====================================
__global__ void gather_embed_kernel(const int* __restrict__ tok,
                                    const float* __restrict__ emb) {
    int r = blockIdx.x, d = threadIdx.x;
    float v = emb[(size_t)tok[r] * Dd + d];
    g_x[r*Dd + d] = v;
    g_feat[(size_t)r*F1 + Mm + d] = v;
}

__global__ void scan_kernel(const float* __restrict__ decays) {
    int b = blockIdx.x, m = threadIdx.x;
    float a = decays[m], s = 0.f;
    for (int t = 0; t < Ss; t++) {
        int r = b*Ss + t;
        s = a*s + g_u[(size_t)r*Mm + m];
        g_feat[(size_t)r*F1 + m] = s;
    }
}

__global__ void build_loc_kernel() {
    int idx = blockIdx.x * blockDim.x + threadIdx.x;
    if (idx >= Rr*Ww*Dd) return;
    int d = idx % Dd, w = (idx / Dd) % Ww, r = idx / (Ww*Dd);
    int s = r % Ss, b = r / Ss;
    int ss = s - (Ww-1) + w;
    g_locin[idx] = (ss >= 0) ? g_x[((size_t)(b*Ss + ss))*Dd + d] : 0.f;
}

__global__ void conv_split_kernel(const float* __restrict__ in,
                                  __nv_bfloat16* __restrict__ hi,
                                  __nv_bfloat16* __restrict__ lo, int n4) {
    int i = blockIdx.x * blockDim.x + threadIdx.x;
    if (i >= n4) return;
    float4 v = ((const float4*)in)[i];
    __nv_bfloat16 h0 = __float2bfloat16(v.x), h1 = __float2bfloat16(v.y);
    __nv_bfloat16 h2 = __float2bfloat16(v.z), h3 = __float2bfloat16(v.w);
    __nv_bfloat162 H0 = {h0, h1}, H1 = {h2, h3};
    __nv_bfloat162 L0 = {__float2bfloat16(v.x - __bfloat162float(h0)),
                         __float2bfloat16(v.y - __bfloat162float(h1))};
    __nv_bfloat162 L1 = {__float2bfloat16(v.z - __bfloat162float(h2)),
                         __float2bfloat16(v.w - __bfloat162float(h3))};
    ((__nv_bfloat162*)hi)[2*i]   = H0;  ((__nv_bfloat162*)hi)[2*i+1] = H1;
    ((__nv_bfloat162*)lo)[2*i]   = L0;  ((__nv_bfloat162*)lo)[2*i+1] = L1;
}

// transpose+split: W[K,N] fp32 row-major -> Wt hi/lo [N,K] bf16
__global__ void wtconv_kernel(const float* __restrict__ W,
                              __nv_bfloat16* __restrict__ hi,
                              __nv_bfloat16* __restrict__ lo, int K, int N) {
    __shared__ float t[32][33];
    int n0 = blockIdx.x * 32, k0 = blockIdx.y * 32;
    int tx = threadIdx.x & 31, ty = threadIdx.x >> 5;
#pragma unroll
    for (int r = 0; r < 4; r++)
        t[ty + 8*r][tx] = W[(size_t)(k0 + ty + 8*r) * N + n0 + tx];
    __syncthreads();
#pragma unroll
    for (int r = 0; r < 4; r++) {
        int n = n0 + ty + 8*r, k = k0 + tx;
        float v = t[tx][ty + 8*r];
        __nv_bfloat16 h = __float2bfloat16(v);
        hi[(size_t)n*K + k] = h;
        lo[(size_t)n*K + k] = __float2bfloat16(v - __bfloat162float(h));
    }
}

// ============ HMMA GEMM, CTA 128x128 (hidden layers, ReLU+split out) =======
#define STAGES 3
#define ROWB   80
#define ABYTES (128*ROWB)
#define STAGEB (2*ABYTES)

__global__ void __launch_bounds__(256, 2) hmma_kernel(
        const __nv_bfloat16* __restrict__ Ahi, const __nv_bfloat16* __restrict__ Alo,
        const __nv_bfloat16* __restrict__ Bhi, const __nv_bfloat16* __restrict__ Blo,
        const float* __restrict__ bias,
        __nv_bfloat16* __restrict__ Chi, __nv_bfloat16* __restrict__ Clo,
        int K, int Ntot) {
    extern __shared__ char smem[];
    const uint32_t sb = smem_u32(smem);
    const int tid = threadIdx.x;
    const int wid = tid >> 5, lid = tid & 31;
    const int wm = wid & 3, wn = wid >> 2;          // 4 M x 2 N
    const int mBase = blockIdx.x * 128;
    const int nBase = blockIdx.y * 128;

    const int KC = K / 32;
    const int NC = 3 * KC;

    float acc[2][8][4];
#pragma unroll
    for (int i = 0; i < 2; i++)
#pragma unroll
        for (int j = 0; j < 8; j++)
#pragma unroll
            for (int q = 0; q < 4; q++) acc[i][j][q] = 0.f;

    auto load_tile = [&](int c, int s) {
        int pass = c / KC, kc = c - pass * KC;
        const __nv_bfloat16* Ap = (pass == 1) ? Alo : Ahi;
        const __nv_bfloat16* Bp = (pass == 2) ? Blo : Bhi;
        int kof = kc * 32;
        uint32_t ab = sb + s * STAGEB;
        uint32_t bb = ab + ABYTES;
#pragma unroll
        for (int i = 0; i < 2; i++) {
            int id = tid + i * 256;
            int row = id >> 2, q = id & 3;
            CP_ASYNC16(ab + row*ROWB + q*16,
                       Ap + (size_t)(mBase + row) * K + kof + q*8);
        }
#pragma unroll
        for (int i = 0; i < 2; i++) {
            int id = tid + i * 256;
            int row = id >> 2, q = id & 3;
            CP_ASYNC16(bb + row*ROWB + q*16,
                       Bp + (size_t)(nBase + row) * K + kof + q*8);
        }
    };

#pragma unroll
    for (int s = 0; s < STAGES - 1; s++) { load_tile(s, s); CP_COMMIT(); }

    const int aRow = (lid & 7) + ((lid >> 3) & 1) * 8;
    const int aKb  = (lid >> 4) * 16;
    const int bRow = (lid & 7) + ((lid >> 4) & 1) * 8;
    const int bKb  = ((lid >> 3) & 1) * 16;

    for (int c = 0; c < NC; c++) {
        CP_WAIT(STAGES - 2);
        __syncthreads();
        if (c + STAGES - 1 < NC) load_tile(c + STAGES - 1, (c + STAGES - 1) % STAGES);
        CP_COMMIT();

        uint32_t ab = sb + (c % STAGES) * STAGEB;
        uint32_t bb = ab + ABYTES;
#pragma unroll
        for (int ks = 0; ks < 2; ks++) {
            uint32_t afr[2][4], bfr[4][4];
#pragma unroll
            for (int i = 0; i < 2; i++)
                ldmx4(afr[i], ab + (wm*32 + i*16 + aRow)*ROWB + ks*32 + aKb);
#pragma unroll
            for (int t = 0; t < 4; t++)
                ldmx4(bfr[t], bb + (wn*64 + t*16 + bRow)*ROWB + ks*32 + bKb);
#pragma unroll
            for (int i = 0; i < 2; i++)
#pragma unroll
                for (int j = 0; j < 8; j++)
                    mma16816(acc[i][j], afr[i], bfr[j >> 1] + (j & 1) * 2);
        }
        __syncthreads();
    }
    CP_WAIT(0);

    const int r0 = lid >> 2;
    const int c0 = (lid & 3) * 2;
#pragma unroll
    for (int i = 0; i < 2; i++) {
#pragma unroll
        for (int j = 0; j < 8; j++) {
            int col = nBase + wn*64 + j*8 + c0;
            int rowA = mBase + wm*32 + i*16 + r0;
            float2 bv = *(const float2*)(bias + col);
            float v0 = fmaxf(acc[i][j][0] + bv.x, 0.f);
            float v1 = fmaxf(acc[i][j][1] + bv.y, 0.f);
            float v2 = fmaxf(acc[i][j][2] + bv.x, 0.f);
            float v3 = fmaxf(acc[i][j][3] + bv.y, 0.f);
            __nv_bfloat16 h0 = __float2bfloat16(v0), h1 = __float2bfloat16(v1);
            __nv_bfloat16 h2 = __float2bfloat16(v2), h3 = __float2bfloat16(v3);
            *(__nv_bfloat162*)(Chi + (size_t)rowA * Ntot + col) = __nv_bfloat162{h0, h1};
            *(__nv_bfloat162*)(Chi + (size_t)(rowA+8) * Ntot + col) = __nv_bfloat162{h2, h3};
            *(__nv_bfloat162*)(Clo + (size_t)rowA * Ntot + col) =
                __nv_bfloat162{__float2bfloat16(v0 - __bfloat162float(h0)),
                               __float2bfloat16(v1 - __bfloat162float(h1))};
            *(__nv_bfloat162*)(Clo + (size_t)(rowA+8) * Ntot + col) =
                __nv_bfloat162{__float2bfloat16(v2 - __bfloat162float(h2)),
                               __float2bfloat16(v3 - __bfloat162float(h3))};
        }
    }
}

// ============ HMMA GEMM, CTA 128x256, warp tile 64x64 (logit layers) =======
// 8 warps: wm = wid>>2 (2 x M64), wn = wid&3 (4 x N64). 1 CTA/SM, 4 stages.
#define STG2    4
#define A2BYTES (128*ROWB)            // 10240
#define B2BYTES (256*ROWB)            // 20480
#define STAGE2B (A2BYTES + B2BYTES)   // 30720

__global__ void __launch_bounds__(256, 1) hmma256_kernel(
        const __nv_bfloat16* __restrict__ Ahi, const __nv_bfloat16* __restrict__ Alo,
        const __nv_bfloat16* __restrict__ Bhi, const __nv_bfloat16* __restrict__ Blo,
        const float* __restrict__ bias,
        float* __restrict__ Cf,
        int K, int Ntot) {
    extern __shared__ char smem[];
    const uint32_t sb = smem_u32(smem);
    const int tid = threadIdx.x;
    const int wid = tid >> 5, lid = tid & 31;
    const int wm = wid >> 2, wn = wid & 3;          // 2 M x 4 N
    const int mBase = blockIdx.x * 128;
    const int nBase = blockIdx.y * 256;

    const int KC = K / 32;
    const int NC = 3 * KC;

    float acc[4][8][4];
#pragma unroll
    for (int i = 0; i < 4; i++)
#pragma unroll
        for (int j = 0; j < 8; j++)
#pragma unroll
            for (int q = 0; q < 4; q++) acc[i][j][q] = 0.f;

    auto load_tile = [&](int c, int s) {
        int pass = c / KC, kc = c - pass * KC;
        const __nv_bfloat16* Ap = (pass == 1) ? Alo : Ahi;
        const __nv_bfloat16* Bp = (pass == 2) ? Blo : Bhi;
        int kof = kc * 32;
        uint32_t ab = sb + s * STAGE2B;
        uint32_t bb = ab + A2BYTES;
#pragma unroll
        for (int i = 0; i < 2; i++) {                 // A: 128 rows
            int id = tid + i * 256;
            int row = id >> 2, q = id & 3;
            CP_ASYNC16(ab + row*ROWB + q*16,
                       Ap + (size_t)(mBase + row) * K + kof + q*8);
        }
#pragma unroll
        for (int i = 0; i < 4; i++) {                 // B: 256 rows
            int id = tid + i * 256;
            int row = id >> 2, q = id & 3;
            CP_ASYNC16(bb + row*ROWB + q*16,
                       Bp + (size_t)(nBase + row) * K + kof + q*8);
        }
    };

#pragma unroll
    for (int s = 0; s < STG2 - 1; s++) { load_tile(s, s); CP_COMMIT(); }

    const int aRow = (lid & 7) + ((lid >> 3) & 1) * 8;
    const int aKb  = (lid >> 4) * 16;
    const int bRow = (lid & 7) + ((lid >> 4) & 1) * 8;
    const int bKb  = ((lid >> 3) & 1) * 16;

    for (int c = 0; c < NC; c++) {
        CP_WAIT(STG2 - 2);
        __syncthreads();
        if (c + STG2 - 1 < NC) load_tile(c + STG2 - 1, (c + STG2 - 1) % STG2);
        CP_COMMIT();

        uint32_t ab = sb + (c % STG2) * STAGE2B;
        uint32_t bb = ab + A2BYTES;
#pragma unroll
        for (int ks = 0; ks < 2; ks++) {
            uint32_t afr[4][4], bfr[4][4];
#pragma unroll
            for (int i = 0; i < 4; i++)
                ldmx4(afr[i], ab + (wm*64 + i*16 + aRow)*ROWB + ks*32 + aKb);
#pragma unroll
            for (int t = 0; t < 4; t++)
                ldmx4(bfr[t], bb + (wn*64 + t*16 + bRow)*ROWB + ks*32 + bKb);
#pragma unroll
            for (int i = 0; i < 4; i++)
#pragma unroll
                for (int j = 0; j < 8; j++)
                    mma16816(acc[i][j], afr[i], bfr[j >> 1] + (j & 1) * 2);
        }
        __syncthreads();
    }
    CP_WAIT(0);

    const int r0 = lid >> 2;
    const int c0 = (lid & 3) * 2;
#pragma unroll
    for (int i = 0; i < 4; i++) {
#pragma unroll
        for (int j = 0; j < 8; j++) {
            int col = nBase + wn*64 + j*8 + c0;
            int rowA = mBase + wm*64 + i*16 + r0;
            float2 bv = *(const float2*)(bias + col);
            *(float2*)(Cf + (size_t)rowA * Ntot + col) =
                make_float2(acc[i][j][0] + bv.x, acc[i][j][1] + bv.y);
            *(float2*)(Cf + (size_t)(rowA + 8) * Ntot + col) =
                make_float2(acc[i][j][2] + bv.x, acc[i][j][3] + bv.y);
        }
    }
}

// ======================= fp32 SGEMM (small u GEMM only) ====================
#define BM 128
#define BNs 128
#define BKs 8
__global__ void __launch_bounds__(256) sgemm_kernel(
        const float* __restrict__ A, const float* __restrict__ Bm,
        float* __restrict__ C, int K, int N) {
    __shared__ float As[BKs][BM];
    __shared__ float Bs2[BKs][BNs];
    int tid = threadIdx.x;
    int tx = tid & 15, ty = tid >> 4;
    int mBase = blockIdx.y * BM, nBase = blockIdx.x * BNs;
    int aM = tid >> 1, aK = (tid & 1) * 4;
    int bK = tid >> 5, bN = (tid & 31) * 4;
    const float* Aptr = A + (size_t)(mBase + aM) * K + aK;
    const float* Bptr = Bm + (size_t)bK * N + nBase + bN;
    float acc[8][8];
#pragma unroll
    for (int i = 0; i < 8; i++)
#pragma unroll
        for (int j = 0; j < 8; j++) acc[i][j] = 0.f;
    for (int kt = 0; kt < K; kt += BKs) {
        float4 av = *(const float4*)Aptr;  Aptr += BKs;
        float4 bv = *(const float4*)Bptr;  Bptr += (size_t)BKs * N;
        As[aK+0][aM] = av.x; As[aK+1][aM] = av.y;
        As[aK+2][aM] = av.z; As[aK+3][aM] = av.w;
        *(float4*)&Bs2[bK][bN] = bv;
        __syncthreads();
        float ar[8], br[8];
#pragma unroll
        for (int k = 0; k < BKs; k++) {
#pragma unroll
            for (int i = 0; i < 8; i++) ar[i] = As[k][ty*8 + i];
#pragma unroll
            for (int j = 0; j < 8; j++) br[j] = Bs2[k][tx*8 + j];
#pragma unroll
            for (int i = 0; i < 8; i++)
#pragma unroll
                for (int j = 0; j < 8; j++)
                    acc[i][j] = fmaf(ar[i], br[j], acc[i][j]);
        }
        __syncthreads();
    }
#pragma unroll
    for (int i = 0; i < 8; i++) {
        float* Crow = C + (size_t)(mBase + ty*8 + i) * N + nBase + tx*8;
#pragma unroll
        for (int j = 0; j < 8; j++) Crow[j] = acc[i][j];
    }
}

// ======================= stats / gate / mix ================================
__global__ void stats_kernel() {
    int r = blockIdx.x, br = blockIdx.y;
    const float* z = (br ? g_loc : g_lin) + (size_t)r * Vv;
    int tid = threadIdx.x;
    float s = 0.f, sq = 0.f, mx = -3.4e38f;
    for (int i = tid; i < Vv; i += 256) {
        float v = z[i];
        s += v; sq += v*v; mx = fmaxf(mx, v);
    }
    __shared__ float ss[256], ssq[256], smx[256];
    ss[tid] = s; ssq[tid] = sq; smx[tid] = mx;
    __syncthreads();
    for (int off = 128; off > 0; off >>= 1) {
        if (tid < off) {
            ss[tid] += ss[tid+off];
            ssq[tid] += ssq[tid+off];
            smx[tid] = fmaxf(smx[tid], smx[tid+off]);
        }
        __syncthreads();
    }
    if (tid == 0) {
        float mean = ss[0] / (float)Vv;
        float var = fmaxf(ssq[0] / (float)Vv - mean*mean, 0.f);
        float* st = g_stats + (size_t)r*6 + br*3;
        st[0] = mean; st[1] = smx[0]; st[2] = sqrtf(var);
    }
}

__global__ void gate_kernel(const float* __restrict__ gw, const float* __restrict__ gb) {
    int r = blockIdx.x * blockDim.x + threadIdx.x;
    if (r >= Rr) return;
    const float* st = g_stats + (size_t)r*6;
    float acc = gb[0];
#pragma unroll
    for (int k = 0; k < 6; k++) acc += st[k] * gw[k];
    g_gate[r] = 1.f / (1.f + expf(-acc));
}

__global__ void mix_kernel(float* __restrict__ out) {
    int r = blockIdx.y;
    int c = blockIdx.x * blockDim.x + threadIdx.x;
    size_t i = (size_t)r * Vv + c;
    float g = g_gate[r];
    out[i] = g * g_lin[i] + (1.f - g) * g_loc[i];
}

// ======================= launch ============================================
extern "C" void kernel_launch(void* const* d_in, const int* in_sizes, int n_in,
                              void* d_out, int out_size) {
    const int*   tokens  = (const int*)  d_in[0];
    const float* emb     = (const float*)d_in[1];
    const float* in_proj = (const float*)d_in[2];
    const float* decays  = (const float*)d_in[3];
    const float* w1      = (const float*)d_in[4];
    const float* b1      = (const float*)d_in[5];
    const float* w2      = (const float*)d_in[6];
    const float* b2      = (const float*)d_in[7];
    const float* lw1     = (const float*)d_in[8];
    const float* lb1     = (const float*)d_in[9];
    const float* lw2     = (const float*)d_in[10];
    const float* lb2     = (const float*)d_in[11];
    const float* gate_w  = (const float*)d_in[12];
    const float* gate_b  = (const float*)d_in[13];
    float* out = (float*)d_out;

    float *gx, *gu, *gfeat, *glocin, *glin, *gloc;
    cudaGetSymbolAddress((void**)&gx,     g_x);
    cudaGetSymbolAddress((void**)&gu,     g_u);
    cudaGetSymbolAddress((void**)&gfeat,  g_feat);
    cudaGetSymbolAddress((void**)&glocin, g_locin);
    cudaGetSymbolAddress((void**)&glin,   g_lin);
    cudaGetSymbolAddress((void**)&gloc,   g_loc);
    __nv_bfloat16 *fh, *fl, *lih, *lil, *hh, *hl, *h2h, *h2l;
    __nv_bfloat16 *w1h, *w1l, *lw1h, *lw1l, *w2h, *w2l, *lw2h, *lw2l;
    cudaGetSymbolAddress((void**)&fh,   g_feat_hi);
    cudaGetSymbolAddress((void**)&fl,   g_feat_lo);
    cudaGetSymbolAddress((void**)&lih,  g_locin_hi);
    cudaGetSymbolAddress((void**)&lil,  g_locin_lo);
    cudaGetSymbolAddress((void**)&hh,   g_h_hi);
    cudaGetSymbolAddress((void**)&hl,   g_h_lo);
    cudaGetSymbolAddress((void**)&h2h,  g_h2_hi);
    cudaGetSymbolAddress((void**)&h2l,  g_h2_lo);
    cudaGetSymbolAddress((void**)&w1h,  g_w1t_hi);
    cudaGetSymbolAddress((void**)&w1l,  g_w1t_lo);
    cudaGetSymbolAddress((void**)&lw1h, g_lw1t_hi);
    cudaGetSymbolAddress((void**)&lw1l, g_lw1t_lo);
    cudaGetSymbolAddress((void**)&w2h,  g_w2t_hi);
    cudaGetSymbolAddress((void**)&w2l,  g_w2t_lo);
    cudaGetSymbolAddress((void**)&lw2h, g_lw2t_hi);
    cudaGetSymbolAddress((void**)&lw2l, g_lw2t_lo);

    constexpr int SMEMB  = STAGES * STAGEB;   // 61440
    constexpr int SMEMB2 = STG2 * STAGE2B;    // 122880
    cudaFuncSetAttribute(hmma_kernel,    cudaFuncAttributeMaxDynamicSharedMemorySize, SMEMB);
    cudaFuncSetAttribute(hmma256_kernel, cudaFuncAttributeMaxDynamicSharedMemorySize, SMEMB2);

    // 1) embedding gather
    gather_embed_kernel<<<Rr, Dd>>>(tokens, emb);
    // 2) u = x @ in_proj
    sgemm_kernel<<<dim3(Mm/BNs, Rr/BM), 256>>>(gx, in_proj, gu, Dd, Mm);
    // 3) decay scan
    scan_kernel<<<Bb, Mm>>>(decays);
    // 4) window features
    build_loc_kernel<<<(Rr*Ww*Dd + 255)/256, 256>>>();
    // 5) split conversions of activations
    conv_split_kernel<<<(Rr*F1/4 + 255)/256, 256>>>(gfeat,  fh,  fl,  Rr*F1/4);
    conv_split_kernel<<<(Rr*F2/4 + 255)/256, 256>>>(glocin, lih, lil, Rr*F2/4);
    // 6) weight transpose+split conversions
    wtconv_kernel<<<dim3(HLh/32, F1/32),  256>>>(w1,  w1h,  w1l,  F1,  HLh);
    wtconv_kernel<<<dim3(HCh/32, F2/32),  256>>>(lw1, lw1h, lw1l, F2,  HCh);
    wtconv_kernel<<<dim3(Vv/32,  HLh/32), 256>>>(w2,  w2h,  w2l,  HLh, Vv);
    wtconv_kernel<<<dim3(Vv/32,  HCh/32), 256>>>(lw2, lw2h, lw2l, HCh, Vv);
    // 7) h = relu(feat @ w1 + b1) -> split bf16
    hmma_kernel<<<dim3(Rr/128, HLh/128), 256, SMEMB>>>(
        fh, fl, w1h, w1l, b1, hh, hl, F1, HLh);
    // 8) h2 = relu(loc @ lw1 + lb1) -> split bf16
    hmma_kernel<<<dim3(Rr/128, HCh/128), 256, SMEMB>>>(
        lih, lil, lw1h, lw1l, lb1, h2h, h2l, F2, HCh);
    // 9) lin_logits = h @ w2 + b2     (128x256 tiles)
    hmma256_kernel<<<dim3(Rr/128, Vv/256), 256, SMEMB2>>>(
        hh, hl, w2h, w2l, b2, glin, HLh, Vv);
    // 10) loc_logits = h2 @ lw2 + lb2
    hmma256_kernel<<<dim3(Rr/128, Vv/256), 256, SMEMB2>>>(
        h2h, h2l, lw2h, lw2l, lb2, gloc, HCh, Vv);
    // 11) stats, gate, mix
    stats_kernel<<<dim3(Rr, 2), 256>>>();
    gate_kernel<<<(Rr + 255)/256, 256>>>(gate_w, gate_b);
    mix_kernel<<<dim3(Vv/256, Rr), 256>>>(out);
}

// round 11
// speedup vs baseline: 1.2042x; 1.2002x over previous
#include <cuda_runtime.h>
#include <cuda_bf16.h>
#include <cstdint>
#include <math.h>

#define Bb   2
#define Ss   1024
#define Vv   32000
#define Dd   256
#define Mm   256
#define Ww   8
#define HLh  1024
#define HCh  1024
#define Rr   (Bb*Ss)          // 2048
#define F1   (Mm+Dd)          // 512
#define F2   (Ww*Dd)          // 2048

// ======================= helpers ===========================================
__device__ __forceinline__ uint32_t smem_u32(const void* p) {
    uint32_t a;
    asm("{ .reg .u64 t; cvta.to.shared.u64 t, %1; cvt.u32.u64 %0, t; }" : "=r"(a) : "l"(p));
    return a;
}
#define CP_ASYNC16(dst, src) \
    asm volatile("cp.async.cg.shared.global [%0], [%1], 16;" :: "r"(dst), "l"(src))
#define CP_COMMIT() asm volatile("cp.async.commit_group;" ::: "memory")
#define CP_WAIT(n)  asm volatile("cp.async.wait_group %0;" :: "n"(n) : "memory")

__device__ __forceinline__ void ldmx4(uint32_t* r, uint32_t addr) {
    asm volatile("ldmatrix.sync.aligned.m8n8.x4.shared.b16 {%0,%1,%2,%3}, [%4];"
        : "=r"(r[0]), "=r"(r[1]), "=r"(r[2]), "=r"(r[3]) : "r"(addr));
}
__device__ __forceinline__ void mma16816(float* c, const uint32_t* a, const uint32_t* b) {
    asm volatile(
        "mma.sync.aligned.m16n8k16.row.col.f32.bf16.bf16.f32 "
        "{%0,%1,%2,%3}, {%4,%5,%6,%7}, {%8,%9}, {%0,%1,%2,%3};"
        : "+f"(c[0]), "+f"(c[1]), "+f"(c[2]), "+f"(c[3])
        : "r"(a[0]), "r"(a[1]), "r"(a[2]), "r"(a[3]), "r"(b[0]), "r"(b[1]));
}
// monotonic float<->uint encode for atomicMax over signed floats
__device__ __forceinline__ uint32_t fenc(float f) {
    uint32_t i = __float_as_uint(f);
    return (i & 0x80000000u) ? ~i : (i | 0x80000000u);
}
__device__ __forceinline__ float fdec(uint32_t u) {
    return (u & 0x80000000u) ? __uint_as_float(u & 0x7FFFFFFFu) : __uint_as_float(~u);
}

// ======================= scratch ===========================================
__device__ float g_x[Rr*Dd];
__device__ float g_u[Rr*Mm];
__device__ float g_lin[(size_t)Rr*Vv];
__device__ float g_loc[(size_t)Rr*Vv];
__device__ float g_gate[Rr];
// per-row stats accumulators [branch][row]
__device__ float    g_rs[2][Rr];
__device__ float    g_rss[2][Rr];
__device__ uint32_t g_rmx[2][Rr];
// bf16 split operands
__device__ __nv_bfloat16 g_feat_hi[Rr*F1],  g_feat_lo[Rr*F1];
__device__ __nv_bfloat16 g_locin_hi[Rr*F2], g_locin_lo[Rr*F2];
__device__ __nv_bfloat16 g_h_hi[Rr*HLh],    g_h_lo[Rr*HLh];
__device__ __nv_bfloat16 g_h2_hi[Rr*HCh],   g_h2_lo[Rr*HCh];
__device__ __nv_bfloat16 g_w1t_hi[HLh*F1],  g_w1t_lo[HLh*F1];
__device__ __nv_bfloat16 g_lw1t_hi[HCh*F2], g_lw1t_lo[HCh*F2];
__device__ __nv_bfloat16 g_w2t_hi[(size_t)Vv*HLh],  g_w2t_lo[(size_t)Vv*HLh];
__device__ __nv_bfloat16 g_lw2t_hi[(size_t)Vv*HCh], g_lw2t_lo[(size_t)Vv*HCh];

// ======================= small kernels =====================================
// embedding gather: fills g_x and feat hi/lo [:, M:]
__global__ void gather_embed_kernel(const int* __restrict__ tok,
                                    const float* __restrict__ emb) {
    int r = blockIdx.x, d = threadIdx.x;
    float v = emb[(size_t)tok[r] * Dd + d];
    g_x[r*Dd + d] = v;
    __nv_bfloat16 h = __float2bfloat16(v);
    g_feat_hi[(size_t)r*F1 + Mm + d] = h;
    g_feat_lo[(size_t)r*F1 + Mm + d] = __float2bfloat16(v - __bfloat162float(h));
}

// decay scan, writing feat hi/lo directly
__global__ void scan_kernel(const float* __restrict__ decays) {
    int b = blockIdx.x, m = threadIdx.x;
    float a = decays[m], s = 0.f;
    for (int t = 0; t < Ss; t++) {
        int r = b*Ss + t;
        s = a*s + g_u[(size_t)r*Mm + m];
        __nv_bfloat16 h = __float2bfloat16(s);
        g_feat_hi[(size_t)r*F1 + m] = h;
        g_feat_lo[(size_t)r*F1 + m] = __float2bfloat16(s - __bfloat162float(h));
    }
}

// fused window build + bf16 split (no fp32 locin)
__global__ void build_loc_split_kernel() {
    int idx = blockIdx.x * blockDim.x + threadIdx.x;
    if (idx >= Rr*Ww*Dd) return;
    int d = idx % Dd, w = (idx / Dd) % Ww, r = idx / (Ww*Dd);
    int s = r % Ss, b = r / Ss;
    int ss = s - (Ww-1) + w;
    float v = (ss >= 0) ? g_x[((size_t)(b*Ss + ss))*Dd + d] : 0.f;
    __nv_bfloat16 h = __float2bfloat16(v);
    g_locin_hi[idx] = h;
    g_locin_lo[idx] = __float2bfloat16(v - __bfloat162float(h));
}

// transpose+split: W[K,N] fp32 row-major -> Wt hi/lo [N,K] bf16
__global__ void wtconv_kernel(const float* __restrict__ W,
                              __nv_bfloat16* __restrict__ hi,
                              __nv_bfloat16* __restrict__ lo, int K, int N) {
    __shared__ float t[32][33];
    int n0 = blockIdx.x * 32, k0 = blockIdx.y * 32;
    int tx = threadIdx.x & 31, ty = threadIdx.x >> 5;
#pragma unroll
    for (int r = 0; r < 4; r++)
        t[ty + 8*r][tx] = W[(size_t)(k0 + ty + 8*r) * N + n0 + tx];
    __syncthreads();
#pragma unroll
    for (int r = 0; r < 4; r++) {
        int n = n0 + ty + 8*r, k = k0 + tx;
        float v = t[tx][ty + 8*r];
        __nv_bfloat16 h = __float2bfloat16(v);
        hi[(size_t)n*K + k] = h;
        lo[(size_t)n*K + k] = __float2bfloat16(v - __bfloat162float(h));
    }
}

// init stats accumulators (encode(-FLT_MAX) > 0x0 for all finite, 0 is safe floor)
__global__ void init_stats_kernel() {
    int i = blockIdx.x * blockDim.x + threadIdx.x;
    if (i >= 2*Rr) return;
    ((float*)g_rs)[i] = 0.f;
    ((float*)g_rss)[i] = 0.f;
    ((uint32_t*)g_rmx)[i] = 0u;
}

// ============ HMMA GEMM, CTA 128x128 (hidden layers, ReLU+split out) =======
#define STAGES 3
#define ROWB   80
#define ABYTES (128*ROWB)
#define STAGEB (2*ABYTES)

__global__ void __launch_bounds__(256, 2) hmma_kernel(
        const __nv_bfloat16* __restrict__ Ahi, const __nv_bfloat16* __restrict__ Alo,
        const __nv_bfloat16* __restrict__ Bhi, const __nv_bfloat16* __restrict__ Blo,
        const float* __restrict__ bias,
        __nv_bfloat16* __restrict__ Chi, __nv_bfloat16* __restrict__ Clo,
        int K, int Ntot) {
    extern __shared__ char smem[];
    const uint32_t sb = smem_u32(smem);
    const int tid = threadIdx.x;
    const int wid = tid >> 5, lid = tid & 31;
    const int wm = wid & 3, wn = wid >> 2;          // 4 M x 2 N
    const int mBase = blockIdx.x * 128;
    const int nBase = blockIdx.y * 128;

    const int KC = K / 32;
    const int NC = 3 * KC;

    float acc[2][8][4];
#pragma unroll
    for (int i = 0; i < 2; i++)
#pragma unroll
        for (int j = 0; j < 8; j++)
#pragma unroll
            for (int q = 0; q < 4; q++) acc[i][j][q] = 0.f;

    auto load_tile = [&](int c, int s) {
        int pass = c / KC, kc = c - pass * KC;
        const __nv_bfloat16* Ap = (pass == 1) ? Alo : Ahi;
        const __nv_bfloat16* Bp = (pass == 2) ? Blo : Bhi;
        int kof = kc * 32;
        uint32_t ab = sb + s * STAGEB;
        uint32_t bb = ab + ABYTES;
#pragma unroll
        for (int i = 0; i < 2; i++) {
            int id = tid + i * 256;
            int row = id >> 2, q = id & 3;
            CP_ASYNC16(ab + row*ROWB + q*16,
                       Ap + (size_t)(mBase + row) * K + kof + q*8);
        }
#pragma unroll
        for (int i = 0; i < 2; i++) {
            int id = tid + i * 256;
            int row = id >> 2, q = id & 3;
            CP_ASYNC16(bb + row*ROWB + q*16,
                       Bp + (size_t)(nBase + row) * K + kof + q*8);
        }
    };

#pragma unroll
    for (int s = 0; s < STAGES - 1; s++) { load_tile(s, s); CP_COMMIT(); }

    const int aRow = (lid & 7) + ((lid >> 3) & 1) * 8;
    const int aKb  = (lid >> 4) * 16;
    const int bRow = (lid & 7) + ((lid >> 4) & 1) * 8;
    const int bKb  = ((lid >> 3) & 1) * 16;

    for (int c = 0; c < NC; c++) {
        CP_WAIT(STAGES - 2);
        __syncthreads();
        if (c + STAGES - 1 < NC) load_tile(c + STAGES - 1, (c + STAGES - 1) % STAGES);
        CP_COMMIT();

        uint32_t ab = sb + (c % STAGES) * STAGEB;
        uint32_t bb = ab + ABYTES;
#pragma unroll
        for (int ks = 0; ks < 2; ks++) {
            uint32_t afr[2][4], bfr[4][4];
#pragma unroll
            for (int i = 0; i < 2; i++)
                ldmx4(afr[i], ab + (wm*32 + i*16 + aRow)*ROWB + ks*32 + aKb);
#pragma unroll
            for (int t = 0; t < 4; t++)
                ldmx4(bfr[t], bb + (wn*64 + t*16 + bRow)*ROWB + ks*32 + bKb);
#pragma unroll
            for (int i = 0; i < 2; i++)
#pragma unroll
                for (int j = 0; j < 8; j++)
                    mma16816(acc[i][j], afr[i], bfr[j >> 1] + (j & 1) * 2);
        }
        __syncthreads();
    }
    CP_WAIT(0);

    const int r0 = lid >> 2;
    const int c0 = (lid & 3) * 2;
#pragma unroll
    for (int i = 0; i < 2; i++) {
#pragma unroll
        for (int j = 0; j < 8; j++) {
            int col = nBase + wn*64 + j*8 + c0;
            int rowA = mBase + wm*32 + i*16 + r0;
            float2 bv = *(const float2*)(bias + col);
            float v0 = fmaxf(acc[i][j][0] + bv.x, 0.f);
            float v1 = fmaxf(acc[i][j][1] + bv.y, 0.f);
            float v2 = fmaxf(acc[i][j][2] + bv.x, 0.f);
            float v3 = fmaxf(acc[i][j][3] + bv.y, 0.f);
            __nv_bfloat16 h0 = __float2bfloat16(v0), h1 = __float2bfloat16(v1);
            __nv_bfloat16 h2 = __float2bfloat16(v2), h3 = __float2bfloat16(v3);
            *(__nv_bfloat162*)(Chi + (size_t)rowA * Ntot + col) = __nv_bfloat162{h0, h1};
            *(__nv_bfloat162*)(Chi + (size_t)(rowA+8) * Ntot + col) = __nv_bfloat162{h2, h3};
            *(__nv_bfloat162*)(Clo + (size_t)rowA * Ntot + col) =
                __nv_bfloat162{__float2bfloat16(v0 - __bfloat162float(h0)),
                               __float2bfloat16(v1 - __bfloat162float(h1))};
            *(__nv_bfloat162*)(Clo + (size_t)(rowA+8) * Ntot + col) =
                __nv_bfloat162{__float2bfloat16(v2 - __bfloat162float(h2)),
                               __float2bfloat16(v3 - __bfloat162float(h3))};
        }
    }
}

// ============ HMMA GEMM, CTA 128x128 (logits, fp32 out + fused row stats) ===
__global__ void __launch_bounds__(256, 2) hmma_logits_kernel(
        const __nv_bfloat16* __restrict__ Ahi, const __nv_bfloat16* __restrict__ Alo,
        const __nv_bfloat16* __restrict__ Bhi, const __nv_bfloat16* __restrict__ Blo,
        const float* __restrict__ bias,
        float* __restrict__ Cf,
        float* __restrict__ rs, float* __restrict__ rss, uint32_t* __restrict__ rmx,
        int K, int Ntot) {
    extern __shared__ char smem[];
    const uint32_t sb = smem_u32(smem);
    const int tid = threadIdx.x;
    const int wid = tid >> 5, lid = tid & 31;
    const int wm = wid & 3, wn = wid >> 2;
    const int mBase = blockIdx.x * 128;
    const int nBase = blockIdx.y * 128;

    const int KC = K / 32;
    const int NC = 3 * KC;

    float acc[2][8][4];
#pragma unroll
    for (int i = 0; i < 2; i++)
#pragma unroll
        for (int j = 0; j < 8; j++)
#pragma unroll
            for (int q = 0; q < 4; q++) acc[i][j][q] = 0.f;

    auto load_tile = [&](int c, int s) {
        int pass = c / KC, kc = c - pass * KC;
        const __nv_bfloat16* Ap = (pass == 1) ? Alo : Ahi;
        const __nv_bfloat16* Bp = (pass == 2) ? Blo : Bhi;
        int kof = kc * 32;
        uint32_t ab = sb + s * STAGEB;
        uint32_t bb = ab + ABYTES;
#pragma unroll
        for (int i = 0; i < 2; i++) {
            int id = tid + i * 256;
            int row = id >> 2, q = id & 3;
            CP_ASYNC16(ab + row*ROWB + q*16,
                       Ap + (size_t)(mBase + row) * K + kof + q*8);
        }
#pragma unroll
        for (int i = 0; i < 2; i++) {
            int id = tid + i * 256;
            int row = id >> 2, q = id & 3;
            CP_ASYNC16(bb + row*ROWB + q*16,
                       Bp + (size_t)(nBase + row) * K + kof + q*8);
        }
    };

#pragma unroll
    for (int s = 0; s < STAGES - 1; s++) { load_tile(s, s); CP_COMMIT(); }

    const int aRow = (lid & 7) + ((lid >> 3) & 1) * 8;
    const int aKb  = (lid >> 4) * 16;
    const int bRow = (lid & 7) + ((lid >> 4) & 1) * 8;
    const int bKb  = ((lid >> 3) & 1) * 16;

    for (int c = 0; c < NC; c++) {
        CP_WAIT(STAGES - 2);
        __syncthreads();
        if (c + STAGES - 1 < NC) load_tile(c + STAGES - 1, (c + STAGES - 1) % STAGES);
        CP_COMMIT();

        uint32_t ab = sb + (c % STAGES) * STAGEB;
        uint32_t bb = ab + ABYTES;
#pragma unroll
        for (int ks = 0; ks < 2; ks++) {
            uint32_t afr[2][4], bfr[4][4];
#pragma unroll
            for (int i = 0; i < 2; i++)
                ldmx4(afr[i], ab + (wm*32 + i*16 + aRow)*ROWB + ks*32 + aKb);
#pragma unroll
            for (int t = 0; t < 4; t++)
                ldmx4(bfr[t], bb + (wn*64 + t*16 + bRow)*ROWB + ks*32 + bKb);
#pragma unroll
            for (int i = 0; i < 2; i++)
#pragma unroll
                for (int j = 0; j < 8; j++)
                    mma16816(acc[i][j], afr[i], bfr[j >> 1] + (j & 1) * 2);
        }
        __syncthreads();
    }
    CP_WAIT(0);

    const int r0 = lid >> 2;
    const int c0 = (lid & 3) * 2;
    // per-thread partials for its 4 rows: t = i*2 + half
    float ps[4], pq[4], pm[4];
#pragma unroll
    for (int t = 0; t < 4; t++) { ps[t] = 0.f; pq[t] = 0.f; pm[t] = -3.4e38f; }

#pragma unroll
    for (int i = 0; i < 2; i++) {
#pragma unroll
        for (int j = 0; j < 8; j++) {
            int col = nBase + wn*64 + j*8 + c0;
            int rowA = mBase + wm*32 + i*16 + r0;
            float2 bv = *(const float2*)(bias + col);
            float v0 = acc[i][j][0] + bv.x, v1 = acc[i][j][1] + bv.y;
            float v2 = acc[i][j][2] + bv.x, v3 = acc[i][j][3] + bv.y;
            *(float2*)(Cf + (size_t)rowA * Ntot + col)       = make_float2(v0, v1);
            *(float2*)(Cf + (size_t)(rowA + 8) * Ntot + col) = make_float2(v2, v3);
            ps[2*i]   += v0 + v1;  pq[2*i]   += v0*v0 + v1*v1;
            pm[2*i]    = fmaxf(pm[2*i], fmaxf(v0, v1));
            ps[2*i+1] += v2 + v3;  pq[2*i+1] += v2*v2 + v3*v3;
            pm[2*i+1]  = fmaxf(pm[2*i+1], fmaxf(v2, v3));
        }
    }
    // reduce across the 4 lanes sharing each row (lid&3)
#pragma unroll
    for (int t = 0; t < 4; t++) {
#pragma unroll
        for (int m = 1; m <= 2; m <<= 1) {
            ps[t] += __shfl_xor_sync(0xffffffffu, ps[t], m);
            pq[t] += __shfl_xor_sync(0xffffffffu, pq[t], m);
            pm[t]  = fmaxf(pm[t], __shfl_xor_sync(0xffffffffu, pm[t], m));
        }
    }
    if ((lid & 3) == 0) {
#pragma unroll
        for (int t = 0; t < 4; t++) {
            int row = mBase + wm*32 + (t >> 1)*16 + r0 + (t & 1)*8;
            atomicAdd(rs + row, ps[t]);
            atomicAdd(rss + row, pq[t]);
            atomicMax(rmx + row, fenc(pm[t]));
        }
    }
}

// ======================= fp32 SGEMM (small u GEMM only) ====================
#define BM 128
#define BNs 128
#define BKs 8
__global__ void __launch_bounds__(256) sgemm_kernel(
        const float* __restrict__ A, const float* __restrict__ Bm,
        float* __restrict__ C, int K, int N) {
    __shared__ float As[BKs][BM];
    __shared__ float Bs2[BKs][BNs];
    int tid = threadIdx.x;
    int tx = tid & 15, ty = tid >> 4;
    int mBase = blockIdx.y * BM, nBase = blockIdx.x * BNs;
    int aM = tid >> 1, aK = (tid & 1) * 4;
    int bK = tid >> 5, bN = (tid & 31) * 4;
    const float* Aptr = A + (size_t)(mBase + aM) * K + aK;
    const float* Bptr = Bm + (size_t)bK * N + nBase + bN;
    float acc[8][8];
#pragma unroll
    for (int i = 0; i < 8; i++)
#pragma unroll
        for (int j = 0; j < 8; j++) acc[i][j] = 0.f;
    for (int kt = 0; kt < K; kt += BKs) {
        float4 av = *(const float4*)Aptr;  Aptr += BKs;
        float4 bv = *(const float4*)Bptr;  Bptr += (size_t)BKs * N;
        As[aK+0][aM] = av.x; As[aK+1][aM] = av.y;
        As[aK+2][aM] = av.z; As[aK+3][aM] = av.w;
        *(float4*)&Bs2[bK][bN] = bv;
        __syncthreads();
        float ar[8], br[8];
#pragma unroll
        for (int k = 0; k < BKs; k++) {
#pragma unroll
            for (int i = 0; i < 8; i++) ar[i] = As[k][ty*8 + i];
#pragma unroll
            for (int j = 0; j < 8; j++) br[j] = Bs2[k][tx*8 + j];
#pragma unroll
            for (int i = 0; i < 8; i++)
#pragma unroll
                for (int j = 0; j < 8; j++)
                    acc[i][j] = fmaf(ar[i], br[j], acc[i][j]);
        }
        __syncthreads();
    }
#pragma unroll
    for (int i = 0; i < 8; i++) {
        float* Crow = C + (size_t)(mBase + ty*8 + i) * N + nBase + tx*8;
#pragma unroll
        for (int j = 0; j < 8; j++) Crow[j] = acc[i][j];
    }
}

// ======================= gate / mix ========================================
__global__ void gate_finalize_kernel(const float* __restrict__ gw,
                                     const float* __restrict__ gb) {
    int r = blockIdx.x * blockDim.x + threadIdx.x;
    if (r >= Rr) return;
    const float inv = 1.f / (float)Vv;
    float mean0 = g_rs[0][r] * inv;
    float std0  = sqrtf(fmaxf(g_rss[0][r] * inv - mean0*mean0, 0.f));
    float max0  = fdec(g_rmx[0][r]);
    float mean1 = g_rs[1][r] * inv;
    float std1  = sqrtf(fmaxf(g_rss[1][r] * inv - mean1*mean1, 0.f));
    float max1  = fdec(g_rmx[1][r]);
    float z = gb[0] + gw[0]*mean0 + gw[1]*max0 + gw[2]*std0
                    + gw[3]*mean1 + gw[4]*max1 + gw[5]*std1;
    g_gate[r] = 1.f / (1.f + expf(-z));
}

__global__ void mix_kernel(float* __restrict__ out) {
    int r = blockIdx.y;
    int c4 = blockIdx.x * blockDim.x + threadIdx.x;   // float4 index
    if (c4 >= Vv/4) return;
    size_t i = (size_t)r * (Vv/4) + c4;
    float g = g_gate[r], og = 1.f - g;
    float4 a = ((const float4*)g_lin)[i];
    float4 b = ((const float4*)g_loc)[i];
    float4 o;
    o.x = g*a.x + og*b.x;  o.y = g*a.y + og*b.y;
    o.z = g*a.z + og*b.z;  o.w = g*a.w + og*b.w;
    ((float4*)out)[i] = o;
}

// ======================= launch ============================================
extern "C" void kernel_launch(void* const* d_in, const int* in_sizes, int n_in,
                              void* d_out, int out_size) {
    const int*   tokens  = (const int*)  d_in[0];
    const float* emb     = (const float*)d_in[1];
    const float* in_proj = (const float*)d_in[2];
    const float* decays  = (const float*)d_in[3];
    const float* w1      = (const float*)d_in[4];
    const float* b1      = (const float*)d_in[5];
    const float* w2      = (const float*)d_in[6];
    const float* b2      = (const float*)d_in[7];
    const float* lw1     = (const float*)d_in[8];
    const float* lb1     = (const float*)d_in[9];
    const float* lw2     = (const float*)d_in[10];
    const float* lb2     = (const float*)d_in[11];
    const float* gate_w  = (const float*)d_in[12];
    const float* gate_b  = (const float*)d_in[13];
    float* out = (float*)d_out;

    float *gx, *gu, *glin, *gloc, *grs, *grss;
    uint32_t* grmx;
    cudaGetSymbolAddress((void**)&gx,   g_x);
    cudaGetSymbolAddress((void**)&gu,   g_u);
    cudaGetSymbolAddress((void**)&glin, g_lin);
    cudaGetSymbolAddress((void**)&gloc, g_loc);
    cudaGetSymbolAddress((void**)&grs,  g_rs);
    cudaGetSymbolAddress((void**)&grss, g_rss);
    cudaGetSymbolAddress((void**)&grmx, g_rmx);
    __nv_bfloat16 *fh, *fl, *lih, *lil, *hh, *hl, *h2h, *h2l;
    __nv_bfloat16 *w1h, *w1l, *lw1h, *lw1l, *w2h, *w2l, *lw2h, *lw2l;
    cudaGetSymbolAddress((void**)&fh,   g_feat_hi);
    cudaGetSymbolAddress((void**)&fl,   g_feat_lo);
    cudaGetSymbolAddress((void**)&lih,  g_locin_hi);
    cudaGetSymbolAddress((void**)&lil,  g_locin_lo);
    cudaGetSymbolAddress((void**)&hh,   g_h_hi);
    cudaGetSymbolAddress((void**)&hl,   g_h_lo);
    cudaGetSymbolAddress((void**)&h2h,  g_h2_hi);
    cudaGetSymbolAddress((void**)&h2l,  g_h2_lo);
    cudaGetSymbolAddress((void**)&w1h,  g_w1t_hi);
    cudaGetSymbolAddress((void**)&w1l,  g_w1t_lo);
    cudaGetSymbolAddress((void**)&lw1h, g_lw1t_hi);
    cudaGetSymbolAddress((void**)&lw1l, g_lw1t_lo);
    cudaGetSymbolAddress((void**)&w2h,  g_w2t_hi);
    cudaGetSymbolAddress((void**)&w2l,  g_w2t_lo);
    cudaGetSymbolAddress((void**)&lw2h, g_lw2t_hi);
    cudaGetSymbolAddress((void**)&lw2l, g_lw2t_lo);

    constexpr int SMEMB = STAGES * STAGEB;   // 61440
    cudaFuncSetAttribute(hmma_kernel, cudaFuncAttributeMaxDynamicSharedMemorySize, SMEMB);
    cudaFuncSetAttribute(hmma_logits_kernel, cudaFuncAttributeMaxDynamicSharedMemorySize, SMEMB);

    // 1) embedding gather (+ feat hi/lo cols M..)
    gather_embed_kernel<<<Rr, Dd>>>(tokens, emb);
    // 2) u = x @ in_proj
    sgemm_kernel<<<dim3(Mm/BNs, Rr/BM), 256>>>(gx, in_proj, gu, Dd, Mm);
    // 3) decay scan -> feat hi/lo cols 0..M
    scan_kernel<<<Bb, Mm>>>(decays);
    // 4) fused window build + split
    build_loc_split_kernel<<<(Rr*Ww*Dd + 255)/256, 256>>>();
    // 5) weight transpose+split conversions
    wtconv_kernel<<<dim3(HLh/32, F1/32),  256>>>(w1,  w1h,  w1l,  F1,  HLh);
    wtconv_kernel<<<dim3(HCh/32, F2/32),  256>>>(lw1, lw1h, lw1l, F2,  HCh);
    wtconv_kernel<<<dim3(Vv/32,  HLh/32), 256>>>(w2,  w2h,  w2l,  HLh, Vv);
    wtconv_kernel<<<dim3(Vv/32,  HCh/32), 256>>>(lw2, lw2h, lw2l, HCh, Vv);
    // 6) init stats accumulators
    init_stats_kernel<<<(2*Rr + 255)/256, 256>>>();
    // 7) h = relu(feat @ w1 + b1) -> split bf16
    hmma_kernel<<<dim3(Rr/128, HLh/128), 256, SMEMB>>>(
        fh, fl, w1h, w1l, b1, hh, hl, F1, HLh);
    // 8) h2 = relu(loc @ lw1 + lb1) -> split bf16
    hmma_kernel<<<dim3(Rr/128, HCh/128), 256, SMEMB>>>(
        lih, lil, lw1h, lw1l, lb1, h2h, h2l, F2, HCh);
    // 9) lin_logits = h @ w2 + b2 (+ fused row stats)
    hmma_logits_kernel<<<dim3(Rr/128, Vv/128), 256, SMEMB>>>(
        hh, hl, w2h, w2l, b2, glin, grs, grss, grmx, HLh, Vv);
    // 10) loc_logits = h2 @ lw2 + lb2 (+ fused row stats)
    hmma_logits_kernel<<<dim3(Rr/128, Vv/128), 256, SMEMB>>>(
        h2h, h2l, lw2h, lw2l, lb2, gloc, grs + Rr, grss + Rr, grmx + Rr, HCh, Vv);
    // 11) gate from accumulated stats, then mix
    gate_finalize_kernel<<<(Rr + 255)/256, 256>>>(gate_w, gate_b);
    mix_kernel<<<dim3((Vv/4 + 255)/256, Rr), 256>>>(out);
}

// round 12
// speedup vs baseline: 1.6500x; 1.3702x over previous
#include <cuda_runtime.h>
#include <cuda_bf16.h>
#include <cuda_fp16.h>
#include <cstdint>
#include <math.h>

#define Bb   2
#define Ss   1024
#define Vv   32000
#define Dd   256
#define Mm   256
#define Ww   8
#define HLh  1024
#define HCh  1024
#define Rr   (Bb*Ss)          // 2048
#define F1   (Mm+Dd)          // 512
#define F2   (Ww*Dd)          // 2048

// ======================= helpers ===========================================
__device__ __forceinline__ uint32_t smem_u32(const void* p) {
    uint32_t a;
    asm("{ .reg .u64 t; cvta.to.shared.u64 t, %1; cvt.u32.u64 %0, t; }" : "=r"(a) : "l"(p));
    return a;
}
#define CP_ASYNC16(dst, src) \
    asm volatile("cp.async.cg.shared.global [%0], [%1], 16;" :: "r"(dst), "l"(src))
#define CP_COMMIT() asm volatile("cp.async.commit_group;" ::: "memory")
#define CP_WAIT(n)  asm volatile("cp.async.wait_group %0;" :: "n"(n) : "memory")

__device__ __forceinline__ void ldmx4(uint32_t* r, uint32_t addr) {
    asm volatile("ldmatrix.sync.aligned.m8n8.x4.shared.b16 {%0,%1,%2,%3}, [%4];"
        : "=r"(r[0]), "=r"(r[1]), "=r"(r[2]), "=r"(r[3]) : "r"(addr));
}
__device__ __forceinline__ void mma_bf16(float* c, const uint32_t* a, const uint32_t* b) {
    asm volatile(
        "mma.sync.aligned.m16n8k16.row.col.f32.bf16.bf16.f32 "
        "{%0,%1,%2,%3}, {%4,%5,%6,%7}, {%8,%9}, {%0,%1,%2,%3};"
        : "+f"(c[0]), "+f"(c[1]), "+f"(c[2]), "+f"(c[3])
        : "r"(a[0]), "r"(a[1]), "r"(a[2]), "r"(a[3]), "r"(b[0]), "r"(b[1]));
}
__device__ __forceinline__ void mma_f16(float* c, const uint32_t* a, const uint32_t* b) {
    asm volatile(
        "mma.sync.aligned.m16n8k16.row.col.f32.f16.f16.f32 "
        "{%0,%1,%2,%3}, {%4,%5,%6,%7}, {%8,%9}, {%0,%1,%2,%3};"
        : "+f"(c[0]), "+f"(c[1]), "+f"(c[2]), "+f"(c[3])
        : "r"(a[0]), "r"(a[1]), "r"(a[2]), "r"(a[3]), "r"(b[0]), "r"(b[1]));
}
// monotonic float<->uint encode for atomicMax over signed floats
__device__ __forceinline__ uint32_t fenc(float f) {
    uint32_t i = __float_as_uint(f);
    return (i & 0x80000000u) ? ~i : (i | 0x80000000u);
}
__device__ __forceinline__ float fdec(uint32_t u) {
    return (u & 0x80000000u) ? __uint_as_float(u & 0x7FFFFFFFu) : __uint_as_float(~u);
}

// ======================= scratch ===========================================
__device__ float g_x[Rr*Dd];
__device__ float g_u[Rr*Mm];
__device__ float g_lin[(size_t)Rr*Vv];
__device__ float g_loc[(size_t)Rr*Vv];
__device__ float g_gate[Rr];
__device__ float    g_rs[2][Rr];
__device__ float    g_rss[2][Rr];
__device__ uint32_t g_rmx[2][Rr];
// bf16 split operands (hidden layers)
__device__ __nv_bfloat16 g_feat_hi[Rr*F1],  g_feat_lo[Rr*F1];
__device__ __nv_bfloat16 g_locin_hi[Rr*F2], g_locin_lo[Rr*F2];
__device__ __nv_bfloat16 g_w1t_hi[HLh*F1],  g_w1t_lo[HLh*F1];
__device__ __nv_bfloat16 g_lw1t_hi[HCh*F2], g_lw1t_lo[HCh*F2];
// fp16 operands (logits layers)
__device__ __half g_h_hi[Rr*HLh],  g_h_lo[Rr*HLh];
__device__ __half g_h2_hi[Rr*HCh], g_h2_lo[Rr*HCh];
__device__ __half g_w2t[(size_t)Vv*HLh];
__device__ __half g_lw2t[(size_t)Vv*HCh];

// ======================= small kernels =====================================
__global__ void gather_embed_kernel(const int* __restrict__ tok,
                                    const float* __restrict__ emb) {
    int r = blockIdx.x, d = threadIdx.x;
    float v = emb[(size_t)tok[r] * Dd + d];
    g_x[r*Dd + d] = v;
    __nv_bfloat16 h = __float2bfloat16(v);
    g_feat_hi[(size_t)r*F1 + Mm + d] = h;
    g_feat_lo[(size_t)r*F1 + Mm + d] = __float2bfloat16(v - __bfloat162float(h));
}

__global__ void scan_kernel(const float* __restrict__ decays) {
    int b = blockIdx.x, m = threadIdx.x;
    float a = decays[m], s = 0.f;
    for (int t = 0; t < Ss; t++) {
        int r = b*Ss + t;
        s = a*s + g_u[(size_t)r*Mm + m];
        __nv_bfloat16 h = __float2bfloat16(s);
        g_feat_hi[(size_t)r*F1 + m] = h;
        g_feat_lo[(size_t)r*F1 + m] = __float2bfloat16(s - __bfloat162float(h));
    }
}

__global__ void build_loc_split_kernel() {
    int idx = blockIdx.x * blockDim.x + threadIdx.x;
    if (idx >= Rr*Ww*Dd) return;
    int d = idx % Dd, w = (idx / Dd) % Ww, r = idx / (Ww*Dd);
    int s = r % Ss, b = r / Ss;
    int ss = s - (Ww-1) + w;
    float v = (ss >= 0) ? g_x[((size_t)(b*Ss + ss))*Dd + d] : 0.f;
    __nv_bfloat16 h = __float2bfloat16(v);
    g_locin_hi[idx] = h;
    g_locin_lo[idx] = __float2bfloat16(v - __bfloat162float(h));
}

// transpose+split: W[K,N] fp32 -> Wt hi/lo [N,K] bf16
__global__ void wtconv_kernel(const float* __restrict__ W,
                              __nv_bfloat16* __restrict__ hi,
                              __nv_bfloat16* __restrict__ lo, int K, int N) {
    __shared__ float t[32][33];
    int n0 = blockIdx.x * 32, k0 = blockIdx.y * 32;
    int tx = threadIdx.x & 31, ty = threadIdx.x >> 5;
#pragma unroll
    for (int r = 0; r < 4; r++)
        t[ty + 8*r][tx] = W[(size_t)(k0 + ty + 8*r) * N + n0 + tx];
    __syncthreads();
#pragma unroll
    for (int r = 0; r < 4; r++) {
        int n = n0 + ty + 8*r, k = k0 + tx;
        float v = t[tx][ty + 8*r];
        __nv_bfloat16 h = __float2bfloat16(v);
        hi[(size_t)n*K + k] = h;
        lo[(size_t)n*K + k] = __float2bfloat16(v - __bfloat162float(h));
    }
}

// transpose: W[K,N] fp32 -> Wt [N,K] single fp16
__global__ void wtconv_f16_kernel(const float* __restrict__ W,
                                  __half* __restrict__ hi, int K, int N) {
    __shared__ float t[32][33];
    int n0 = blockIdx.x * 32, k0 = blockIdx.y * 32;
    int tx = threadIdx.x & 31, ty = threadIdx.x >> 5;
#pragma unroll
    for (int r = 0; r < 4; r++)
        t[ty + 8*r][tx] = W[(size_t)(k0 + ty + 8*r) * N + n0 + tx];
    __syncthreads();
#pragma unroll
    for (int r = 0; r < 4; r++) {
        int n = n0 + ty + 8*r, k = k0 + tx;
        hi[(size_t)n*K + k] = __float2half_rn(t[tx][ty + 8*r]);
    }
}

__global__ void init_stats_kernel() {
    int i = blockIdx.x * blockDim.x + threadIdx.x;
    if (i >= 2*Rr) return;
    ((float*)g_rs)[i] = 0.f;
    ((float*)g_rss)[i] = 0.f;
    ((uint32_t*)g_rmx)[i] = 0u;
}

// ============ HMMA GEMM, 128x128, bf16 3-pass (hidden; ReLU + fp16 split) ==
#define STAGES 3
#define ROWB   80
#define ABYTES (128*ROWB)
#define STAGEB (2*ABYTES)

__global__ void __launch_bounds__(256, 2) hmma_kernel(
        const __nv_bfloat16* __restrict__ Ahi, const __nv_bfloat16* __restrict__ Alo,
        const __nv_bfloat16* __restrict__ Bhi, const __nv_bfloat16* __restrict__ Blo,
        const float* __restrict__ bias,
        __half* __restrict__ Chi, __half* __restrict__ Clo,
        int K, int Ntot) {
    extern __shared__ char smem[];
    const uint32_t sb = smem_u32(smem);
    const int tid = threadIdx.x;
    const int wid = tid >> 5, lid = tid & 31;
    const int wm = wid & 3, wn = wid >> 2;          // 4 M x 2 N
    const int mBase = blockIdx.x * 128;
    const int nBase = blockIdx.y * 128;

    const int KC = K / 32;
    const int NC = 3 * KC;

    float acc[2][8][4];
#pragma unroll
    for (int i = 0; i < 2; i++)
#pragma unroll
        for (int j = 0; j < 8; j++)
#pragma unroll
            for (int q = 0; q < 4; q++) acc[i][j][q] = 0.f;

    auto load_tile = [&](int c, int s) {
        int pass = c / KC, kc = c - pass * KC;
        const __nv_bfloat16* Ap = (pass == 1) ? Alo : Ahi;
        const __nv_bfloat16* Bp = (pass == 2) ? Blo : Bhi;
        int kof = kc * 32;
        uint32_t ab = sb + s * STAGEB;
        uint32_t bb = ab + ABYTES;
#pragma unroll
        for (int i = 0; i < 2; i++) {
            int id = tid + i * 256;
            int row = id >> 2, q = id & 3;
            CP_ASYNC16(ab + row*ROWB + q*16,
                       Ap + (size_t)(mBase + row) * K + kof + q*8);
        }
#pragma unroll
        for (int i = 0; i < 2; i++) {
            int id = tid + i * 256;
            int row = id >> 2, q = id & 3;
            CP_ASYNC16(bb + row*ROWB + q*16,
                       Bp + (size_t)(nBase + row) * K + kof + q*8);
        }
    };

#pragma unroll
    for (int s = 0; s < STAGES - 1; s++) { load_tile(s, s); CP_COMMIT(); }

    const int aRow = (lid & 7) + ((lid >> 3) & 1) * 8;
    const int aKb  = (lid >> 4) * 16;
    const int bRow = (lid & 7) + ((lid >> 4) & 1) * 8;
    const int bKb  = ((lid >> 3) & 1) * 16;

    for (int c = 0; c < NC; c++) {
        CP_WAIT(STAGES - 2);
        __syncthreads();       // single bar per chunk: also fences stage c+2 reuse
        if (c + STAGES - 1 < NC) load_tile(c + STAGES - 1, (c + STAGES - 1) % STAGES);
        CP_COMMIT();

        uint32_t ab = sb + (c % STAGES) * STAGEB;
        uint32_t bb = ab + ABYTES;
#pragma unroll
        for (int ks = 0; ks < 2; ks++) {
            uint32_t afr[2][4], bfr[4][4];
#pragma unroll
            for (int i = 0; i < 2; i++)
                ldmx4(afr[i], ab + (wm*32 + i*16 + aRow)*ROWB + ks*32 + aKb);
#pragma unroll
            for (int t = 0; t < 4; t++)
                ldmx4(bfr[t], bb + (wn*64 + t*16 + bRow)*ROWB + ks*32 + bKb);
#pragma unroll
            for (int i = 0; i < 2; i++)
#pragma unroll
                for (int j = 0; j < 8; j++)
                    mma_bf16(acc[i][j], afr[i], bfr[j >> 1] + (j & 1) * 2);
        }
    }
    CP_WAIT(0);

    const int r0 = lid >> 2;
    const int c0 = (lid & 3) * 2;
#pragma unroll
    for (int i = 0; i < 2; i++) {
#pragma unroll
        for (int j = 0; j < 8; j++) {
            int col = nBase + wn*64 + j*8 + c0;
            int rowA = mBase + wm*32 + i*16 + r0;
            float2 bv = *(const float2*)(bias + col);
            float v0 = fmaxf(acc[i][j][0] + bv.x, 0.f);
            float v1 = fmaxf(acc[i][j][1] + bv.y, 0.f);
            float v2 = fmaxf(acc[i][j][2] + bv.x, 0.f);
            float v3 = fmaxf(acc[i][j][3] + bv.y, 0.f);
            __half h0 = __float2half_rn(v0), h1 = __float2half_rn(v1);
            __half h2 = __float2half_rn(v2), h3 = __float2half_rn(v3);
            *(__half2*)(Chi + (size_t)rowA * Ntot + col)     = __half2{h0, h1};
            *(__half2*)(Chi + (size_t)(rowA+8) * Ntot + col) = __half2{h2, h3};
            *(__half2*)(Clo + (size_t)rowA * Ntot + col) =
                __half2{__float2half_rn(v0 - __half2float(h0)),
                        __float2half_rn(v1 - __half2float(h1))};
            *(__half2*)(Clo + (size_t)(rowA+8) * Ntot + col) =
                __half2{__float2half_rn(v2 - __half2float(h2)),
                        __float2half_rn(v3 - __half2float(h3))};
        }
    }
}

// ==== HMMA GEMM, 128x128, fp16 2-pass (logits; fp32 out + fused row stats) ==
__global__ void __launch_bounds__(256, 2) hmma_logits_kernel(
        const __half* __restrict__ Ahi, const __half* __restrict__ Alo,
        const __half* __restrict__ Bw,
        const float* __restrict__ bias,
        float* __restrict__ Cf,
        float* __restrict__ rs, float* __restrict__ rss, uint32_t* __restrict__ rmx,
        int K, int Ntot) {
    extern __shared__ char smem[];
    const uint32_t sb = smem_u32(smem);
    const int tid = threadIdx.x;
    const int wid = tid >> 5, lid = tid & 31;
    const int wm = wid & 3, wn = wid >> 2;
    const int mBase = blockIdx.x * 128;
    const int nBase = blockIdx.y * 128;

    const int KC = K / 32;
    const int NC = 2 * KC;          // 2 passes: Ahi*B, Alo*B

    float acc[2][8][4];
#pragma unroll
    for (int i = 0; i < 2; i++)
#pragma unroll
        for (int j = 0; j < 8; j++)
#pragma unroll
            for (int q = 0; q < 4; q++) acc[i][j][q] = 0.f;

    auto load_tile = [&](int c, int s) {
        int pass = c / KC, kc = c - pass * KC;
        const __half* Ap = pass ? Alo : Ahi;
        int kof = kc * 32;
        uint32_t ab = sb + s * STAGEB;
        uint32_t bb = ab + ABYTES;
#pragma unroll
        for (int i = 0; i < 2; i++) {
            int id = tid + i * 256;
            int row = id >> 2, q = id & 3;
            CP_ASYNC16(ab + row*ROWB + q*16,
                       Ap + (size_t)(mBase + row) * K + kof + q*8);
        }
#pragma unroll
        for (int i = 0; i < 2; i++) {
            int id = tid + i * 256;
            int row = id >> 2, q = id & 3;
            CP_ASYNC16(bb + row*ROWB + q*16,
                       Bw + (size_t)(nBase + row) * K + kof + q*8);
        }
    };

#pragma unroll
    for (int s = 0; s < STAGES - 1; s++) { load_tile(s, s); CP_COMMIT(); }

    const int aRow = (lid & 7) + ((lid >> 3) & 1) * 8;
    const int aKb  = (lid >> 4) * 16;
    const int bRow = (lid & 7) + ((lid >> 4) & 1) * 8;
    const int bKb  = ((lid >> 3) & 1) * 16;

    for (int c = 0; c < NC; c++) {
        CP_WAIT(STAGES - 2);
        __syncthreads();
        if (c + STAGES - 1 < NC) load_tile(c + STAGES - 1, (c + STAGES - 1) % STAGES);
        CP_COMMIT();

        uint32_t ab = sb + (c % STAGES) * STAGEB;
        uint32_t bb = ab + ABYTES;
#pragma unroll
        for (int ks = 0; ks < 2; ks++) {
            uint32_t afr[2][4], bfr[4][4];
#pragma unroll
            for (int i = 0; i < 2; i++)
                ldmx4(afr[i], ab + (wm*32 + i*16 + aRow)*ROWB + ks*32 + aKb);
#pragma unroll
            for (int t = 0; t < 4; t++)
                ldmx4(bfr[t], bb + (wn*64 + t*16 + bRow)*ROWB + ks*32 + bKb);
#pragma unroll
            for (int i = 0; i < 2; i++)
#pragma unroll
                for (int j = 0; j < 8; j++)
                    mma_f16(acc[i][j], afr[i], bfr[j >> 1] + (j & 1) * 2);
        }
    }
    CP_WAIT(0);

    const int r0 = lid >> 2;
    const int c0 = (lid & 3) * 2;
    float ps[4], pq[4], pm[4];
#pragma unroll
    for (int t = 0; t < 4; t++) { ps[t] = 0.f; pq[t] = 0.f; pm[t] = -3.4e38f; }

#pragma unroll
    for (int i = 0; i < 2; i++) {
#pragma unroll
        for (int j = 0; j < 8; j++) {
            int col = nBase + wn*64 + j*8 + c0;
            int rowA = mBase + wm*32 + i*16 + r0;
            float2 bv = *(const float2*)(bias + col);
            float v0 = acc[i][j][0] + bv.x, v1 = acc[i][j][1] + bv.y;
            float v2 = acc[i][j][2] + bv.x, v3 = acc[i][j][3] + bv.y;
            *(float2*)(Cf + (size_t)rowA * Ntot + col)       = make_float2(v0, v1);
            *(float2*)(Cf + (size_t)(rowA + 8) * Ntot + col) = make_float2(v2, v3);
            ps[2*i]   += v0 + v1;  pq[2*i]   += v0*v0 + v1*v1;
            pm[2*i]    = fmaxf(pm[2*i], fmaxf(v0, v1));
            ps[2*i+1] += v2 + v3;  pq[2*i+1] += v2*v2 + v3*v3;
            pm[2*i+1]  = fmaxf(pm[2*i+1], fmaxf(v2, v3));
        }
    }
#pragma unroll
    for (int t = 0; t < 4; t++) {
#pragma unroll
        for (int m = 1; m <= 2; m <<= 1) {
            ps[t] += __shfl_xor_sync(0xffffffffu, ps[t], m);
            pq[t] += __shfl_xor_sync(0xffffffffu, pq[t], m);
            pm[t]  = fmaxf(pm[t], __shfl_xor_sync(0xffffffffu, pm[t], m));
        }
    }
    if ((lid & 3) == 0) {
#pragma unroll
        for (int t = 0; t < 4; t++) {
            int row = mBase + wm*32 + (t >> 1)*16 + r0 + (t & 1)*8;
            atomicAdd(rs + row, ps[t]);
            atomicAdd(rss + row, pq[t]);
            atomicMax(rmx + row, fenc(pm[t]));
        }
    }
}

// ======================= fp32 SGEMM (small u GEMM only) ====================
#define BM 128
#define BNs 128
#define BKs 8
__global__ void __launch_bounds__(256) sgemm_kernel(
        const float* __restrict__ A, const float* __restrict__ Bm,
        float* __restrict__ C, int K, int N) {
    __shared__ float As[BKs][BM];
    __shared__ float Bs2[BKs][BNs];
    int tid = threadIdx.x;
    int tx = tid & 15, ty = tid >> 4;
    int mBase = blockIdx.y * BM, nBase = blockIdx.x * BNs;
    int aM = tid >> 1, aK = (tid & 1) * 4;
    int bK = tid >> 5, bN = (tid & 31) * 4;
    const float* Aptr = A + (size_t)(mBase + aM) * K + aK;
    const float* Bptr = Bm + (size_t)bK * N + nBase + bN;
    float acc[8][8];
#pragma unroll
    for (int i = 0; i < 8; i++)
#pragma unroll
        for (int j = 0; j < 8; j++) acc[i][j] = 0.f;
    for (int kt = 0; kt < K; kt += BKs) {
        float4 av = *(const float4*)Aptr;  Aptr += BKs;
        float4 bv = *(const float4*)Bptr;  Bptr += (size_t)BKs * N;
        As[aK+0][aM] = av.x; As[aK+1][aM] = av.y;
        As[aK+2][aM] = av.z; As[aK+3][aM] = av.w;
        *(float4*)&Bs2[bK][bN] = bv;
        __syncthreads();
        float ar[8], br[8];
#pragma unroll
        for (int k = 0; k < BKs; k++) {
#pragma unroll
            for (int i = 0; i < 8; i++) ar[i] = As[k][ty*8 + i];
#pragma unroll
            for (int j = 0; j < 8; j++) br[j] = Bs2[k][tx*8 + j];
#pragma unroll
            for (int i = 0; i < 8; i++)
#pragma unroll
                for (int j = 0; j < 8; j++)
                    acc[i][j] = fmaf(ar[i], br[j], acc[i][j]);
        }
        __syncthreads();
    }
#pragma unroll
    for (int i = 0; i < 8; i++) {
        float* Crow = C + (size_t)(mBase + ty*8 + i) * N + nBase + tx*8;
#pragma unroll
        for (int j = 0; j < 8; j++) Crow[j] = acc[i][j];
    }
}

// ======================= gate / mix ========================================
__global__ void gate_finalize_kernel(const float* __restrict__ gw,
                                     const float* __restrict__ gb) {
    int r = blockIdx.x * blockDim.x + threadIdx.x;
    if (r >= Rr) return;
    const float inv = 1.f / (float)Vv;
    float mean0 = g_rs[0][r] * inv;
    float std0  = sqrtf(fmaxf(g_rss[0][r] * inv - mean0*mean0, 0.f));
    float max0  = fdec(g_rmx[0][r]);
    float mean1 = g_rs[1][r] * inv;
    float std1  = sqrtf(fmaxf(g_rss[1][r] * inv - mean1*mean1, 0.f));
    float max1  = fdec(g_rmx[1][r]);
    float z = gb[0] + gw[0]*mean0 + gw[1]*max0 + gw[2]*std0
                    + gw[3]*mean1 + gw[4]*max1 + gw[5]*std1;
    g_gate[r] = 1.f / (1.f + expf(-z));
}

__global__ void mix_kernel(float* __restrict__ out) {
    int r = blockIdx.y;
    int c4 = blockIdx.x * blockDim.x + threadIdx.x;
    if (c4 >= Vv/4) return;
    size_t i = (size_t)r * (Vv/4) + c4;
    float g = g_gate[r], og = 1.f - g;
    float4 a = ((const float4*)g_lin)[i];
    float4 b = ((const float4*)g_loc)[i];
    float4 o;
    o.x = g*a.x + og*b.x;  o.y = g*a.y + og*b.y;
    o.z = g*a.z + og*b.z;  o.w = g*a.w + og*b.w;
    ((float4*)out)[i] = o;
}

// ======================= launch ============================================
extern "C" void kernel_launch(void* const* d_in, const int* in_sizes, int n_in,
                              void* d_out, int out_size) {
    const int*   tokens  = (const int*)  d_in[0];
    const float* emb     = (const float*)d_in[1];
    const float* in_proj = (const float*)d_in[2];
    const float* decays  = (const float*)d_in[3];
    const float* w1      = (const float*)d_in[4];
    const float* b1      = (const float*)d_in[5];
    const float* w2      = (const float*)d_in[6];
    const float* b2      = (const float*)d_in[7];
    const float* lw1     = (const float*)d_in[8];
    const float* lb1     = (const float*)d_in[9];
    const float* lw2     = (const float*)d_in[10];
    const float* lb2     = (const float*)d_in[11];
    const float* gate_w  = (const float*)d_in[12];
    const float* gate_b  = (const float*)d_in[13];
    float* out = (float*)d_out;

    float *gx, *gu, *glin, *gloc, *grs, *grss;
    uint32_t* grmx;
    cudaGetSymbolAddress((void**)&gx,   g_x);
    cudaGetSymbolAddress((void**)&gu,   g_u);
    cudaGetSymbolAddress((void**)&glin, g_lin);
    cudaGetSymbolAddress((void**)&gloc, g_loc);
    cudaGetSymbolAddress((void**)&grs,  g_rs);
    cudaGetSymbolAddress((void**)&grss, g_rss);
    cudaGetSymbolAddress((void**)&grmx, g_rmx);
    __nv_bfloat16 *fh, *fl, *lih, *lil, *w1h, *w1l, *lw1h, *lw1l;
    __half *hh, *hl, *h2h, *h2l, *w2t, *lw2t;
    cudaGetSymbolAddress((void**)&fh,   g_feat_hi);
    cudaGetSymbolAddress((void**)&fl,   g_feat_lo);
    cudaGetSymbolAddress((void**)&lih,  g_locin_hi);
    cudaGetSymbolAddress((void**)&lil,  g_locin_lo);
    cudaGetSymbolAddress((void**)&w1h,  g_w1t_hi);
    cudaGetSymbolAddress((void**)&w1l,  g_w1t_lo);
    cudaGetSymbolAddress((void**)&lw1h, g_lw1t_hi);
    cudaGetSymbolAddress((void**)&lw1l, g_lw1t_lo);
    cudaGetSymbolAddress((void**)&hh,   g_h_hi);
    cudaGetSymbolAddress((void**)&hl,   g_h_lo);
    cudaGetSymbolAddress((void**)&h2h,  g_h2_hi);
    cudaGetSymbolAddress((void**)&h2l,  g_h2_lo);
    cudaGetSymbolAddress((void**)&w2t,  g_w2t);
    cudaGetSymbolAddress((void**)&lw2t, g_lw2t);

    constexpr int SMEMB = STAGES * STAGEB;   // 61440
    cudaFuncSetAttribute(hmma_kernel, cudaFuncAttributeMaxDynamicSharedMemorySize, SMEMB);
    cudaFuncSetAttribute(hmma_logits_kernel, cudaFuncAttributeMaxDynamicSharedMemorySize, SMEMB);

    // 1) embedding gather (+ feat hi/lo cols M..)
    gather_embed_kernel<<<Rr, Dd>>>(tokens, emb);
    // 2) u = x @ in_proj
    sgemm_kernel<<<dim3(Mm/BNs, Rr/BM), 256>>>(gx, in_proj, gu, Dd, Mm);
    // 3) decay scan -> feat hi/lo cols 0..M
    scan_kernel<<<Bb, Mm>>>(decays);
    // 4) fused window build + split
    build_loc_split_kernel<<<(Rr*Ww*Dd + 255)/256, 256>>>();
    // 5) weight conversions
    wtconv_kernel<<<dim3(HLh/32, F1/32),  256>>>(w1,  w1h,  w1l,  F1,  HLh);
    wtconv_kernel<<<dim3(HCh/32, F2/32),  256>>>(lw1, lw1h, lw1l, F2,  HCh);
    wtconv_f16_kernel<<<dim3(Vv/32, HLh/32), 256>>>(w2,  w2t,  HLh, Vv);
    wtconv_f16_kernel<<<dim3(Vv/32, HCh/32), 256>>>(lw2, lw2t, HCh, Vv);
    // 6) init stats accumulators
    init_stats_kernel<<<(2*Rr + 255)/256, 256>>>();
    // 7) h = relu(feat @ w1 + b1) -> fp16 split
    hmma_kernel<<<dim3(Rr/128, HLh/128), 256, SMEMB>>>(
        fh, fl, w1h, w1l, b1, hh, hl, F1, HLh);
    // 8) h2 = relu(loc @ lw1 + lb1) -> fp16 split
    hmma_kernel<<<dim3(Rr/128, HCh/128), 256, SMEMB>>>(
        lih, lil, lw1h, lw1l, lb1, h2h, h2l, F2, HCh);
    // 9) lin_logits = h @ w2 + b2 (fp16 2-pass, fused stats)
    hmma_logits_kernel<<<dim3(Rr/128, Vv/128), 256, SMEMB>>>(
        hh, hl, w2t, b2, glin, grs, grss, grmx, HLh, Vv);
    // 10) loc_logits = h2 @ lw2 + lb2
    hmma_logits_kernel<<<dim3(Rr/128, Vv/128), 256, SMEMB>>>(
        h2h, h2l, lw2t, lb2, gloc, grs + Rr, grss + Rr, grmx + Rr, HCh, Vv);
    // 11) gate, mix
    gate_finalize_kernel<<<(Rr + 255)/256, 256>>>(gate_w, gate_b);
    mix_kernel<<<dim3((Vv/4 + 255)/256, Rr), 256>>>(out);
}

// round 13
// speedup vs baseline: 2.4825x; 1.5046x over previous
#include <cuda_runtime.h>
#include <cuda_bf16.h>
#include <cuda_fp16.h>
#include <cstdint>
#include <math.h>

#define Bb   2
#define Ss   1024
#define Vv   32000
#define Dd   256
#define Mm   256
#define Ww   8
#define HLh  1024
#define HCh  1024
#define Rr   (Bb*Ss)          // 2048
#define F1   (Mm+Dd)          // 512
#define F2   (Ww*Dd)          // 2048

// ======================= helpers ===========================================
__device__ __forceinline__ uint32_t smem_u32(const void* p) {
    uint32_t a;
    asm("{ .reg .u64 t; cvta.to.shared.u64 t, %1; cvt.u32.u64 %0, t; }" : "=r"(a) : "l"(p));
    return a;
}
#define CP_ASYNC16(dst, src) \
    asm volatile("cp.async.cg.shared.global [%0], [%1], 16;" :: "r"(dst), "l"(src))
#define CP_COMMIT() asm volatile("cp.async.commit_group;" ::: "memory")
#define CP_WAIT(n)  asm volatile("cp.async.wait_group %0;" :: "n"(n) : "memory")

__device__ __forceinline__ void ldmx4(uint32_t* r, uint32_t addr) {
    asm volatile("ldmatrix.sync.aligned.m8n8.x4.shared.b16 {%0,%1,%2,%3}, [%4];"
        : "=r"(r[0]), "=r"(r[1]), "=r"(r[2]), "=r"(r[3]) : "r"(addr));
}
__device__ __forceinline__ void mma_bf16(float* c, const uint32_t* a, const uint32_t* b) {
    asm volatile(
        "mma.sync.aligned.m16n8k16.row.col.f32.bf16.bf16.f32 "
        "{%0,%1,%2,%3}, {%4,%5,%6,%7}, {%8,%9}, {%0,%1,%2,%3};"
        : "+f"(c[0]), "+f"(c[1]), "+f"(c[2]), "+f"(c[3])
        : "r"(a[0]), "r"(a[1]), "r"(a[2]), "r"(a[3]), "r"(b[0]), "r"(b[1]));
}
__device__ __forceinline__ void mma_f16(float* c, const uint32_t* a, const uint32_t* b) {
    asm volatile(
        "mma.sync.aligned.m16n8k16.row.col.f32.f16.f16.f32 "
        "{%0,%1,%2,%3}, {%4,%5,%6,%7}, {%8,%9}, {%0,%1,%2,%3};"
        : "+f"(c[0]), "+f"(c[1]), "+f"(c[2]), "+f"(c[3])
        : "r"(a[0]), "r"(a[1]), "r"(a[2]), "r"(a[3]), "r"(b[0]), "r"(b[1]));
}
// monotonic float<->uint encode for atomicMax over signed floats
__device__ __forceinline__ uint32_t fenc(float f) {
    uint32_t i = __float_as_uint(f);
    return (i & 0x80000000u) ? ~i : (i | 0x80000000u);
}
__device__ __forceinline__ float fdec(uint32_t u) {
    return (u & 0x80000000u) ? __uint_as_float(u & 0x7FFFFFFFu) : __uint_as_float(~u);
}

// ======================= scratch ===========================================
__device__ float g_x[Rr*Dd];
__device__ float g_u[Rr*Mm];
__device__ float g_lin[(size_t)Rr*Vv];
__device__ float g_loc[(size_t)Rr*Vv];
__device__ float g_gate[Rr];
__device__ float    g_rs[2][Rr];
__device__ float    g_rss[2][Rr];
__device__ uint32_t g_rmx[2][Rr];
// bf16 split operands (hidden layers)
__device__ __nv_bfloat16 g_feat_hi[Rr*F1],  g_feat_lo[Rr*F1];
__device__ __nv_bfloat16 g_locin_hi[Rr*F2], g_locin_lo[Rr*F2];
__device__ __nv_bfloat16 g_w1t_hi[HLh*F1],  g_w1t_lo[HLh*F1];
__device__ __nv_bfloat16 g_lw1t_hi[HCh*F2], g_lw1t_lo[HCh*F2];
// fp16 operands (logits layers, single precision level)
__device__ __half g_h[Rr*HLh];
__device__ __half g_h2[Rr*HCh];
__device__ __half g_w2t[(size_t)Vv*HLh];
__device__ __half g_lw2t[(size_t)Vv*HCh];

// ======================= small kernels =====================================
__global__ void gather_embed_kernel(const int* __restrict__ tok,
                                    const float* __restrict__ emb) {
    int r = blockIdx.x, d = threadIdx.x;
    float v = emb[(size_t)tok[r] * Dd + d];
    g_x[r*Dd + d] = v;
    __nv_bfloat16 h = __float2bfloat16(v);
    g_feat_hi[(size_t)r*F1 + Mm + d] = h;
    g_feat_lo[(size_t)r*F1 + Mm + d] = __float2bfloat16(v - __bfloat162float(h));
}

__global__ void scan_kernel(const float* __restrict__ decays) {
    int b = blockIdx.x, m = threadIdx.x;
    float a = decays[m], s = 0.f;
    for (int t = 0; t < Ss; t++) {
        int r = b*Ss + t;
        s = a*s + g_u[(size_t)r*Mm + m];
        __nv_bfloat16 h = __float2bfloat16(s);
        g_feat_hi[(size_t)r*F1 + m] = h;
        g_feat_lo[(size_t)r*F1 + m] = __float2bfloat16(s - __bfloat162float(h));
    }
}

__global__ void build_loc_split_kernel() {
    int idx = blockIdx.x * blockDim.x + threadIdx.x;
    if (idx >= Rr*Ww*Dd) return;
    int d = idx % Dd, w = (idx / Dd) % Ww, r = idx / (Ww*Dd);
    int s = r % Ss, b = r / Ss;
    int ss = s - (Ww-1) + w;
    float v = (ss >= 0) ? g_x[((size_t)(b*Ss + ss))*Dd + d] : 0.f;
    __nv_bfloat16 h = __float2bfloat16(v);
    g_locin_hi[idx] = h;
    g_locin_lo[idx] = __float2bfloat16(v - __bfloat162float(h));
}

// transpose+split: W[K,N] fp32 -> Wt hi/lo [N,K] bf16
__global__ void wtconv_kernel(const float* __restrict__ W,
                              __nv_bfloat16* __restrict__ hi,
                              __nv_bfloat16* __restrict__ lo, int K, int N) {
    __shared__ float t[32][33];
    int n0 = blockIdx.x * 32, k0 = blockIdx.y * 32;
    int tx = threadIdx.x & 31, ty = threadIdx.x >> 5;
#pragma unroll
    for (int r = 0; r < 4; r++)
        t[ty + 8*r][tx] = W[(size_t)(k0 + ty + 8*r) * N + n0 + tx];
    __syncthreads();
#pragma unroll
    for (int r = 0; r < 4; r++) {
        int n = n0 + ty + 8*r, k = k0 + tx;
        float v = t[tx][ty + 8*r];
        __nv_bfloat16 h = __float2bfloat16(v);
        hi[(size_t)n*K + k] = h;
        lo[(size_t)n*K + k] = __float2bfloat16(v - __bfloat162float(h));
    }
}

// transpose: W[K,N] fp32 -> Wt [N,K] single fp16
__global__ void wtconv_f16_kernel(const float* __restrict__ W,
                                  __half* __restrict__ hi, int K, int N) {
    __shared__ float t[32][33];
    int n0 = blockIdx.x * 32, k0 = blockIdx.y * 32;
    int tx = threadIdx.x & 31, ty = threadIdx.x >> 5;
#pragma unroll
    for (int r = 0; r < 4; r++)
        t[ty + 8*r][tx] = W[(size_t)(k0 + ty + 8*r) * N + n0 + tx];
    __syncthreads();
#pragma unroll
    for (int r = 0; r < 4; r++) {
        int n = n0 + ty + 8*r, k = k0 + tx;
        hi[(size_t)n*K + k] = __float2half_rn(t[tx][ty + 8*r]);
    }
}

__global__ void init_stats_kernel() {
    int i = blockIdx.x * blockDim.x + threadIdx.x;
    if (i >= 2*Rr) return;
    ((float*)g_rs)[i] = 0.f;
    ((float*)g_rss)[i] = 0.f;
    ((uint32_t*)g_rmx)[i] = 0u;
}

// ============ HMMA GEMM, 128x128, bf16 3-pass (hidden; ReLU -> fp16) =======
#define STAGES 3
#define ROWB   80
#define ABYTES (128*ROWB)
#define STAGEB (2*ABYTES)

__global__ void __launch_bounds__(256, 2) hmma_kernel(
        const __nv_bfloat16* __restrict__ Ahi, const __nv_bfloat16* __restrict__ Alo,
        const __nv_bfloat16* __restrict__ Bhi, const __nv_bfloat16* __restrict__ Blo,
        const float* __restrict__ bias,
        __half* __restrict__ Chi,
        int K, int Ntot) {
    extern __shared__ char smem[];
    const uint32_t sb = smem_u32(smem);
    const int tid = threadIdx.x;
    const int wid = tid >> 5, lid = tid & 31;
    const int wm = wid & 3, wn = wid >> 2;          // 4 M x 2 N
    const int mBase = blockIdx.x * 128;
    const int nBase = blockIdx.y * 128;

    const int KC = K / 32;
    const int NC = 3 * KC;

    float acc[2][8][4];
#pragma unroll
    for (int i = 0; i < 2; i++)
#pragma unroll
        for (int j = 0; j < 8; j++)
#pragma unroll
            for (int q = 0; q < 4; q++) acc[i][j][q] = 0.f;

    auto load_tile = [&](int c, int s) {
        int pass = c / KC, kc = c - pass * KC;
        const __nv_bfloat16* Ap = (pass == 1) ? Alo : Ahi;
        const __nv_bfloat16* Bp = (pass == 2) ? Blo : Bhi;
        int kof = kc * 32;
        uint32_t ab = sb + s * STAGEB;
        uint32_t bb = ab + ABYTES;
#pragma unroll
        for (int i = 0; i < 2; i++) {
            int id = tid + i * 256;
            int row = id >> 2, q = id & 3;
            CP_ASYNC16(ab + row*ROWB + q*16,
                       Ap + (size_t)(mBase + row) * K + kof + q*8);
        }
#pragma unroll
        for (int i = 0; i < 2; i++) {
            int id = tid + i * 256;
            int row = id >> 2, q = id & 3;
            CP_ASYNC16(bb + row*ROWB + q*16,
                       Bp + (size_t)(nBase + row) * K + kof + q*8);
        }
    };

#pragma unroll
    for (int s = 0; s < STAGES - 1; s++) { load_tile(s, s); CP_COMMIT(); }

    const int aRow = (lid & 7) + ((lid >> 3) & 1) * 8;
    const int aKb  = (lid >> 4) * 16;
    const int bRow = (lid & 7) + ((lid >> 4) & 1) * 8;
    const int bKb  = ((lid >> 3) & 1) * 16;

    for (int c = 0; c < NC; c++) {
        CP_WAIT(STAGES - 2);
        __syncthreads();
        if (c + STAGES - 1 < NC) load_tile(c + STAGES - 1, (c + STAGES - 1) % STAGES);
        CP_COMMIT();

        uint32_t ab = sb + (c % STAGES) * STAGEB;
        uint32_t bb = ab + ABYTES;
#pragma unroll
        for (int ks = 0; ks < 2; ks++) {
            uint32_t afr[2][4], bfr[4][4];
#pragma unroll
            for (int i = 0; i < 2; i++)
                ldmx4(afr[i], ab + (wm*32 + i*16 + aRow)*ROWB + ks*32 + aKb);
#pragma unroll
            for (int t = 0; t < 4; t++)
                ldmx4(bfr[t], bb + (wn*64 + t*16 + bRow)*ROWB + ks*32 + bKb);
#pragma unroll
            for (int i = 0; i < 2; i++)
#pragma unroll
                for (int j = 0; j < 8; j++)
                    mma_bf16(acc[i][j], afr[i], bfr[j >> 1] + (j & 1) * 2);
        }
    }
    CP_WAIT(0);

    const int r0 = lid >> 2;
    const int c0 = (lid & 3) * 2;
#pragma unroll
    for (int i = 0; i < 2; i++) {
#pragma unroll
        for (int j = 0; j < 8; j++) {
            int col = nBase + wn*64 + j*8 + c0;
            int rowA = mBase + wm*32 + i*16 + r0;
            float2 bv = *(const float2*)(bias + col);
            float v0 = fmaxf(acc[i][j][0] + bv.x, 0.f);
            float v1 = fmaxf(acc[i][j][1] + bv.y, 0.f);
            float v2 = fmaxf(acc[i][j][2] + bv.x, 0.f);
            float v3 = fmaxf(acc[i][j][3] + bv.y, 0.f);
            *(__half2*)(Chi + (size_t)rowA * Ntot + col) =
                __half2{__float2half_rn(v0), __float2half_rn(v1)};
            *(__half2*)(Chi + (size_t)(rowA+8) * Ntot + col) =
                __half2{__float2half_rn(v2), __float2half_rn(v3)};
        }
    }
}

// ==== HMMA GEMM, 128x128, fp16 1-pass (logits; fp32 out + fused row stats) ==
__global__ void __launch_bounds__(256, 2) hmma_logits_kernel(
        const __half* __restrict__ A,
        const __half* __restrict__ Bw,
        const float* __restrict__ bias,
        float* __restrict__ Cf,
        float* __restrict__ rs, float* __restrict__ rss, uint32_t* __restrict__ rmx,
        int K, int Ntot) {
    extern __shared__ char smem[];
    const uint32_t sb = smem_u32(smem);
    const int tid = threadIdx.x;
    const int wid = tid >> 5, lid = tid & 31;
    const int wm = wid & 3, wn = wid >> 2;
    const int mBase = blockIdx.x * 128;
    const int nBase = blockIdx.y * 128;

    const int NC = K / 32;          // single pass

    float acc[2][8][4];
#pragma unroll
    for (int i = 0; i < 2; i++)
#pragma unroll
        for (int j = 0; j < 8; j++)
#pragma unroll
            for (int q = 0; q < 4; q++) acc[i][j][q] = 0.f;

    auto load_tile = [&](int c, int s) {
        int kof = c * 32;
        uint32_t ab = sb + s * STAGEB;
        uint32_t bb = ab + ABYTES;
#pragma unroll
        for (int i = 0; i < 2; i++) {
            int id = tid + i * 256;
            int row = id >> 2, q = id & 3;
            CP_ASYNC16(ab + row*ROWB + q*16,
                       A + (size_t)(mBase + row) * K + kof + q*8);
        }
#pragma unroll
        for (int i = 0; i < 2; i++) {
            int id = tid + i * 256;
            int row = id >> 2, q = id & 3;
            CP_ASYNC16(bb + row*ROWB + q*16,
                       Bw + (size_t)(nBase + row) * K + kof + q*8);
        }
    };

#pragma unroll
    for (int s = 0; s < STAGES - 1; s++) { load_tile(s, s); CP_COMMIT(); }

    const int aRow = (lid & 7) + ((lid >> 3) & 1) * 8;
    const int aKb  = (lid >> 4) * 16;
    const int bRow = (lid & 7) + ((lid >> 4) & 1) * 8;
    const int bKb  = ((lid >> 3) & 1) * 16;

    for (int c = 0; c < NC; c++) {
        CP_WAIT(STAGES - 2);
        __syncthreads();
        if (c + STAGES - 1 < NC) load_tile(c + STAGES - 1, (c + STAGES - 1) % STAGES);
        CP_COMMIT();

        uint32_t ab = sb + (c % STAGES) * STAGEB;
        uint32_t bb = ab + ABYTES;
#pragma unroll
        for (int ks = 0; ks < 2; ks++) {
            uint32_t afr[2][4], bfr[4][4];
#pragma unroll
            for (int i = 0; i < 2; i++)
                ldmx4(afr[i], ab + (wm*32 + i*16 + aRow)*ROWB + ks*32 + aKb);
#pragma unroll
            for (int t = 0; t < 4; t++)
                ldmx4(bfr[t], bb + (wn*64 + t*16 + bRow)*ROWB + ks*32 + bKb);
#pragma unroll
            for (int i = 0; i < 2; i++)
#pragma unroll
                for (int j = 0; j < 8; j++)
                    mma_f16(acc[i][j], afr[i], bfr[j >> 1] + (j & 1) * 2);
        }
    }
    CP_WAIT(0);

    const int r0 = lid >> 2;
    const int c0 = (lid & 3) * 2;
    float ps[4], pq[4], pm[4];
#pragma unroll
    for (int t = 0; t < 4; t++) { ps[t] = 0.f; pq[t] = 0.f; pm[t] = -3.4e38f; }

#pragma unroll
    for (int i = 0; i < 2; i++) {
#pragma unroll
        for (int j = 0; j < 8; j++) {
            int col = nBase + wn*64 + j*8 + c0;
            int rowA = mBase + wm*32 + i*16 + r0;
            float2 bv = *(const float2*)(bias + col);
            float v0 = acc[i][j][0] + bv.x, v1 = acc[i][j][1] + bv.y;
            float v2 = acc[i][j][2] + bv.x, v3 = acc[i][j][3] + bv.y;
            *(float2*)(Cf + (size_t)rowA * Ntot + col)       = make_float2(v0, v1);
            *(float2*)(Cf + (size_t)(rowA + 8) * Ntot + col) = make_float2(v2, v3);
            ps[2*i]   += v0 + v1;  pq[2*i]   += v0*v0 + v1*v1;
            pm[2*i]    = fmaxf(pm[2*i], fmaxf(v0, v1));
            ps[2*i+1] += v2 + v3;  pq[2*i+1] += v2*v2 + v3*v3;
            pm[2*i+1]  = fmaxf(pm[2*i+1], fmaxf(v2, v3));
        }
    }
#pragma unroll
    for (int t = 0; t < 4; t++) {
#pragma unroll
        for (int m = 1; m <= 2; m <<= 1) {
            ps[t] += __shfl_xor_sync(0xffffffffu, ps[t], m);
            pq[t] += __shfl_xor_sync(0xffffffffu, pq[t], m);
            pm[t]  = fmaxf(pm[t], __shfl_xor_sync(0xffffffffu, pm[t], m));
        }
    }
    if ((lid & 3) == 0) {
#pragma unroll
        for (int t = 0; t < 4; t++) {
            int row = mBase + wm*32 + (t >> 1)*16 + r0 + (t & 1)*8;
            atomicAdd(rs + row, ps[t]);
            atomicAdd(rss + row, pq[t]);
            atomicMax(rmx + row, fenc(pm[t]));
        }
    }
}

// ======================= fp32 SGEMM (small u GEMM only) ====================
#define BM 128
#define BNs 128
#define BKs 8
__global__ void __launch_bounds__(256) sgemm_kernel(
        const float* __restrict__ A, const float* __restrict__ Bm,
        float* __restrict__ C, int K, int N) {
    __shared__ float As[BKs][BM];
    __shared__ float Bs2[BKs][BNs];
    int tid = threadIdx.x;
    int tx = tid & 15, ty = tid >> 4;
    int mBase = blockIdx.y * BM, nBase = blockIdx.x * BNs;
    int aM = tid >> 1, aK = (tid & 1) * 4;
    int bK = tid >> 5, bN = (tid & 31) * 4;
    const float* Aptr = A + (size_t)(mBase + aM) * K + aK;
    const float* Bptr = Bm + (size_t)bK * N + nBase + bN;
    float acc[8][8];
#pragma unroll
    for (int i = 0; i < 8; i++)
#pragma unroll
        for (int j = 0; j < 8; j++) acc[i][j] = 0.f;
    for (int kt = 0; kt < K; kt += BKs) {
        float4 av = *(const float4*)Aptr;  Aptr += BKs;
        float4 bv = *(const float4*)Bptr;  Bptr += (size_t)BKs * N;
        As[aK+0][aM] = av.x; As[aK+1][aM] = av.y;
        As[aK+2][aM] = av.z; As[aK+3][aM] = av.w;
        *(float4*)&Bs2[bK][bN] = bv;
        __syncthreads();
        float ar[8], br[8];
#pragma unroll
        for (int k = 0; k < BKs; k++) {
#pragma unroll
            for (int i = 0; i < 8; i++) ar[i] = As[k][ty*8 + i];
#pragma unroll
            for (int j = 0; j < 8; j++) br[j] = Bs2[k][tx*8 + j];
#pragma unroll
            for (int i = 0; i < 8; i++)
#pragma unroll
                for (int j = 0; j < 8; j++)
                    acc[i][j] = fmaf(ar[i], br[j], acc[i][j]);
        }
        __syncthreads();
    }
#pragma unroll
    for (int i = 0; i < 8; i++) {
        float* Crow = C + (size_t)(mBase + ty*8 + i) * N + nBase + tx*8;
#pragma unroll
        for (int j = 0; j < 8; j++) Crow[j] = acc[i][j];
    }
}

// ======================= gate / mix ========================================
__global__ void gate_finalize_kernel(const float* __restrict__ gw,
                                     const float* __restrict__ gb) {
    int r = blockIdx.x * blockDim.x + threadIdx.x;
    if (r >= Rr) return;
    const float inv = 1.f / (float)Vv;
    float mean0 = g_rs[0][r] * inv;
    float std0  = sqrtf(fmaxf(g_rss[0][r] * inv - mean0*mean0, 0.f));
    float max0  = fdec(g_rmx[0][r]);
    float mean1 = g_rs[1][r] * inv;
    float std1  = sqrtf(fmaxf(g_rss[1][r] * inv - mean1*mean1, 0.f));
    float max1  = fdec(g_rmx[1][r]);
    float z = gb[0] + gw[0]*mean0 + gw[1]*max0 + gw[2]*std0
                    + gw[3]*mean1 + gw[4]*max1 + gw[5]*std1;
    g_gate[r] = 1.f / (1.f + expf(-z));
}

__global__ void mix_kernel(float* __restrict__ out) {
    int r = blockIdx.y;
    int c4 = blockIdx.x * blockDim.x + threadIdx.x;
    if (c4 >= Vv/4) return;
    size_t i = (size_t)r * (Vv/4) + c4;
    float g = g_gate[r], og = 1.f - g;
    float4 a = ((const float4*)g_lin)[i];
    float4 b = ((const float4*)g_loc)[i];
    float4 o;
    o.x = g*a.x + og*b.x;  o.y = g*a.y + og*b.y;
    o.z = g*a.z + og*b.z;  o.w = g*a.w + og*b.w;
    ((float4*)out)[i] = o;
}

// ======================= launch ============================================
extern "C" void kernel_launch(void* const* d_in, const int* in_sizes, int n_in,
                              void* d_out, int out_size) {
    const int*   tokens  = (const int*)  d_in[0];
    const float* emb     = (const float*)d_in[1];
    const float* in_proj = (const float*)d_in[2];
    const float* decays  = (const float*)d_in[3];
    const float* w1      = (const float*)d_in[4];
    const float* b1      = (const float*)d_in[5];
    const float* w2      = (const float*)d_in[6];
    const float* b2      = (const float*)d_in[7];
    const float* lw1     = (const float*)d_in[8];
    const float* lb1     = (const float*)d_in[9];
    const float* lw2     = (const float*)d_in[10];
    const float* lb2     = (const float*)d_in[11];
    const float* gate_w  = (const float*)d_in[12];
    const float* gate_b  = (const float*)d_in[13];
    float* out = (float*)d_out;

    float *gx, *gu, *glin, *gloc, *grs, *grss;
    uint32_t* grmx;
    cudaGetSymbolAddress((void**)&gx,   g_x);
    cudaGetSymbolAddress((void**)&gu,   g_u);
    cudaGetSymbolAddress((void**)&glin, g_lin);
    cudaGetSymbolAddress((void**)&gloc, g_loc);
    cudaGetSymbolAddress((void**)&grs,  g_rs);
    cudaGetSymbolAddress((void**)&grss, g_rss);
    cudaGetSymbolAddress((void**)&grmx, g_rmx);
    __nv_bfloat16 *fh, *fl, *lih, *lil, *w1h, *w1l, *lw1h, *lw1l;
    __half *hh, *h2h, *w2t, *lw2t;
    cudaGetSymbolAddress((void**)&fh,   g_feat_hi);
    cudaGetSymbolAddress((void**)&fl,   g_feat_lo);
    cudaGetSymbolAddress((void**)&lih,  g_locin_hi);
    cudaGetSymbolAddress((void**)&lil,  g_locin_lo);
    cudaGetSymbolAddress((void**)&w1h,  g_w1t_hi);
    cudaGetSymbolAddress((void**)&w1l,  g_w1t_lo);
    cudaGetSymbolAddress((void**)&lw1h, g_lw1t_hi);
    cudaGetSymbolAddress((void**)&lw1l, g_lw1t_lo);
    cudaGetSymbolAddress((void**)&hh,   g_h);
    cudaGetSymbolAddress((void**)&h2h,  g_h2);
    cudaGetSymbolAddress((void**)&w2t,  g_w2t);
    cudaGetSymbolAddress((void**)&lw2t, g_lw2t);

    constexpr int SMEMB = STAGES * STAGEB;   // 61440
    cudaFuncSetAttribute(hmma_kernel, cudaFuncAttributeMaxDynamicSharedMemorySize, SMEMB);
    cudaFuncSetAttribute(hmma_logits_kernel, cudaFuncAttributeMaxDynamicSharedMemorySize, SMEMB);

    // 1) embedding gather (+ feat hi/lo cols M..)
    gather_embed_kernel<<<Rr, Dd>>>(tokens, emb);
    // 2) u = x @ in_proj
    sgemm_kernel<<<dim3(Mm/BNs, Rr/BM), 256>>>(gx, in_proj, gu, Dd, Mm);
    // 3) decay scan -> feat hi/lo cols 0..M
    scan_kernel<<<Bb, Mm>>>(decays);
    // 4) fused window build + split
    build_loc_split_kernel<<<(Rr*Ww*Dd + 255)/256, 256>>>();
    // 5) weight conversions
    wtconv_kernel<<<dim3(HLh/32, F1/32),  256>>>(w1,  w1h,  w1l,  F1,  HLh);
    wtconv_kernel<<<dim3(HCh/32, F2/32),  256>>>(lw1, lw1h, lw1l, F2,  HCh);
    wtconv_f16_kernel<<<dim3(Vv/32, HLh/32), 256>>>(w2,  w2t,  HLh, Vv);
    wtconv_f16_kernel<<<dim3(Vv/32, HCh/32), 256>>>(lw2, lw2t, HCh, Vv);
    // 6) init stats accumulators
    init_stats_kernel<<<(2*Rr + 255)/256, 256>>>();
    // 7) h = relu(feat @ w1 + b1) -> fp16
    hmma_kernel<<<dim3(Rr/128, HLh/128), 256, SMEMB>>>(
        fh, fl, w1h, w1l, b1, hh, F1, HLh);
    // 8) h2 = relu(loc @ lw1 + lb1) -> fp16
    hmma_kernel<<<dim3(Rr/128, HCh/128), 256, SMEMB>>>(
        lih, lil, lw1h, lw1l, lb1, h2h, F2, HCh);
    // 9) lin_logits = h @ w2 + b2 (fp16 1-pass, fused stats)
    hmma_logits_kernel<<<dim3(Rr/128, Vv/128), 256, SMEMB>>>(
        hh, w2t, b2, glin, grs, grss, grmx, HLh, Vv);
    // 10) loc_logits = h2 @ lw2 + lb2
    hmma_logits_kernel<<<dim3(Rr/128, Vv/128), 256, SMEMB>>>(
        h2h, lw2t, lb2, gloc, grs + Rr, grss + Rr, grmx + Rr, HCh, Vv);
    // 11) gate, mix
    gate_finalize_kernel<<<(Rr + 255)/256, 256>>>(gate_w, gate_b);
    mix_kernel<<<dim3((Vv/4 + 255)/256, Rr), 256>>>(out);
}

// round 14
// speedup vs baseline: 2.6439x; 1.0650x over previous
#include <cuda_runtime.h>
#include <cuda_fp16.h>
#include <cstdint>
#include <math.h>

#define Bb   2
#define Ss   1024
#define Vv   32000
#define Dd   256
#define Mm   256
#define Ww   8
#define HLh  1024
#define HCh  1024
#define Rr   (Bb*Ss)          // 2048
#define F1   (Mm+Dd)          // 512
#define F2   (Ww*Dd)          // 2048

// ======================= helpers ===========================================
__device__ __forceinline__ uint32_t smem_u32(const void* p) {
    uint32_t a;
    asm("{ .reg .u64 t; cvta.to.shared.u64 t, %1; cvt.u32.u64 %0, t; }" : "=r"(a) : "l"(p));
    return a;
}
#define CP_ASYNC16(dst, src) \
    asm volatile("cp.async.cg.shared.global [%0], [%1], 16;" :: "r"(dst), "l"(src))
#define CP_COMMIT() asm volatile("cp.async.commit_group;" ::: "memory")
#define CP_WAIT(n)  asm volatile("cp.async.wait_group %0;" :: "n"(n) : "memory")
#define STG_CS32(p, v) \
    asm volatile("st.global.cs.b32 [%0], %1;" :: "l"(p), "r"(v) : "memory")

__device__ __forceinline__ void ldmx4(uint32_t* r, uint32_t addr) {
    asm volatile("ldmatrix.sync.aligned.m8n8.x4.shared.b16 {%0,%1,%2,%3}, [%4];"
        : "=r"(r[0]), "=r"(r[1]), "=r"(r[2]), "=r"(r[3]) : "r"(addr));
}
__device__ __forceinline__ void mma_f16(float* c, const uint32_t* a, const uint32_t* b) {
    asm volatile(
        "mma.sync.aligned.m16n8k16.row.col.f32.f16.f16.f32 "
        "{%0,%1,%2,%3}, {%4,%5,%6,%7}, {%8,%9}, {%0,%1,%2,%3};"
        : "+f"(c[0]), "+f"(c[1]), "+f"(c[2]), "+f"(c[3])
        : "r"(a[0]), "r"(a[1]), "r"(a[2]), "r"(a[3]), "r"(b[0]), "r"(b[1]));
}
// monotonic float<->uint encode for atomicMax over signed floats
__device__ __forceinline__ uint32_t fenc(float f) {
    uint32_t i = __float_as_uint(f);
    return (i & 0x80000000u) ? ~i : (i | 0x80000000u);
}
__device__ __forceinline__ float fdec(uint32_t u) {
    return (u & 0x80000000u) ? __uint_as_float(u & 0x7FFFFFFFu) : __uint_as_float(~u);
}
__device__ __forceinline__ uint32_t pack_h2(float a, float b) {
    __half2 h{__float2half_rn(a), __float2half_rn(b)};
    return *reinterpret_cast<uint32_t*>(&h);
}

// ======================= scratch ===========================================
__device__ float g_x[Rr*Dd];
__device__ float g_u[Rr*Mm];
__device__ float g_gate[Rr];
__device__ float    g_rs[2][Rr];
__device__ float    g_rss[2][Rr];
__device__ uint32_t g_rmx[2][Rr];
// fp16 logits intermediates
__device__ __half g_lin[(size_t)Rr*Vv];
__device__ __half g_loc[(size_t)Rr*Vv];
// fp16 operands
__device__ __half g_feat_hi[Rr*F1],  g_feat_lo[Rr*F1];
__device__ __half g_locin_hi[Rr*F2], g_locin_lo[Rr*F2];
__device__ __half g_w1t[HLh*F1];
__device__ __half g_lw1t[HCh*F2];
__device__ __half g_h[Rr*HLh];
__device__ __half g_h2[Rr*HCh];
__device__ __half g_w2t[(size_t)Vv*HLh];
__device__ __half g_lw2t[(size_t)Vv*HCh];

// ======================= small kernels =====================================
__global__ void gather_embed_kernel(const int* __restrict__ tok,
                                    const float* __restrict__ emb) {
    int r = blockIdx.x, d = threadIdx.x;
    float v = emb[(size_t)tok[r] * Dd + d];
    g_x[r*Dd + d] = v;
    __half h = __float2half_rn(v);
    g_feat_hi[(size_t)r*F1 + Mm + d] = h;
    g_feat_lo[(size_t)r*F1 + Mm + d] = __float2half_rn(v - __half2float(h));
}

__global__ void scan_kernel(const float* __restrict__ decays) {
    int b = blockIdx.x, m = threadIdx.x;
    float a = decays[m], s = 0.f;
    for (int t = 0; t < Ss; t++) {
        int r = b*Ss + t;
        s = a*s + g_u[(size_t)r*Mm + m];
        __half h = __float2half_rn(s);
        g_feat_hi[(size_t)r*F1 + m] = h;
        g_feat_lo[(size_t)r*F1 + m] = __float2half_rn(s - __half2float(h));
    }
}

__global__ void build_loc_split_kernel() {
    int idx = blockIdx.x * blockDim.x + threadIdx.x;
    if (idx >= Rr*Ww*Dd) return;
    int d = idx % Dd, w = (idx / Dd) % Ww, r = idx / (Ww*Dd);
    int s = r % Ss, b = r / Ss;
    int ss = s - (Ww-1) + w;
    float v = (ss >= 0) ? g_x[((size_t)(b*Ss + ss))*Dd + d] : 0.f;
    __half h = __float2half_rn(v);
    g_locin_hi[idx] = h;
    g_locin_lo[idx] = __float2half_rn(v - __half2float(h));
}

// transpose: W[K,N] fp32 -> Wt [N,K] single fp16
__global__ void wtconv_f16_kernel(const float* __restrict__ W,
                                  __half* __restrict__ hi, int K, int N) {
    __shared__ float t[32][33];
    int n0 = blockIdx.x * 32, k0 = blockIdx.y * 32;
    int tx = threadIdx.x & 31, ty = threadIdx.x >> 5;
#pragma unroll
    for (int r = 0; r < 4; r++)
        t[ty + 8*r][tx] = W[(size_t)(k0 + ty + 8*r) * N + n0 + tx];
    __syncthreads();
#pragma unroll
    for (int r = 0; r < 4; r++) {
        int n = n0 + ty + 8*r, k = k0 + tx;
        hi[(size_t)n*K + k] = __float2half_rn(t[tx][ty + 8*r]);
    }
}

__global__ void init_stats_kernel() {
    int i = blockIdx.x * blockDim.x + threadIdx.x;
    if (i >= 2*Rr) return;
    ((float*)g_rs)[i] = 0.f;
    ((float*)g_rss)[i] = 0.f;
    ((uint32_t*)g_rmx)[i] = 0u;
}

// ============ HMMA GEMM, 128x128, fp16 2-pass (hidden; ReLU -> fp16) =======
#define STAGES 3
#define ROWB   80
#define ABYTES (128*ROWB)
#define STAGEB (2*ABYTES)

__global__ void __launch_bounds__(256, 2) hmma_hidden_kernel(
        const __half* __restrict__ Ahi, const __half* __restrict__ Alo,
        const __half* __restrict__ Bw,
        const float* __restrict__ bias,
        __half* __restrict__ Chi,
        int K, int Ntot) {
    extern __shared__ char smem[];
    const uint32_t sb = smem_u32(smem);
    const int tid = threadIdx.x;
    const int wid = tid >> 5, lid = tid & 31;
    const int wm = wid & 3, wn = wid >> 2;          // 4 M x 2 N
    const int mBase = blockIdx.x * 128;
    const int nBase = blockIdx.y * 128;

    const int KC = K / 32;
    const int NC = 2 * KC;          // 2 passes: Ahi*B, Alo*B

    float acc[2][8][4];
#pragma unroll
    for (int i = 0; i < 2; i++)
#pragma unroll
        for (int j = 0; j < 8; j++)
#pragma unroll
            for (int q = 0; q < 4; q++) acc[i][j][q] = 0.f;

    auto load_tile = [&](int c, int s) {
        int pass = c / KC, kc = c - pass * KC;
        const __half* Ap = pass ? Alo : Ahi;
        int kof = kc * 32;
        uint32_t ab = sb + s * STAGEB;
        uint32_t bb = ab + ABYTES;
#pragma unroll
        for (int i = 0; i < 2; i++) {
            int id = tid + i * 256;
            int row = id >> 2, q = id & 3;
            CP_ASYNC16(ab + row*ROWB + q*16,
                       Ap + (size_t)(mBase + row) * K + kof + q*8);
        }
#pragma unroll
        for (int i = 0; i < 2; i++) {
            int id = tid + i * 256;
            int row = id >> 2, q = id & 3;
            CP_ASYNC16(bb + row*ROWB + q*16,
                       Bw + (size_t)(nBase + row) * K + kof + q*8);
        }
    };

#pragma unroll
    for (int s = 0; s < STAGES - 1; s++) { load_tile(s, s); CP_COMMIT(); }

    const int aRow = (lid & 7) + ((lid >> 3) & 1) * 8;
    const int aKb  = (lid >> 4) * 16;
    const int bRow = (lid & 7) + ((lid >> 4) & 1) * 8;
    const int bKb  = ((lid >> 3) & 1) * 16;

    for (int c = 0; c < NC; c++) {
        CP_WAIT(STAGES - 2);
        __syncthreads();
        if (c + STAGES - 1 < NC) load_tile(c + STAGES - 1, (c + STAGES - 1) % STAGES);
        CP_COMMIT();

        uint32_t ab = sb + (c % STAGES) * STAGEB;
        uint32_t bb = ab + ABYTES;
#pragma unroll
        for (int ks = 0; ks < 2; ks++) {
            uint32_t afr[2][4], bfr[4][4];
#pragma unroll
            for (int i = 0; i < 2; i++)
                ldmx4(afr[i], ab + (wm*32 + i*16 + aRow)*ROWB + ks*32 + aKb);
#pragma unroll
            for (int t = 0; t < 4; t++)
                ldmx4(bfr[t], bb + (wn*64 + t*16 + bRow)*ROWB + ks*32 + bKb);
#pragma unroll
            for (int i = 0; i < 2; i++)
#pragma unroll
                for (int j = 0; j < 8; j++)
                    mma_f16(acc[i][j], afr[i], bfr[j >> 1] + (j & 1) * 2);
        }
    }
    CP_WAIT(0);

    const int r0 = lid >> 2;
    const int c0 = (lid & 3) * 2;
#pragma unroll
    for (int i = 0; i < 2; i++) {
#pragma unroll
        for (int j = 0; j < 8; j++) {
            int col = nBase + wn*64 + j*8 + c0;
            int rowA = mBase + wm*32 + i*16 + r0;
            float2 bv = *(const float2*)(bias + col);
            float v0 = fmaxf(acc[i][j][0] + bv.x, 0.f);
            float v1 = fmaxf(acc[i][j][1] + bv.y, 0.f);
            float v2 = fmaxf(acc[i][j][2] + bv.x, 0.f);
            float v3 = fmaxf(acc[i][j][3] + bv.y, 0.f);
            *(uint32_t*)(Chi + (size_t)rowA * Ntot + col)     = pack_h2(v0, v1);
            *(uint32_t*)(Chi + (size_t)(rowA+8) * Ntot + col) = pack_h2(v2, v3);
        }
    }
}

// ==== HMMA GEMM, 128x128, fp16 1-pass (logits; fp16 out + fused row stats) ==
__global__ void __launch_bounds__(256, 2) hmma_logits_kernel(
        const __half* __restrict__ A,
        const __half* __restrict__ Bw,
        const float* __restrict__ bias,
        __half* __restrict__ Cf,
        float* __restrict__ rs, float* __restrict__ rss, uint32_t* __restrict__ rmx,
        int K, int Ntot) {
    extern __shared__ char smem[];
    const uint32_t sb = smem_u32(smem);
    const int tid = threadIdx.x;
    const int wid = tid >> 5, lid = tid & 31;
    const int wm = wid & 3, wn = wid >> 2;
    const int mBase = blockIdx.x * 128;
    const int nBase = blockIdx.y * 128;

    const int NC = K / 32;          // single pass

    float acc[2][8][4];
#pragma unroll
    for (int i = 0; i < 2; i++)
#pragma unroll
        for (int j = 0; j < 8; j++)
#pragma unroll
            for (int q = 0; q < 4; q++) acc[i][j][q] = 0.f;

    auto load_tile = [&](int c, int s) {
        int kof = c * 32;
        uint32_t ab = sb + s * STAGEB;
        uint32_t bb = ab + ABYTES;
#pragma unroll
        for (int i = 0; i < 2; i++) {
            int id = tid + i * 256;
            int row = id >> 2, q = id & 3;
            CP_ASYNC16(ab + row*ROWB + q*16,
                       A + (size_t)(mBase + row) * K + kof + q*8);
        }
#pragma unroll
        for (int i = 0; i < 2; i++) {
            int id = tid + i * 256;
            int row = id >> 2, q = id & 3;
            CP_ASYNC16(bb + row*ROWB + q*16,
                       Bw + (size_t)(nBase + row) * K + kof + q*8);
        }
    };

#pragma unroll
    for (int s = 0; s < STAGES - 1; s++) { load_tile(s, s); CP_COMMIT(); }

    const int aRow = (lid & 7) + ((lid >> 3) & 1) * 8;
    const int aKb  = (lid >> 4) * 16;
    const int bRow = (lid & 7) + ((lid >> 4) & 1) * 8;
    const int bKb  = ((lid >> 3) & 1) * 16;

    for (int c = 0; c < NC; c++) {
        CP_WAIT(STAGES - 2);
        __syncthreads();
        if (c + STAGES - 1 < NC) load_tile(c + STAGES - 1, (c + STAGES - 1) % STAGES);
        CP_COMMIT();

        uint32_t ab = sb + (c % STAGES) * STAGEB;
        uint32_t bb = ab + ABYTES;
#pragma unroll
        for (int ks = 0; ks < 2; ks++) {
            uint32_t afr[2][4], bfr[4][4];
#pragma unroll
            for (int i = 0; i < 2; i++)
                ldmx4(afr[i], ab + (wm*32 + i*16 + aRow)*ROWB + ks*32 + aKb);
#pragma unroll
            for (int t = 0; t < 4; t++)
                ldmx4(bfr[t], bb + (wn*64 + t*16 + bRow)*ROWB + ks*32 + bKb);
#pragma unroll
            for (int i = 0; i < 2; i++)
#pragma unroll
                for (int j = 0; j < 8; j++)
                    mma_f16(acc[i][j], afr[i], bfr[j >> 1] + (j & 1) * 2);
        }
    }
    CP_WAIT(0);

    const int r0 = lid >> 2;
    const int c0 = (lid & 3) * 2;
    float ps[4], pq[4], pm[4];
#pragma unroll
    for (int t = 0; t < 4; t++) { ps[t] = 0.f; pq[t] = 0.f; pm[t] = -3.4e38f; }

#pragma unroll
    for (int i = 0; i < 2; i++) {
#pragma unroll
        for (int j = 0; j < 8; j++) {
            int col = nBase + wn*64 + j*8 + c0;
            int rowA = mBase + wm*32 + i*16 + r0;
            float2 bv = *(const float2*)(bias + col);
            float v0 = acc[i][j][0] + bv.x, v1 = acc[i][j][1] + bv.y;
            float v2 = acc[i][j][2] + bv.x, v3 = acc[i][j][3] + bv.y;
            STG_CS32(Cf + (size_t)rowA * Ntot + col,       pack_h2(v0, v1));
            STG_CS32(Cf + (size_t)(rowA + 8) * Ntot + col, pack_h2(v2, v3));
            ps[2*i]   += v0 + v1;  pq[2*i]   += v0*v0 + v1*v1;
            pm[2*i]    = fmaxf(pm[2*i], fmaxf(v0, v1));
            ps[2*i+1] += v2 + v3;  pq[2*i+1] += v2*v2 + v3*v3;
            pm[2*i+1]  = fmaxf(pm[2*i+1], fmaxf(v2, v3));
        }
    }
#pragma unroll
    for (int t = 0; t < 4; t++) {
#pragma unroll
        for (int m = 1; m <= 2; m <<= 1) {
            ps[t] += __shfl_xor_sync(0xffffffffu, ps[t], m);
            pq[t] += __shfl_xor_sync(0xffffffffu, pq[t], m);
            pm[t]  = fmaxf(pm[t], __shfl_xor_sync(0xffffffffu, pm[t], m));
        }
    }
    if ((lid & 3) == 0) {
#pragma unroll
        for (int t = 0; t < 4; t++) {
            int row = mBase + wm*32 + (t >> 1)*16 + r0 + (t & 1)*8;
            atomicAdd(rs + row, ps[t]);
            atomicAdd(rss + row, pq[t]);
            atomicMax(rmx + row, fenc(pm[t]));
        }
    }
}

// ======================= fp32 SGEMM (small u GEMM only) ====================
#define BM 128
#define BNs 128
#define BKs 8
__global__ void __launch_bounds__(256) sgemm_kernel(
        const float* __restrict__ A, const float* __restrict__ Bm,
        float* __restrict__ C, int K, int N) {
    __shared__ float As[BKs][BM];
    __shared__ float Bs2[BKs][BNs];
    int tid = threadIdx.x;
    int tx = tid & 15, ty = tid >> 4;
    int mBase = blockIdx.y * BM, nBase = blockIdx.x * BNs;
    int aM = tid >> 1, aK = (tid & 1) * 4;
    int bK = tid >> 5, bN = (tid & 31) * 4;
    const float* Aptr = A + (size_t)(mBase + aM) * K + aK;
    const float* Bptr = Bm + (size_t)bK * N + nBase + bN;
    float acc[8][8];
#pragma unroll
    for (int i = 0; i < 8; i++)
#pragma unroll
        for (int j = 0; j < 8; j++) acc[i][j] = 0.f;
    for (int kt = 0; kt < K; kt += BKs) {
        float4 av = *(const float4*)Aptr;  Aptr += BKs;
        float4 bv = *(const float4*)Bptr;  Bptr += (size_t)BKs * N;
        As[aK+0][aM] = av.x; As[aK+1][aM] = av.y;
        As[aK+2][aM] = av.z; As[aK+3][aM] = av.w;
        *(float4*)&Bs2[bK][bN] = bv;
        __syncthreads();
        float ar[8], br[8];
#pragma unroll
        for (int k = 0; k < BKs; k++) {
#pragma unroll
            for (int i = 0; i < 8; i++) ar[i] = As[k][ty*8 + i];
#pragma unroll
            for (int j = 0; j < 8; j++) br[j] = Bs2[k][tx*8 + j];
#pragma unroll
            for (int i = 0; i < 8; i++)
#pragma unroll
                for (int j = 0; j < 8; j++)
                    acc[i][j] = fmaf(ar[i], br[j], acc[i][j]);
        }
        __syncthreads();
    }
#pragma unroll
    for (int i = 0; i < 8; i++) {
        float* Crow = C + (size_t)(mBase + ty*8 + i) * N + nBase + tx*8;
#pragma unroll
        for (int j = 0; j < 8; j++) Crow[j] = acc[i][j];
    }
}

// ======================= gate / mix ========================================
__global__ void gate_finalize_kernel(const float* __restrict__ gw,
                                     const float* __restrict__ gb) {
    int r = blockIdx.x * blockDim.x + threadIdx.x;
    if (r >= Rr) return;
    const float inv = 1.f / (float)Vv;
    float mean0 = g_rs[0][r] * inv;
    float std0  = sqrtf(fmaxf(g_rss[0][r] * inv - mean0*mean0, 0.f));
    float max0  = fdec(g_rmx[0][r]);
    float mean1 = g_rs[1][r] * inv;
    float std1  = sqrtf(fmaxf(g_rss[1][r] * inv - mean1*mean1, 0.f));
    float max1  = fdec(g_rmx[1][r]);
    float z = gb[0] + gw[0]*mean0 + gw[1]*max0 + gw[2]*std0
                    + gw[3]*mean1 + gw[4]*max1 + gw[5]*std1;
    g_gate[r] = 1.f / (1.f + expf(-z));
}

__global__ void mix_kernel(float* __restrict__ out) {
    int r = blockIdx.y;
    int c4 = blockIdx.x * blockDim.x + threadIdx.x;   // 4 cols / thread
    if (c4 >= Vv/4) return;
    size_t i2 = (size_t)r * (Vv/2) + (size_t)c4 * 2;
    float g = g_gate[r], og = 1.f - g;
    __half2 a0 = ((const __half2*)g_lin)[i2], a1 = ((const __half2*)g_lin)[i2+1];
    __half2 b0 = ((const __half2*)g_loc)[i2], b1 = ((const __half2*)g_loc)[i2+1];
    float4 o;
    o.x = g*__half2float(a0.x) + og*__half2float(b0.x);
    o.y = g*__half2float(a0.y) + og*__half2float(b0.y);
    o.z = g*__half2float(a1.x) + og*__half2float(b1.x);
    o.w = g*__half2float(a1.y) + og*__half2float(b1.y);
    ((float4*)out)[(size_t)r * (Vv/4) + c4] = o;
}

// ======================= launch ============================================
extern "C" void kernel_launch(void* const* d_in, const int* in_sizes, int n_in,
                              void* d_out, int out_size) {
    const int*   tokens  = (const int*)  d_in[0];
    const float* emb     = (const float*)d_in[1];
    const float* in_proj = (const float*)d_in[2];
    const float* decays  = (const float*)d_in[3];
    const float* w1      = (const float*)d_in[4];
    const float* b1      = (const float*)d_in[5];
    const float* w2      = (const float*)d_in[6];
    const float* b2      = (const float*)d_in[7];
    const float* lw1     = (const float*)d_in[8];
    const float* lb1     = (const float*)d_in[9];
    const float* lw2     = (const float*)d_in[10];
    const float* lb2     = (const float*)d_in[11];
    const float* gate_w  = (const float*)d_in[12];
    const float* gate_b  = (const float*)d_in[13];
    float* out = (float*)d_out;

    float *gx, *gu, *grs, *grss;
    uint32_t* grmx;
    cudaGetSymbolAddress((void**)&gx,   g_x);
    cudaGetSymbolAddress((void**)&gu,   g_u);
    cudaGetSymbolAddress((void**)&grs,  g_rs);
    cudaGetSymbolAddress((void**)&grss, g_rss);
    cudaGetSymbolAddress((void**)&grmx, g_rmx);
    __half *glin, *gloc, *fh, *fl, *lih, *lil, *w1t, *lw1t, *hh, *h2h, *w2t, *lw2t;
    cudaGetSymbolAddress((void**)&glin, g_lin);
    cudaGetSymbolAddress((void**)&gloc, g_loc);
    cudaGetSymbolAddress((void**)&fh,   g_feat_hi);
    cudaGetSymbolAddress((void**)&fl,   g_feat_lo);
    cudaGetSymbolAddress((void**)&lih,  g_locin_hi);
    cudaGetSymbolAddress((void**)&lil,  g_locin_lo);
    cudaGetSymbolAddress((void**)&w1t,  g_w1t);
    cudaGetSymbolAddress((void**)&lw1t, g_lw1t);
    cudaGetSymbolAddress((void**)&hh,   g_h);
    cudaGetSymbolAddress((void**)&h2h,  g_h2);
    cudaGetSymbolAddress((void**)&w2t,  g_w2t);
    cudaGetSymbolAddress((void**)&lw2t, g_lw2t);

    constexpr int SMEMB = STAGES * STAGEB;   // 61440
    cudaFuncSetAttribute(hmma_hidden_kernel, cudaFuncAttributeMaxDynamicSharedMemorySize, SMEMB);
    cudaFuncSetAttribute(hmma_logits_kernel, cudaFuncAttributeMaxDynamicSharedMemorySize, SMEMB);

    // 1) embedding gather (+ feat hi/lo cols M..)
    gather_embed_kernel<<<Rr, Dd>>>(tokens, emb);
    // 2) u = x @ in_proj
    sgemm_kernel<<<dim3(Mm/BNs, Rr/BM), 256>>>(gx, in_proj, gu, Dd, Mm);
    // 3) decay scan -> feat hi/lo cols 0..M
    scan_kernel<<<Bb, Mm>>>(decays);
    // 4) fused window build + split
    build_loc_split_kernel<<<(Rr*Ww*Dd + 255)/256, 256>>>();
    // 5) weight conversions (all single fp16)
    wtconv_f16_kernel<<<dim3(HLh/32, F1/32),  256>>>(w1,  w1t,  F1,  HLh);
    wtconv_f16_kernel<<<dim3(HCh/32, F2/32),  256>>>(lw1, lw1t, F2,  HCh);
    wtconv_f16_kernel<<<dim3(Vv/32, HLh/32), 256>>>(w2,  w2t,  HLh, Vv);
    wtconv_f16_kernel<<<dim3(Vv/32, HCh/32), 256>>>(lw2, lw2t, HCh, Vv);
    // 6) init stats accumulators
    init_stats_kernel<<<(2*Rr + 255)/256, 256>>>();
    // 7) h = relu(feat @ w1 + b1) -> fp16  (fp16 2-pass)
    hmma_hidden_kernel<<<dim3(Rr/128, HLh/128), 256, SMEMB>>>(
        fh, fl, w1t, b1, hh, F1, HLh);
    // 8) h2 = relu(loc @ lw1 + lb1) -> fp16
    hmma_hidden_kernel<<<dim3(Rr/128, HCh/128), 256, SMEMB>>>(
        lih, lil, lw1t, lb1, h2h, F2, HCh);
    // 9) lin_logits = h @ w2 + b2 (fp16 1-pass, fp16 out, fused stats)
    hmma_logits_kernel<<<dim3(Rr/128, Vv/128), 256, SMEMB>>>(
        hh, w2t, b2, glin, grs, grss, grmx, HLh, Vv);
    // 10) loc_logits = h2 @ lw2 + lb2
    hmma_logits_kernel<<<dim3(Rr/128, Vv/128), 256, SMEMB>>>(
        h2h, lw2t, lb2, gloc, grs + Rr, grss + Rr, grmx + Rr, HCh, Vv);
    // 11) gate, mix
    gate_finalize_kernel<<<(Rr + 255)/256, 256>>>(gate_w, gate_b);
    mix_kernel<<<dim3((Vv/4 + 255)/256, Rr), 256>>>(out);
}

// round 15
// speedup vs baseline: 2.8056x; 1.0611x over previous
#include <cuda_runtime.h>
#include <cuda_fp16.h>
#include <cstdint>
#include <math.h>

#define Bb   2
#define Ss   1024
#define Vv   32000
#define Dd   256
#define Mm   256
#define Ww   8
#define HLh  1024
#define HCh  1024
#define Rr   (Bb*Ss)          // 2048
#define F1   (Mm+Dd)          // 512
#define F2   (Ww*Dd)          // 2048

// ======================= helpers ===========================================
__device__ __forceinline__ uint32_t smem_u32(const void* p) {
    uint32_t a;
    asm("{ .reg .u64 t; cvta.to.shared.u64 t, %1; cvt.u32.u64 %0, t; }" : "=r"(a) : "l"(p));
    return a;
}
#define CP_ASYNC16(dst, src) \
    asm volatile("cp.async.cg.shared.global [%0], [%1], 16;" :: "r"(dst), "l"(src))
#define CP_COMMIT() asm volatile("cp.async.commit_group;" ::: "memory")
#define CP_WAIT(n)  asm volatile("cp.async.wait_group %0;" :: "n"(n) : "memory")
#define STG_CS32(p, v) \
    asm volatile("st.global.cs.b32 [%0], %1;" :: "l"(p), "r"(v) : "memory")

__device__ __forceinline__ void ldmx4(uint32_t* r, uint32_t addr) {
    asm volatile("ldmatrix.sync.aligned.m8n8.x4.shared.b16 {%0,%1,%2,%3}, [%4];"
        : "=r"(r[0]), "=r"(r[1]), "=r"(r[2]), "=r"(r[3]) : "r"(addr));
}
__device__ __forceinline__ void mma_f16(float* c, const uint32_t* a, const uint32_t* b) {
    asm volatile(
        "mma.sync.aligned.m16n8k16.row.col.f32.f16.f16.f32 "
        "{%0,%1,%2,%3}, {%4,%5,%6,%7}, {%8,%9}, {%0,%1,%2,%3};"
        : "+f"(c[0]), "+f"(c[1]), "+f"(c[2]), "+f"(c[3])
        : "r"(a[0]), "r"(a[1]), "r"(a[2]), "r"(a[3]), "r"(b[0]), "r"(b[1]));
}
// monotonic float<->uint encode for atomicMax over signed floats
__device__ __forceinline__ uint32_t fenc(float f) {
    uint32_t i = __float_as_uint(f);
    return (i & 0x80000000u) ? ~i : (i | 0x80000000u);
}
__device__ __forceinline__ float fdec(uint32_t u) {
    return (u & 0x80000000u) ? __uint_as_float(u & 0x7FFFFFFFu) : __uint_as_float(~u);
}
__device__ __forceinline__ uint32_t pack_h2(float a, float b) {
    __half2 h{__float2half_rn(a), __float2half_rn(b)};
    return *reinterpret_cast<uint32_t*>(&h);
}

// ======================= scratch ===========================================
__device__ float g_x[Rr*Dd];
__device__ float g_u[Rr*Mm];
__device__ float g_gate[Rr];
__device__ float    g_rs[2][Rr];
__device__ float    g_rss[2][Rr];
__device__ uint32_t g_rmx[2][Rr];
// fp16 logits intermediates
__device__ __half g_lin[(size_t)Rr*Vv];
__device__ __half g_loc[(size_t)Rr*Vv];
// fp16 operands
__device__ __half g_feat_hi[Rr*F1],  g_feat_lo[Rr*F1];
__device__ __half g_locin_hi[Rr*F2], g_locin_lo[Rr*F2];
__device__ __half g_w1t[HLh*F1];
__device__ __half g_lw1t[HCh*F2];
__device__ __half g_h[Rr*HLh];
__device__ __half g_h2[Rr*HCh];
__device__ __half g_w2t[(size_t)Vv*HLh];
__device__ __half g_lw2t[(size_t)Vv*HCh];

// ======================= small kernels =====================================
__global__ void gather_embed_kernel(const int* __restrict__ tok,
                                    const float* __restrict__ emb) {
    int r = blockIdx.x, d = threadIdx.x;
    float v = emb[(size_t)tok[r] * Dd + d];
    g_x[r*Dd + d] = v;
    __half h = __float2half_rn(v);
    g_feat_hi[(size_t)r*F1 + Mm + d] = h;
    g_feat_lo[(size_t)r*F1 + Mm + d] = __float2half_rn(v - __half2float(h));
}

__global__ void scan_kernel(const float* __restrict__ decays) {
    int b = blockIdx.x, m = threadIdx.x;
    float a = decays[m], s = 0.f;
    for (int t = 0; t < Ss; t++) {
        int r = b*Ss + t;
        s = a*s + g_u[(size_t)r*Mm + m];
        __half h = __float2half_rn(s);
        g_feat_hi[(size_t)r*F1 + m] = h;
        g_feat_lo[(size_t)r*F1 + m] = __float2half_rn(s - __half2float(h));
    }
}

__global__ void build_loc_split_kernel() {
    int idx = blockIdx.x * blockDim.x + threadIdx.x;
    if (idx >= Rr*Ww*Dd) return;
    int d = idx % Dd, w = (idx / Dd) % Ww, r = idx / (Ww*Dd);
    int s = r % Ss, b = r / Ss;
    int ss = s - (Ww-1) + w;
    float v = (ss >= 0) ? g_x[((size_t)(b*Ss + ss))*Dd + d] : 0.f;
    __half h = __float2half_rn(v);
    g_locin_hi[idx] = h;
    g_locin_lo[idx] = __float2half_rn(v - __half2float(h));
}

// transpose: W[K,N] fp32 -> Wt [N,K] single fp16
__global__ void wtconv_f16_kernel(const float* __restrict__ W,
                                  __half* __restrict__ hi, int K, int N) {
    __shared__ float t[32][33];
    int n0 = blockIdx.x * 32, k0 = blockIdx.y * 32;
    int tx = threadIdx.x & 31, ty = threadIdx.x >> 5;
#pragma unroll
    for (int r = 0; r < 4; r++)
        t[ty + 8*r][tx] = W[(size_t)(k0 + ty + 8*r) * N + n0 + tx];
    __syncthreads();
#pragma unroll
    for (int r = 0; r < 4; r++) {
        int n = n0 + ty + 8*r, k = k0 + tx;
        hi[(size_t)n*K + k] = __float2half_rn(t[tx][ty + 8*r]);
    }
}

__global__ void init_stats_kernel() {
    int i = blockIdx.x * blockDim.x + threadIdx.x;
    if (i >= 2*Rr) return;
    ((float*)g_rs)[i] = 0.f;
    ((float*)g_rss)[i] = 0.f;
    ((uint32_t*)g_rmx)[i] = 0u;
}

// ===== HMMA GEMM, CTA 128x128, 128 thr / 4 warps (2Mx2N), warp 64x64 =======
#define STAGES 3
#define ROWB   80
#define ABYTES (128*ROWB)
#define STAGEB (2*ABYTES)

// hidden: fp16 2-pass (Ahi, Alo vs single B), ReLU -> fp16
__global__ void __launch_bounds__(128, 2) hmma_hidden_kernel(
        const __half* __restrict__ Ahi, const __half* __restrict__ Alo,
        const __half* __restrict__ Bw,
        const float* __restrict__ bias,
        __half* __restrict__ Chi,
        int K, int Ntot) {
    extern __shared__ char smem[];
    const uint32_t sb = smem_u32(smem);
    const int tid = threadIdx.x;
    const int wid = tid >> 5, lid = tid & 31;
    const int wm = wid & 1, wn = wid >> 1;          // 2 M x 2 N
    const int mBase = blockIdx.x * 128;
    const int nBase = blockIdx.y * 128;

    const int KC = K / 32;
    const int NC = 2 * KC;

    float acc[4][8][4];
#pragma unroll
    for (int i = 0; i < 4; i++)
#pragma unroll
        for (int j = 0; j < 8; j++)
#pragma unroll
            for (int q = 0; q < 4; q++) acc[i][j][q] = 0.f;

    auto load_tile = [&](int c, int s) {
        int pass = c / KC, kc = c - pass * KC;
        const __half* Ap = pass ? Alo : Ahi;
        int kof = kc * 32;
        uint32_t ab = sb + s * STAGEB;
        uint32_t bb = ab + ABYTES;
#pragma unroll
        for (int i = 0; i < 4; i++) {
            int id = tid + i * 128;
            int row = id >> 2, q = id & 3;
            CP_ASYNC16(ab + row*ROWB + q*16,
                       Ap + (size_t)(mBase + row) * K + kof + q*8);
        }
#pragma unroll
        for (int i = 0; i < 4; i++) {
            int id = tid + i * 128;
            int row = id >> 2, q = id & 3;
            CP_ASYNC16(bb + row*ROWB + q*16,
                       Bw + (size_t)(nBase + row) * K + kof + q*8);
        }
    };

#pragma unroll
    for (int s = 0; s < STAGES - 1; s++) { load_tile(s, s); CP_COMMIT(); }

    const int aRow = (lid & 7) + ((lid >> 3) & 1) * 8;
    const int aKb  = (lid >> 4) * 16;
    const int bRow = (lid & 7) + ((lid >> 4) & 1) * 8;
    const int bKb  = ((lid >> 3) & 1) * 16;

    for (int c = 0; c < NC; c++) {
        CP_WAIT(STAGES - 2);
        __syncthreads();
        if (c + STAGES - 1 < NC) load_tile(c + STAGES - 1, (c + STAGES - 1) % STAGES);
        CP_COMMIT();

        uint32_t ab = sb + (c % STAGES) * STAGEB;
        uint32_t bb = ab + ABYTES;
#pragma unroll
        for (int ks = 0; ks < 2; ks++) {
            uint32_t afr[4][4], bfr[4][4];
#pragma unroll
            for (int i = 0; i < 4; i++)
                ldmx4(afr[i], ab + (wm*64 + i*16 + aRow)*ROWB + ks*32 + aKb);
#pragma unroll
            for (int t = 0; t < 4; t++)
                ldmx4(bfr[t], bb + (wn*64 + t*16 + bRow)*ROWB + ks*32 + bKb);
#pragma unroll
            for (int i = 0; i < 4; i++)
#pragma unroll
                for (int j = 0; j < 8; j++)
                    mma_f16(acc[i][j], afr[i], bfr[j >> 1] + (j & 1) * 2);
        }
    }
    CP_WAIT(0);

    const int r0 = lid >> 2;
    const int c0 = (lid & 3) * 2;
#pragma unroll
    for (int i = 0; i < 4; i++) {
#pragma unroll
        for (int j = 0; j < 8; j++) {
            int col = nBase + wn*64 + j*8 + c0;
            int rowA = mBase + wm*64 + i*16 + r0;
            float2 bv = *(const float2*)(bias + col);
            float v0 = fmaxf(acc[i][j][0] + bv.x, 0.f);
            float v1 = fmaxf(acc[i][j][1] + bv.y, 0.f);
            float v2 = fmaxf(acc[i][j][2] + bv.x, 0.f);
            float v3 = fmaxf(acc[i][j][3] + bv.y, 0.f);
            *(uint32_t*)(Chi + (size_t)rowA * Ntot + col)     = pack_h2(v0, v1);
            *(uint32_t*)(Chi + (size_t)(rowA+8) * Ntot + col) = pack_h2(v2, v3);
        }
    }
}

// logits: fp16 1-pass; fp16 out + fused row stats
__global__ void __launch_bounds__(128, 2) hmma_logits_kernel(
        const __half* __restrict__ A,
        const __half* __restrict__ Bw,
        const float* __restrict__ bias,
        __half* __restrict__ Cf,
        float* __restrict__ rs, float* __restrict__ rss, uint32_t* __restrict__ rmx,
        int K, int Ntot) {
    extern __shared__ char smem[];
    const uint32_t sb = smem_u32(smem);
    const int tid = threadIdx.x;
    const int wid = tid >> 5, lid = tid & 31;
    const int wm = wid & 1, wn = wid >> 1;          // 2 M x 2 N
    const int mBase = blockIdx.x * 128;
    const int nBase = blockIdx.y * 128;

    const int NC = K / 32;          // single pass

    float acc[4][8][4];
#pragma unroll
    for (int i = 0; i < 4; i++)
#pragma unroll
        for (int j = 0; j < 8; j++)
#pragma unroll
            for (int q = 0; q < 4; q++) acc[i][j][q] = 0.f;

    auto load_tile = [&](int c, int s) {
        int kof = c * 32;
        uint32_t ab = sb + s * STAGEB;
        uint32_t bb = ab + ABYTES;
#pragma unroll
        for (int i = 0; i < 4; i++) {
            int id = tid + i * 128;
            int row = id >> 2, q = id & 3;
            CP_ASYNC16(ab + row*ROWB + q*16,
                       A + (size_t)(mBase + row) * K + kof + q*8);
        }
#pragma unroll
        for (int i = 0; i < 4; i++) {
            int id = tid + i * 128;
            int row = id >> 2, q = id & 3;
            CP_ASYNC16(bb + row*ROWB + q*16,
                       Bw + (size_t)(nBase + row) * K + kof + q*8);
        }
    };

#pragma unroll
    for (int s = 0; s < STAGES - 1; s++) { load_tile(s, s); CP_COMMIT(); }

    const int aRow = (lid & 7) + ((lid >> 3) & 1) * 8;
    const int aKb  = (lid >> 4) * 16;
    const int bRow = (lid & 7) + ((lid >> 4) & 1) * 8;
    const int bKb  = ((lid >> 3) & 1) * 16;

    for (int c = 0; c < NC; c++) {
        CP_WAIT(STAGES - 2);
        __syncthreads();
        if (c + STAGES - 1 < NC) load_tile(c + STAGES - 1, (c + STAGES - 1) % STAGES);
        CP_COMMIT();

        uint32_t ab = sb + (c % STAGES) * STAGEB;
        uint32_t bb = ab + ABYTES;
#pragma unroll
        for (int ks = 0; ks < 2; ks++) {
            uint32_t afr[4][4], bfr[4][4];
#pragma unroll
            for (int i = 0; i < 4; i++)
                ldmx4(afr[i], ab + (wm*64 + i*16 + aRow)*ROWB + ks*32 + aKb);
#pragma unroll
            for (int t = 0; t < 4; t++)
                ldmx4(bfr[t], bb + (wn*64 + t*16 + bRow)*ROWB + ks*32 + bKb);
#pragma unroll
            for (int i = 0; i < 4; i++)
#pragma unroll
                for (int j = 0; j < 8; j++)
                    mma_f16(acc[i][j], afr[i], bfr[j >> 1] + (j & 1) * 2);
        }
    }
    CP_WAIT(0);

    const int r0 = lid >> 2;
    const int c0 = (lid & 3) * 2;
    float ps[8], pq[8], pm[8];
#pragma unroll
    for (int t = 0; t < 8; t++) { ps[t] = 0.f; pq[t] = 0.f; pm[t] = -3.4e38f; }

#pragma unroll
    for (int i = 0; i < 4; i++) {
#pragma unroll
        for (int j = 0; j < 8; j++) {
            int col = nBase + wn*64 + j*8 + c0;
            int rowA = mBase + wm*64 + i*16 + r0;
            float2 bv = *(const float2*)(bias + col);
            float v0 = acc[i][j][0] + bv.x, v1 = acc[i][j][1] + bv.y;
            float v2 = acc[i][j][2] + bv.x, v3 = acc[i][j][3] + bv.y;
            STG_CS32(Cf + (size_t)rowA * Ntot + col,       pack_h2(v0, v1));
            STG_CS32(Cf + (size_t)(rowA + 8) * Ntot + col, pack_h2(v2, v3));
            ps[2*i]   += v0 + v1;  pq[2*i]   += v0*v0 + v1*v1;
            pm[2*i]    = fmaxf(pm[2*i], fmaxf(v0, v1));
            ps[2*i+1] += v2 + v3;  pq[2*i+1] += v2*v2 + v3*v3;
            pm[2*i+1]  = fmaxf(pm[2*i+1], fmaxf(v2, v3));
        }
    }
#pragma unroll
    for (int t = 0; t < 8; t++) {
#pragma unroll
        for (int m = 1; m <= 2; m <<= 1) {
            ps[t] += __shfl_xor_sync(0xffffffffu, ps[t], m);
            pq[t] += __shfl_xor_sync(0xffffffffu, pq[t], m);
            pm[t]  = fmaxf(pm[t], __shfl_xor_sync(0xffffffffu, pm[t], m));
        }
    }
    if ((lid & 3) == 0) {
#pragma unroll
        for (int t = 0; t < 8; t++) {
            int row = mBase + wm*64 + (t >> 1)*16 + r0 + (t & 1)*8;
            atomicAdd(rs + row, ps[t]);
            atomicAdd(rss + row, pq[t]);
            atomicMax(rmx + row, fenc(pm[t]));
        }
    }
}

// ======================= fp32 SGEMM (small u GEMM only) ====================
#define BM 128
#define BNs 128
#define BKs 8
__global__ void __launch_bounds__(256) sgemm_kernel(
        const float* __restrict__ A, const float* __restrict__ Bm,
        float* __restrict__ C, int K, int N) {
    __shared__ float As[BKs][BM];
    __shared__ float Bs2[BKs][BNs];
    int tid = threadIdx.x;
    int tx = tid & 15, ty = tid >> 4;
    int mBase = blockIdx.y * BM, nBase = blockIdx.x * BNs;
    int aM = tid >> 1, aK = (tid & 1) * 4;
    int bK = tid >> 5, bN = (tid & 31) * 4;
    const float* Aptr = A + (size_t)(mBase + aM) * K + aK;
    const float* Bptr = Bm + (size_t)bK * N + nBase + bN;
    float acc[8][8];
#pragma unroll
    for (int i = 0; i < 8; i++)
#pragma unroll
        for (int j = 0; j < 8; j++) acc[i][j] = 0.f;
    for (int kt = 0; kt < K; kt += BKs) {
        float4 av = *(const float4*)Aptr;  Aptr += BKs;
        float4 bv = *(const float4*)Bptr;  Bptr += (size_t)BKs * N;
        As[aK+0][aM] = av.x; As[aK+1][aM] = av.y;
        As[aK+2][aM] = av.z; As[aK+3][aM] = av.w;
        *(float4*)&Bs2[bK][bN] = bv;
        __syncthreads();
        float ar[8], br[8];
#pragma unroll
        for (int k = 0; k < BKs; k++) {
#pragma unroll
            for (int i = 0; i < 8; i++) ar[i] = As[k][ty*8 + i];
#pragma unroll
            for (int j = 0; j < 8; j++) br[j] = Bs2[k][tx*8 + j];
#pragma unroll
            for (int i = 0; i < 8; i++)
#pragma unroll
                for (int j = 0; j < 8; j++)
                    acc[i][j] = fmaf(ar[i], br[j], acc[i][j]);
        }
        __syncthreads();
    }
#pragma unroll
    for (int i = 0; i < 8; i++) {
        float* Crow = C + (size_t)(mBase + ty*8 + i) * N + nBase + tx*8;
#pragma unroll
        for (int j = 0; j < 8; j++) Crow[j] = acc[i][j];
    }
}

// ======================= gate / mix ========================================
__global__ void gate_finalize_kernel(const float* __restrict__ gw,
                                     const float* __restrict__ gb) {
    int r = blockIdx.x * blockDim.x + threadIdx.x;
    if (r >= Rr) return;
    const float inv = 1.f / (float)Vv;
    float mean0 = g_rs[0][r] * inv;
    float std0  = sqrtf(fmaxf(g_rss[0][r] * inv - mean0*mean0, 0.f));
    float max0  = fdec(g_rmx[0][r]);
    float mean1 = g_rs[1][r] * inv;
    float std1  = sqrtf(fmaxf(g_rss[1][r] * inv - mean1*mean1, 0.f));
    float max1  = fdec(g_rmx[1][r]);
    float z = gb[0] + gw[0]*mean0 + gw[1]*max0 + gw[2]*std0
                    + gw[3]*mean1 + gw[4]*max1 + gw[5]*std1;
    g_gate[r] = 1.f / (1.f + expf(-z));
}

__global__ void mix_kernel(float* __restrict__ out) {
    int r = blockIdx.y;
    int c4 = blockIdx.x * blockDim.x + threadIdx.x;   // 4 cols / thread
    if (c4 >= Vv/4) return;
    size_t i2 = (size_t)r * (Vv/2) + (size_t)c4 * 2;
    float g = g_gate[r], og = 1.f - g;
    __half2 a0 = ((const __half2*)g_lin)[i2], a1 = ((const __half2*)g_lin)[i2+1];
    __half2 b0 = ((const __half2*)g_loc)[i2], b1 = ((const __half2*)g_loc)[i2+1];
    float4 o;
    o.x = g*__half2float(a0.x) + og*__half2float(b0.x);
    o.y = g*__half2float(a0.y) + og*__half2float(b0.y);
    o.z = g*__half2float(a1.x) + og*__half2float(b1.x);
    o.w = g*__half2float(a1.y) + og*__half2float(b1.y);
    ((float4*)out)[(size_t)r * (Vv/4) + c4] = o;
}

// ======================= launch ============================================
extern "C" void kernel_launch(void* const* d_in, const int* in_sizes, int n_in,
                              void* d_out, int out_size) {
    const int*   tokens  = (const int*)  d_in[0];
    const float* emb     = (const float*)d_in[1];
    const float* in_proj = (const float*)d_in[2];
    const float* decays  = (const float*)d_in[3];
    const float* w1      = (const float*)d_in[4];
    const float* b1      = (const float*)d_in[5];
    const float* w2      = (const float*)d_in[6];
    const float* b2      = (const float*)d_in[7];
    const float* lw1     = (const float*)d_in[8];
    const float* lb1     = (const float*)d_in[9];
    const float* lw2     = (const float*)d_in[10];
    const float* lb2     = (const float*)d_in[11];
    const float* gate_w  = (const float*)d_in[12];
    const float* gate_b  = (const float*)d_in[13];
    float* out = (float*)d_out;

    float *gx, *gu, *grs, *grss;
    uint32_t* grmx;
    cudaGetSymbolAddress((void**)&gx,   g_x);
    cudaGetSymbolAddress((void**)&gu,   g_u);
    cudaGetSymbolAddress((void**)&grs,  g_rs);
    cudaGetSymbolAddress((void**)&grss, g_rss);
    cudaGetSymbolAddress((void**)&grmx, g_rmx);
    __half *glin, *gloc, *fh, *fl, *lih, *lil, *w1t, *lw1t, *hh, *h2h, *w2t, *lw2t;
    cudaGetSymbolAddress((void**)&glin, g_lin);
    cudaGetSymbolAddress((void**)&gloc, g_loc);
    cudaGetSymbolAddress((void**)&fh,   g_feat_hi);
    cudaGetSymbolAddress((void**)&fl,   g_feat_lo);
    cudaGetSymbolAddress((void**)&lih,  g_locin_hi);
    cudaGetSymbolAddress((void**)&lil,  g_locin_lo);
    cudaGetSymbolAddress((void**)&w1t,  g_w1t);
    cudaGetSymbolAddress((void**)&lw1t, g_lw1t);
    cudaGetSymbolAddress((void**)&hh,   g_h);
    cudaGetSymbolAddress((void**)&h2h,  g_h2);
    cudaGetSymbolAddress((void**)&w2t,  g_w2t);
    cudaGetSymbolAddress((void**)&lw2t, g_lw2t);

    constexpr int SMEMB = STAGES * STAGEB;   // 61440
    cudaFuncSetAttribute(hmma_hidden_kernel, cudaFuncAttributeMaxDynamicSharedMemorySize, SMEMB);
    cudaFuncSetAttribute(hmma_logits_kernel, cudaFuncAttributeMaxDynamicSharedMemorySize, SMEMB);

    // 1) embedding gather (+ feat hi/lo cols M..)
    gather_embed_kernel<<<Rr, Dd>>>(tokens, emb);
    // 2) u = x @ in_proj
    sgemm_kernel<<<dim3(Mm/BNs, Rr/BM), 256>>>(gx, in_proj, gu, Dd, Mm);
    // 3) decay scan -> feat hi/lo cols 0..M
    scan_kernel<<<Bb, Mm>>>(decays);
    // 4) fused window build + split
    build_loc_split_kernel<<<(Rr*Ww*Dd + 255)/256, 256>>>();
    // 5) weight conversions (all single fp16)
    wtconv_f16_kernel<<<dim3(HLh/32, F1/32),  256>>>(w1,  w1t,  F1,  HLh);
    wtconv_f16_kernel<<<dim3(HCh/32, F2/32),  256>>>(lw1, lw1t, F2,  HCh);
    wtconv_f16_kernel<<<dim3(Vv/32, HLh/32), 256>>>(w2,  w2t,  HLh, Vv);
    wtconv_f16_kernel<<<dim3(Vv/32, HCh/32), 256>>>(lw2, lw2t, HCh, Vv);
    // 6) init stats accumulators
    init_stats_kernel<<<(2*Rr + 255)/256, 256>>>();
    // 7) h = relu(feat @ w1 + b1) -> fp16  (fp16 2-pass)
    hmma_hidden_kernel<<<dim3(Rr/128, HLh/128), 128, SMEMB>>>(
        fh, fl, w1t, b1, hh, F1, HLh);
    // 8) h2 = relu(loc @ lw1 + lb1) -> fp16
    hmma_hidden_kernel<<<dim3(Rr/128, HCh/128), 128, SMEMB>>>(
        lih, lil, lw1t, lb1, h2h, F2, HCh);
    // 9) lin_logits = h @ w2 + b2 (fp16 1-pass, fp16 out, fused stats)
    hmma_logits_kernel<<<dim3(Rr/128, Vv/128), 128, SMEMB>>>(
        hh, w2t, b2, glin, grs, grss, grmx, HLh, Vv);
    // 10) loc_logits = h2 @ lw2 + lb2
    hmma_logits_kernel<<<dim3(Rr/128, Vv/128), 128, SMEMB>>>(
        h2h, lw2t, lb2, gloc, grs + Rr, grss + Rr, grmx + Rr, HCh, Vv);
    // 11) gate, mix
    gate_finalize_kernel<<<(Rr + 255)/256, 256>>>(gate_w, gate_b);
    mix_kernel<<<dim3((Vv/4 + 255)/256, Rr), 256>>>(out);
}

// round 16
// speedup vs baseline: 2.8087x; 1.0011x over previous
#include <cuda_runtime.h>
#include <cuda_fp16.h>
#include <cstdint>
#include <math.h>

#define Bb   2
#define Ss   1024
#define Vv   32000
#define Dd   256
#define Mm   256
#define Ww   8
#define HLh  1024
#define HCh  1024
#define Rr   (Bb*Ss)          // 2048
#define F1   (Mm+Dd)          // 512
#define F2   (Ww*Dd)          // 2048

// ======================= helpers ===========================================
__device__ __forceinline__ uint32_t smem_u32(const void* p) {
    uint32_t a;
    asm("{ .reg .u64 t; cvta.to.shared.u64 t, %1; cvt.u32.u64 %0, t; }" : "=r"(a) : "l"(p));
    return a;
}
#define CP_ASYNC16(dst, src) \
    asm volatile("cp.async.cg.shared.global [%0], [%1], 16;" :: "r"(dst), "l"(src))
#define CP_COMMIT() asm volatile("cp.async.commit_group;" ::: "memory")
#define CP_WAIT(n)  asm volatile("cp.async.wait_group %0;" :: "n"(n) : "memory")
#define STG_CS32(p, v) \
    asm volatile("st.global.cs.b32 [%0], %1;" :: "l"(p), "r"(v) : "memory")

__device__ __forceinline__ void ldmx4(uint32_t* r, uint32_t addr) {
    asm volatile("ldmatrix.sync.aligned.m8n8.x4.shared.b16 {%0,%1,%2,%3}, [%4];"
        : "=r"(r[0]), "=r"(r[1]), "=r"(r[2]), "=r"(r[3]) : "r"(addr));
}
__device__ __forceinline__ void mma_f16(float* c, const uint32_t* a, const uint32_t* b) {
    asm volatile(
        "mma.sync.aligned.m16n8k16.row.col.f32.f16.f16.f32 "
        "{%0,%1,%2,%3}, {%4,%5,%6,%7}, {%8,%9}, {%0,%1,%2,%3};"
        : "+f"(c[0]), "+f"(c[1]), "+f"(c[2]), "+f"(c[3])
        : "r"(a[0]), "r"(a[1]), "r"(a[2]), "r"(a[3]), "r"(b[0]), "r"(b[1]));
}
// monotonic float<->uint encode for atomicMax over signed floats
__device__ __forceinline__ uint32_t fenc(float f) {
    uint32_t i = __float_as_uint(f);
    return (i & 0x80000000u) ? ~i : (i | 0x80000000u);
}
__device__ __forceinline__ float fdec(uint32_t u) {
    return (u & 0x80000000u) ? __uint_as_float(u & 0x7FFFFFFFu) : __uint_as_float(~u);
}
__device__ __forceinline__ uint32_t pack_h2(float a, float b) {
    __half2 h{__float2half_rn(a), __float2half_rn(b)};
    return *reinterpret_cast<uint32_t*>(&h);
}

// ======================= scratch ===========================================
__device__ float g_x[Rr*Dd];
__device__ float g_u[Rr*Mm];
__device__ float g_gate[Rr];
__device__ float    g_rs[2][Rr];
__device__ float    g_rss[2][Rr];
__device__ uint32_t g_rmx[2][Rr];
// fp16 logits intermediates
__device__ __half g_lin[(size_t)Rr*Vv];
__device__ __half g_loc[(size_t)Rr*Vv];
// fp16 operands
__device__ __half g_feat_hi[Rr*F1],  g_feat_lo[Rr*F1];
__device__ __half g_locin_hi[Rr*F2], g_locin_lo[Rr*F2];
__device__ __half g_w1t[HLh*F1];
__device__ __half g_lw1t[HCh*F2];
__device__ __half g_h[Rr*HLh];
__device__ __half g_h2[Rr*HCh];
__device__ __half g_w2t[(size_t)Vv*HLh];
__device__ __half g_lw2t[(size_t)Vv*HCh];

// ======================= small kernels =====================================
__global__ void gather_embed_kernel(const int* __restrict__ tok,
                                    const float* __restrict__ emb) {
    int r = blockIdx.x, d = threadIdx.x;
    float v = emb[(size_t)tok[r] * Dd + d];
    g_x[r*Dd + d] = v;
    __half h = __float2half_rn(v);
    g_feat_hi[(size_t)r*F1 + Mm + d] = h;
    g_feat_lo[(size_t)r*F1 + Mm + d] = __float2half_rn(v - __half2float(h));
}

__global__ void scan_kernel(const float* __restrict__ decays) {
    int b = blockIdx.x, m = threadIdx.x;
    float a = decays[m], s = 0.f;
    for (int t = 0; t < Ss; t++) {
        int r = b*Ss + t;
        s = a*s + g_u[(size_t)r*Mm + m];
        __half h = __float2half_rn(s);
        g_feat_hi[(size_t)r*F1 + m] = h;
        g_feat_lo[(size_t)r*F1 + m] = __float2half_rn(s - __half2float(h));
    }
}

__global__ void build_loc_split_kernel() {
    int idx = blockIdx.x * blockDim.x + threadIdx.x;
    if (idx >= Rr*Ww*Dd) return;
    int d = idx % Dd, w = (idx / Dd) % Ww, r = idx / (Ww*Dd);
    int s = r % Ss, b = r / Ss;
    int ss = s - (Ww-1) + w;
    float v = (ss >= 0) ? g_x[((size_t)(b*Ss + ss))*Dd + d] : 0.f;
    __half h = __float2half_rn(v);
    g_locin_hi[idx] = h;
    g_locin_lo[idx] = __float2half_rn(v - __half2float(h));
}

// transpose: W[K,N] fp32 -> Wt [N,K] single fp16
__global__ void wtconv_f16_kernel(const float* __restrict__ W,
                                  __half* __restrict__ hi, int K, int N) {
    __shared__ float t[32][33];
    int n0 = blockIdx.x * 32, k0 = blockIdx.y * 32;
    int tx = threadIdx.x & 31, ty = threadIdx.x >> 5;
#pragma unroll
    for (int r = 0; r < 4; r++)
        t[ty + 8*r][tx] = W[(size_t)(k0 + ty + 8*r) * N + n0 + tx];
    __syncthreads();
#pragma unroll
    for (int r = 0; r < 4; r++) {
        int n = n0 + ty + 8*r, k = k0 + tx;
        hi[(size_t)n*K + k] = __float2half_rn(t[tx][ty + 8*r]);
    }
}

__global__ void init_stats_kernel() {
    int i = blockIdx.x * blockDim.x + threadIdx.x;
    if (i >= 2*Rr) return;
    ((float*)g_rs)[i] = 0.f;
    ((float*)g_rss)[i] = 0.f;
    ((uint32_t*)g_rmx)[i] = 0u;
}

// ===== HMMA GEMM, CTA 128x128, 128 thr / 4 warps (2Mx2N), warp 64x64 =======
#define STAGES 3
#define ROWB   80
#define ABYTES (128*ROWB)
#define STAGEB (2*ABYTES)

// hidden: fp16 2-pass (Ahi, Alo vs single B), ReLU -> fp16
__global__ void __launch_bounds__(128, 2) hmma_hidden_kernel(
        const __half* __restrict__ Ahi, const __half* __restrict__ Alo,
        const __half* __restrict__ Bw,
        const float* __restrict__ bias,
        __half* __restrict__ Chi,
        int K, int Ntot) {
    extern __shared__ char smem[];
    const uint32_t sb = smem_u32(smem);
    const int tid = threadIdx.x;
    const int wid = tid >> 5, lid = tid & 31;
    const int wm = wid & 1, wn = wid >> 1;          // 2 M x 2 N
    const int mBase = blockIdx.x * 128;
    const int nBase = blockIdx.y * 128;

    const int KC = K / 32;
    const int NC = 2 * KC;

    float acc[4][8][4];
#pragma unroll
    for (int i = 0; i < 4; i++)
#pragma unroll
        for (int j = 0; j < 8; j++)
#pragma unroll
            for (int q = 0; q < 4; q++) acc[i][j][q] = 0.f;

    auto load_tile = [&](int c, int s) {
        int pass = c / KC, kc = c - pass * KC;
        const __half* Ap = pass ? Alo : Ahi;
        int kof = kc * 32;
        uint32_t ab = sb + s * STAGEB;
        uint32_t bb = ab + ABYTES;
#pragma unroll
        for (int i = 0; i < 4; i++) {
            int id = tid + i * 128;
            int row = id >> 2, q = id & 3;
            CP_ASYNC16(ab + row*ROWB + q*16,
                       Ap + (size_t)(mBase + row) * K + kof + q*8);
        }
#pragma unroll
        for (int i = 0; i < 4; i++) {
            int id = tid + i * 128;
            int row = id >> 2, q = id & 3;
            CP_ASYNC16(bb + row*ROWB + q*16,
                       Bw + (size_t)(nBase + row) * K + kof + q*8);
        }
    };

#pragma unroll
    for (int s = 0; s < STAGES - 1; s++) { load_tile(s, s); CP_COMMIT(); }

    const int aRow = (lid & 7) + ((lid >> 3) & 1) * 8;
    const int aKb  = (lid >> 4) * 16;
    const int bRow = (lid & 7) + ((lid >> 4) & 1) * 8;
    const int bKb  = ((lid >> 3) & 1) * 16;

    for (int c = 0; c < NC; c++) {
        CP_WAIT(STAGES - 2);
        __syncthreads();
        if (c + STAGES - 1 < NC) load_tile(c + STAGES - 1, (c + STAGES - 1) % STAGES);
        CP_COMMIT();

        uint32_t ab = sb + (c % STAGES) * STAGEB;
        uint32_t bb = ab + ABYTES;
#pragma unroll
        for (int ks = 0; ks < 2; ks++) {
            uint32_t afr[4][4], bfr[4][4];
#pragma unroll
            for (int i = 0; i < 4; i++)
                ldmx4(afr[i], ab + (wm*64 + i*16 + aRow)*ROWB + ks*32 + aKb);
#pragma unroll
            for (int t = 0; t < 4; t++)
                ldmx4(bfr[t], bb + (wn*64 + t*16 + bRow)*ROWB + ks*32 + bKb);
#pragma unroll
            for (int i = 0; i < 4; i++)
#pragma unroll
                for (int j = 0; j < 8; j++)
                    mma_f16(acc[i][j], afr[i], bfr[j >> 1] + (j & 1) * 2);
        }
    }
    CP_WAIT(0);

    const int r0 = lid >> 2;
    const int c0 = (lid & 3) * 2;
#pragma unroll
    for (int i = 0; i < 4; i++) {
#pragma unroll
        for (int j = 0; j < 8; j++) {
            int col = nBase + wn*64 + j*8 + c0;
            int rowA = mBase + wm*64 + i*16 + r0;
            float2 bv = *(const float2*)(bias + col);
            float v0 = fmaxf(acc[i][j][0] + bv.x, 0.f);
            float v1 = fmaxf(acc[i][j][1] + bv.y, 0.f);
            float v2 = fmaxf(acc[i][j][2] + bv.x, 0.f);
            float v3 = fmaxf(acc[i][j][3] + bv.y, 0.f);
            *(uint32_t*)(Chi + (size_t)rowA * Ntot + col)     = pack_h2(v0, v1);
            *(uint32_t*)(Chi + (size_t)(rowA+8) * Ntot + col) = pack_h2(v2, v3);
        }
    }
}

// logits: fp16 1-pass; fp16 out + fused row stats
__global__ void __launch_bounds__(128, 2) hmma_logits_kernel(
        const __half* __restrict__ A,
        const __half* __restrict__ Bw,
        const float* __restrict__ bias,
        __half* __restrict__ Cf,
        float* __restrict__ rs, float* __restrict__ rss, uint32_t* __restrict__ rmx,
        int K, int Ntot) {
    extern __shared__ char smem[];
    const uint32_t sb = smem_u32(smem);
    const int tid = threadIdx.x;
    const int wid = tid >> 5, lid = tid & 31;
    const int wm = wid & 1, wn = wid >> 1;          // 2 M x 2 N
    const int mBase = blockIdx.x * 128;
    const int nBase = blockIdx.y * 128;

    const int NC = K / 32;          // single pass

    float acc[4][8][4];
#pragma unroll
    for (int i = 0; i < 4; i++)
#pragma unroll
        for (int j = 0; j < 8; j++)
#pragma unroll
            for (int q = 0; q < 4; q++) acc[i][j][q] = 0.f;

    auto load_tile = [&](int c, int s) {
        int kof = c * 32;
        uint32_t ab = sb + s * STAGEB;
        uint32_t bb = ab + ABYTES;
#pragma unroll
        for (int i = 0; i < 4; i++) {
            int id = tid + i * 128;
            int row = id >> 2, q = id & 3;
            CP_ASYNC16(ab + row*ROWB + q*16,
                       A + (size_t)(mBase + row) * K + kof + q*8);
        }
#pragma unroll
        for (int i = 0; i < 4; i++) {
            int id = tid + i * 128;
            int row = id >> 2, q = id & 3;
            CP_ASYNC16(bb + row*ROWB + q*16,
                       Bw + (size_t)(nBase + row) * K + kof + q*8);
        }
    };

#pragma unroll
    for (int s = 0; s < STAGES - 1; s++) { load_tile(s, s); CP_COMMIT(); }

    const int aRow = (lid & 7) + ((lid >> 3) & 1) * 8;
    const int aKb  = (lid >> 4) * 16;
    const int bRow = (lid & 7) + ((lid >> 4) & 1) * 8;
    const int bKb  = ((lid >> 3) & 1) * 16;

    for (int c = 0; c < NC; c++) {
        CP_WAIT(STAGES - 2);
        __syncthreads();
        if (c + STAGES - 1 < NC) load_tile(c + STAGES - 1, (c + STAGES - 1) % STAGES);
        CP_COMMIT();

        uint32_t ab = sb + (c % STAGES) * STAGEB;
        uint32_t bb = ab + ABYTES;
#pragma unroll
        for (int ks = 0; ks < 2; ks++) {
            uint32_t afr[4][4], bfr[4][4];
#pragma unroll
            for (int i = 0; i < 4; i++)
                ldmx4(afr[i], ab + (wm*64 + i*16 + aRow)*ROWB + ks*32 + aKb);
#pragma unroll
            for (int t = 0; t < 4; t++)
                ldmx4(bfr[t], bb + (wn*64 + t*16 + bRow)*ROWB + ks*32 + bKb);
#pragma unroll
            for (int i = 0; i < 4; i++)
#pragma unroll
                for (int j = 0; j < 8; j++)
                    mma_f16(acc[i][j], afr[i], bfr[j >> 1] + (j & 1) * 2);
        }
    }
    CP_WAIT(0);

    const int r0 = lid >> 2;
    const int c0 = (lid & 3) * 2;
    float ps[8], pq[8], pm[8];
#pragma unroll
    for (int t = 0; t < 8; t++) { ps[t] = 0.f; pq[t] = 0.f; pm[t] = -3.4e38f; }

#pragma unroll
    for (int i = 0; i < 4; i++) {
#pragma unroll
        for (int j = 0; j < 8; j++) {
            int col = nBase + wn*64 + j*8 + c0;
            int rowA = mBase + wm*64 + i*16 + r0;
            float2 bv = *(const float2*)(bias + col);
            float v0 = acc[i][j][0] + bv.x, v1 = acc[i][j][1] + bv.y;
            float v2 = acc[i][j][2] + bv.x, v3 = acc[i][j][3] + bv.y;
            STG_CS32(Cf + (size_t)rowA * Ntot + col,       pack_h2(v0, v1));
            STG_CS32(Cf + (size_t)(rowA + 8) * Ntot + col, pack_h2(v2, v3));
            ps[2*i]   += v0 + v1;  pq[2*i]   += v0*v0 + v1*v1;
            pm[2*i]    = fmaxf(pm[2*i], fmaxf(v0, v1));
            ps[2*i+1] += v2 + v3;  pq[2*i+1] += v2*v2 + v3*v3;
            pm[2*i+1]  = fmaxf(pm[2*i+1], fmaxf(v2, v3));
        }
    }
#pragma unroll
    for (int t = 0; t < 8; t++) {
#pragma unroll
        for (int m = 1; m <= 2; m <<= 1) {
            ps[t] += __shfl_xor_sync(0xffffffffu, ps[t], m);
            pq[t] += __shfl_xor_sync(0xffffffffu, pq[t], m);
            pm[t]  = fmaxf(pm[t], __shfl_xor_sync(0xffffffffu, pm[t], m));
        }
    }
    if ((lid & 3) == 0) {
#pragma unroll
        for (int t = 0; t < 8; t++) {
            int row = mBase + wm*64 + (t >> 1)*16 + r0 + (t & 1)*8;
            atomicAdd(rs + row, ps[t]);
            atomicAdd(rss + row, pq[t]);
            atomicMax(rmx + row, fenc(pm[t]));
        }
    }
}

// ======================= fp32 SGEMM (small u GEMM only) ====================
#define BM 128
#define BNs 128
#define BKs 8
__global__ void __launch_bounds__(256) sgemm_kernel(
        const float* __restrict__ A, const float* __restrict__ Bm,
        float* __restrict__ C, int K, int N) {
    __shared__ float As[BKs][BM];
    __shared__ float Bs2[BKs][BNs];
    int tid = threadIdx.x;
    int tx = tid & 15, ty = tid >> 4;
    int mBase = blockIdx.y * BM, nBase = blockIdx.x * BNs;
    int aM = tid >> 1, aK = (tid & 1) * 4;
    int bK = tid >> 5, bN = (tid & 31) * 4;
    const float* Aptr = A + (size_t)(mBase + aM) * K + aK;
    const float* Bptr = Bm + (size_t)bK * N + nBase + bN;
    float acc[8][8];
#pragma unroll
    for (int i = 0; i < 8; i++)
#pragma unroll
        for (int j = 0; j < 8; j++) acc[i][j] = 0.f;
    for (int kt = 0; kt < K; kt += BKs) {
        float4 av = *(const float4*)Aptr;  Aptr += BKs;
        float4 bv = *(const float4*)Bptr;  Bptr += (size_t)BKs * N;
        As[aK+0][aM] = av.x; As[aK+1][aM] = av.y;
        As[aK+2][aM] = av.z; As[aK+3][aM] = av.w;
        *(float4*)&Bs2[bK][bN] = bv;
        __syncthreads();
        float ar[8], br[8];
#pragma unroll
        for (int k = 0; k < BKs; k++) {
#pragma unroll
            for (int i = 0; i < 8; i++) ar[i] = As[k][ty*8 + i];
#pragma unroll
            for (int j = 0; j < 8; j++) br[j] = Bs2[k][tx*8 + j];
#pragma unroll
            for (int i = 0; i < 8; i++)
#pragma unroll
                for (int j = 0; j < 8; j++)
                    acc[i][j] = fmaf(ar[i], br[j], acc[i][j]);
        }
        __syncthreads();
    }
#pragma unroll
    for (int i = 0; i < 8; i++) {
        float* Crow = C + (size_t)(mBase + ty*8 + i) * N + nBase + tx*8;
#pragma unroll
        for (int j = 0; j < 8; j++) Crow[j] = acc[i][j];
    }
}

// ======================= gate / mix ========================================
__global__ void gate_finalize_kernel(const float* __restrict__ gw,
                                     const float* __restrict__ gb) {
    int r = blockIdx.x * blockDim.x + threadIdx.x;
    if (r >= Rr) return;
    const float inv = 1.f / (float)Vv;
    float mean0 = g_rs[0][r] * inv;
    float std0  = sqrtf(fmaxf(g_rss[0][r] * inv - mean0*mean0, 0.f));
    float max0  = fdec(g_rmx[0][r]);
    float mean1 = g_rs[1][r] * inv;
    float std1  = sqrtf(fmaxf(g_rss[1][r] * inv - mean1*mean1, 0.f));
    float max1  = fdec(g_rmx[1][r]);
    float z = gb[0] + gw[0]*mean0 + gw[1]*max0 + gw[2]*std0
                    + gw[3]*mean1 + gw[4]*max1 + gw[5]*std1;
    g_gate[r] = 1.f / (1.f + expf(-z));
}

__global__ void mix_kernel(float* __restrict__ out) {
    int r = blockIdx.y;
    int c4 = blockIdx.x * blockDim.x + threadIdx.x;   // 4 cols / thread
    if (c4 >= Vv/4) return;
    size_t i2 = (size_t)r * (Vv/2) + (size_t)c4 * 2;
    float g = g_gate[r], og = 1.f - g;
    __half2 a0 = ((const __half2*)g_lin)[i2], a1 = ((const __half2*)g_lin)[i2+1];
    __half2 b0 = ((const __half2*)g_loc)[i2], b1 = ((const __half2*)g_loc)[i2+1];
    float4 o;
    o.x = g*__half2float(a0.x) + og*__half2float(b0.x);
    o.y = g*__half2float(a0.y) + og*__half2float(b0.y);
    o.z = g*__half2float(a1.x) + og*__half2float(b1.x);
    o.w = g*__half2float(a1.y) + og*__half2float(b1.y);
    ((float4*)out)[(size_t)r * (Vv/4) + c4] = o;
}

// ======================= launch ============================================
extern "C" void kernel_launch(void* const* d_in, const int* in_sizes, int n_in,
                              void* d_out, int out_size) {
    const int*   tokens  = (const int*)  d_in[0];
    const float* emb     = (const float*)d_in[1];
    const float* in_proj = (const float*)d_in[2];
    const float* decays  = (const float*)d_in[3];
    const float* w1      = (const float*)d_in[4];
    const float* b1      = (const float*)d_in[5];
    const float* w2      = (const float*)d_in[6];
    const float* b2      = (const float*)d_in[7];
    const float* lw1     = (const float*)d_in[8];
    const float* lb1     = (const float*)d_in[9];
    const float* lw2     = (const float*)d_in[10];
    const float* lb2     = (const float*)d_in[11];
    const float* gate_w  = (const float*)d_in[12];
    const float* gate_b  = (const float*)d_in[13];
    float* out = (float*)d_out;

    float *gx, *gu, *grs, *grss;
    uint32_t* grmx;
    cudaGetSymbolAddress((void**)&gx,   g_x);
    cudaGetSymbolAddress((void**)&gu,   g_u);
    cudaGetSymbolAddress((void**)&grs,  g_rs);
    cudaGetSymbolAddress((void**)&grss, g_rss);
    cudaGetSymbolAddress((void**)&grmx, g_rmx);
    __half *glin, *gloc, *fh, *fl, *lih, *lil, *w1t, *lw1t, *hh, *h2h, *w2t, *lw2t;
    cudaGetSymbolAddress((void**)&glin, g_lin);
    cudaGetSymbolAddress((void**)&gloc, g_loc);
    cudaGetSymbolAddress((void**)&fh,   g_feat_hi);
    cudaGetSymbolAddress((void**)&fl,   g_feat_lo);
    cudaGetSymbolAddress((void**)&lih,  g_locin_hi);
    cudaGetSymbolAddress((void**)&lil,  g_locin_lo);
    cudaGetSymbolAddress((void**)&w1t,  g_w1t);
    cudaGetSymbolAddress((void**)&lw1t, g_lw1t);
    cudaGetSymbolAddress((void**)&hh,   g_h);
    cudaGetSymbolAddress((void**)&h2h,  g_h2);
    cudaGetSymbolAddress((void**)&w2t,  g_w2t);
    cudaGetSymbolAddress((void**)&lw2t, g_lw2t);

    constexpr int SMEMB = STAGES * STAGEB;   // 61440
    cudaFuncSetAttribute(hmma_hidden_kernel, cudaFuncAttributeMaxDynamicSharedMemorySize, SMEMB);
    cudaFuncSetAttribute(hmma_logits_kernel, cudaFuncAttributeMaxDynamicSharedMemorySize, SMEMB);

    // 1) embedding gather (+ feat hi/lo cols M..)
    gather_embed_kernel<<<Rr, Dd>>>(tokens, emb);
    // 2) u = x @ in_proj
    sgemm_kernel<<<dim3(Mm/BNs, Rr/BM), 256>>>(gx, in_proj, gu, Dd, Mm);
    // 3) decay scan -> feat hi/lo cols 0..M
    scan_kernel<<<Bb, Mm>>>(decays);
    // 4) fused window build + split
    build_loc_split_kernel<<<(Rr*Ww*Dd + 255)/256, 256>>>();
    // 5) weight conversions (all single fp16)
    wtconv_f16_kernel<<<dim3(HLh/32, F1/32),  256>>>(w1,  w1t,  F1,  HLh);
    wtconv_f16_kernel<<<dim3(HCh/32, F2/32),  256>>>(lw1, lw1t, F2,  HCh);
    wtconv_f16_kernel<<<dim3(Vv/32, HLh/32), 256>>>(w2,  w2t,  HLh, Vv);
    wtconv_f16_kernel<<<dim3(Vv/32, HCh/32), 256>>>(lw2, lw2t, HCh, Vv);
    // 6) init stats accumulators
    init_stats_kernel<<<(2*Rr + 255)/256, 256>>>();
    // 7) h = relu(feat @ w1 + b1) -> fp16  (fp16 2-pass)
    hmma_hidden_kernel<<<dim3(Rr/128, HLh/128), 128, SMEMB>>>(
        fh, fl, w1t, b1, hh, F1, HLh);
    // 8) h2 = relu(loc @ lw1 + lb1) -> fp16
    hmma_hidden_kernel<<<dim3(Rr/128, HCh/128), 128, SMEMB>>>(
        lih, lil, lw1t, lb1, h2h, F2, HCh);
    // 9) lin_logits = h @ w2 + b2 (fp16 1-pass, fp16 out, fused stats)
    hmma_logits_kernel<<<dim3(Rr/128, Vv/128), 128, SMEMB>>>(
        hh, w2t, b2, glin, grs, grss, grmx, HLh, Vv);
    // 10) loc_logits = h2 @ lw2 + lb2
    hmma_logits_kernel<<<dim3(Rr/128, Vv/128), 128, SMEMB>>>(
        h2h, lw2t, lb2, gloc, grs + Rr, grss + Rr, grmx + Rr, HCh, Vv);
    // 11) gate, mix
    gate_finalize_kernel<<<(Rr + 255)/256, 256>>>(gate_w, gate_b);
    mix_kernel<<<dim3((Vv/4 + 255)/256, Rr), 256>>>(out);
}

// round 17
// speedup vs baseline: 2.9216x; 1.0402x over previous
#include <cuda_runtime.h>
#include <cuda_fp16.h>
#include <cstdint>
#include <math.h>

#define Bb   2
#define Ss   1024
#define Vv   32000
#define Dd   256
#define Mm   256
#define Ww   8
#define HLh  1024
#define HCh  1024
#define Rr   (Bb*Ss)          // 2048
#define F1   (Mm+Dd)          // 512
#define F2   (Ww*Dd)          // 2048

// ======================= helpers ===========================================
__device__ __forceinline__ uint32_t smem_u32(const void* p) {
    uint32_t a;
    asm("{ .reg .u64 t; cvta.to.shared.u64 t, %1; cvt.u32.u64 %0, t; }" : "=r"(a) : "l"(p));
    return a;
}
#define CP_ASYNC16(dst, src) \
    asm volatile("cp.async.cg.shared.global [%0], [%1], 16;" :: "r"(dst), "l"(src))
#define CP_COMMIT() asm volatile("cp.async.commit_group;" ::: "memory")
#define CP_WAIT(n)  asm volatile("cp.async.wait_group %0;" :: "n"(n) : "memory")
#define STG_CS32(p, v) \
    asm volatile("st.global.cs.b32 [%0], %1;" :: "l"(p), "r"(v) : "memory")

__device__ __forceinline__ void ldmx4(uint32_t* r, uint32_t addr) {
    asm volatile("ldmatrix.sync.aligned.m8n8.x4.shared.b16 {%0,%1,%2,%3}, [%4];"
        : "=r"(r[0]), "=r"(r[1]), "=r"(r[2]), "=r"(r[3]) : "r"(addr));
}
__device__ __forceinline__ void mma_f16(float* c, const uint32_t* a, const uint32_t* b) {
    asm volatile(
        "mma.sync.aligned.m16n8k16.row.col.f32.f16.f16.f32 "
        "{%0,%1,%2,%3}, {%4,%5,%6,%7}, {%8,%9}, {%0,%1,%2,%3};"
        : "+f"(c[0]), "+f"(c[1]), "+f"(c[2]), "+f"(c[3])
        : "r"(a[0]), "r"(a[1]), "r"(a[2]), "r"(a[3]), "r"(b[0]), "r"(b[1]));
}
// monotonic float<->uint encode for atomicMax over signed floats
__device__ __forceinline__ uint32_t fenc(float f) {
    uint32_t i = __float_as_uint(f);
    return (i & 0x80000000u) ? ~i : (i | 0x80000000u);
}
__device__ __forceinline__ float fdec(uint32_t u) {
    return (u & 0x80000000u) ? __uint_as_float(u & 0x7FFFFFFFu) : __uint_as_float(~u);
}
__device__ __forceinline__ uint32_t pack_h2(float a, float b) {
    __half2 h{__float2half_rn(a), __float2half_rn(b)};
    return *reinterpret_cast<uint32_t*>(&h);
}

// ======================= scratch ===========================================
__device__ float g_x[Rr*Dd];
__device__ float g_u[Rr*Mm];
__device__ float g_gate[Rr];
__device__ float    g_rs[2][Rr];
__device__ float    g_rss[2][Rr];
__device__ uint32_t g_rmx[2][Rr];
// fp16 logits intermediates
__device__ __half g_lin[(size_t)Rr*Vv];
__device__ __half g_loc[(size_t)Rr*Vv];
// fp16 operands (single precision level everywhere)
__device__ __half g_feat[Rr*F1];
__device__ __half g_locin[Rr*F2];
__device__ __half g_w1t[HLh*F1];
__device__ __half g_lw1t[HCh*F2];
__device__ __half g_h[Rr*HLh];
__device__ __half g_h2[Rr*HCh];
__device__ __half g_w2t[(size_t)Vv*HLh];
__device__ __half g_lw2t[(size_t)Vv*HCh];

// ======================= small kernels =====================================
__global__ void gather_embed_kernel(const int* __restrict__ tok,
                                    const float* __restrict__ emb) {
    int r = blockIdx.x, d = threadIdx.x;
    float v = emb[(size_t)tok[r] * Dd + d];
    g_x[r*Dd + d] = v;
    g_feat[(size_t)r*F1 + Mm + d] = __float2half_rn(v);
}

__global__ void scan_kernel(const float* __restrict__ decays) {
    int b = blockIdx.x, m = threadIdx.x;
    float a = decays[m], s = 0.f;
    for (int t = 0; t < Ss; t++) {
        int r = b*Ss + t;
        s = a*s + g_u[(size_t)r*Mm + m];
        g_feat[(size_t)r*F1 + m] = __float2half_rn(s);
    }
}

__global__ void build_loc_kernel() {
    int idx = blockIdx.x * blockDim.x + threadIdx.x;
    if (idx >= Rr*Ww*Dd) return;
    int d = idx % Dd, w = (idx / Dd) % Ww, r = idx / (Ww*Dd);
    int s = r % Ss, b = r / Ss;
    int ss = s - (Ww-1) + w;
    float v = (ss >= 0) ? g_x[((size_t)(b*Ss + ss))*Dd + d] : 0.f;
    g_locin[idx] = __float2half_rn(v);
}

// transpose: W[K,N] fp32 -> Wt [N,K] single fp16
__global__ void wtconv_f16_kernel(const float* __restrict__ W,
                                  __half* __restrict__ hi, int K, int N) {
    __shared__ float t[32][33];
    int n0 = blockIdx.x * 32, k0 = blockIdx.y * 32;
    int tx = threadIdx.x & 31, ty = threadIdx.x >> 5;
#pragma unroll
    for (int r = 0; r < 4; r++)
        t[ty + 8*r][tx] = W[(size_t)(k0 + ty + 8*r) * N + n0 + tx];
    __syncthreads();
#pragma unroll
    for (int r = 0; r < 4; r++) {
        int n = n0 + ty + 8*r, k = k0 + tx;
        hi[(size_t)n*K + k] = __float2half_rn(t[tx][ty + 8*r]);
    }
}

__global__ void init_stats_kernel() {
    int i = blockIdx.x * blockDim.x + threadIdx.x;
    if (i >= 2*Rr) return;
    ((float*)g_rs)[i] = 0.f;
    ((float*)g_rss)[i] = 0.f;
    ((uint32_t*)g_rmx)[i] = 0u;
}

// ===== HMMA GEMM, CTA 128x128, 128 thr / 4 warps (2Mx2N), warp 64x64 =======
#define STAGES 3
#define ROWB   80
#define ABYTES (128*ROWB)
#define STAGEB (2*ABYTES)

// hidden: fp16 1-pass, ReLU -> fp16
__global__ void __launch_bounds__(128, 2) hmma_hidden_kernel(
        const __half* __restrict__ A,
        const __half* __restrict__ Bw,
        const float* __restrict__ bias,
        __half* __restrict__ Chi,
        int K, int Ntot) {
    extern __shared__ char smem[];
    const uint32_t sb = smem_u32(smem);
    const int tid = threadIdx.x;
    const int wid = tid >> 5, lid = tid & 31;
    const int wm = wid & 1, wn = wid >> 1;          // 2 M x 2 N
    const int mBase = blockIdx.x * 128;
    const int nBase = blockIdx.y * 128;

    const int NC = K / 32;

    float acc[4][8][4];
#pragma unroll
    for (int i = 0; i < 4; i++)
#pragma unroll
        for (int j = 0; j < 8; j++)
#pragma unroll
            for (int q = 0; q < 4; q++) acc[i][j][q] = 0.f;

    auto load_tile = [&](int c, int s) {
        int kof = c * 32;
        uint32_t ab = sb + s * STAGEB;
        uint32_t bb = ab + ABYTES;
#pragma unroll
        for (int i = 0; i < 4; i++) {
            int id = tid + i * 128;
            int row = id >> 2, q = id & 3;
            CP_ASYNC16(ab + row*ROWB + q*16,
                       A + (size_t)(mBase + row) * K + kof + q*8);
        }
#pragma unroll
        for (int i = 0; i < 4; i++) {
            int id = tid + i * 128;
            int row = id >> 2, q = id & 3;
            CP_ASYNC16(bb + row*ROWB + q*16,
                       Bw + (size_t)(nBase + row) * K + kof + q*8);
        }
    };

#pragma unroll
    for (int s = 0; s < STAGES - 1; s++) { load_tile(s, s); CP_COMMIT(); }

    const int aRow = (lid & 7) + ((lid >> 3) & 1) * 8;
    const int aKb  = (lid >> 4) * 16;
    const int bRow = (lid & 7) + ((lid >> 4) & 1) * 8;
    const int bKb  = ((lid >> 3) & 1) * 16;

    for (int c = 0; c < NC; c++) {
        CP_WAIT(STAGES - 2);
        __syncthreads();
        if (c + STAGES - 1 < NC) load_tile(c + STAGES - 1, (c + STAGES - 1) % STAGES);
        CP_COMMIT();

        uint32_t ab = sb + (c % STAGES) * STAGEB;
        uint32_t bb = ab + ABYTES;
#pragma unroll
        for (int ks = 0; ks < 2; ks++) {
            uint32_t afr[4][4], bfr[4][4];
#pragma unroll
            for (int i = 0; i < 4; i++)
                ldmx4(afr[i], ab + (wm*64 + i*16 + aRow)*ROWB + ks*32 + aKb);
#pragma unroll
            for (int t = 0; t < 4; t++)
                ldmx4(bfr[t], bb + (wn*64 + t*16 + bRow)*ROWB + ks*32 + bKb);
#pragma unroll
            for (int i = 0; i < 4; i++)
#pragma unroll
                for (int j = 0; j < 8; j++)
                    mma_f16(acc[i][j], afr[i], bfr[j >> 1] + (j & 1) * 2);
        }
    }
    CP_WAIT(0);

    const int r0 = lid >> 2;
    const int c0 = (lid & 3) * 2;
#pragma unroll
    for (int i = 0; i < 4; i++) {
#pragma unroll
        for (int j = 0; j < 8; j++) {
            int col = nBase + wn*64 + j*8 + c0;
            int rowA = mBase + wm*64 + i*16 + r0;
            float2 bv = *(const float2*)(bias + col);
            float v0 = fmaxf(acc[i][j][0] + bv.x, 0.f);
            float v1 = fmaxf(acc[i][j][1] + bv.y, 0.f);
            float v2 = fmaxf(acc[i][j][2] + bv.x, 0.f);
            float v3 = fmaxf(acc[i][j][3] + bv.y, 0.f);
            *(uint32_t*)(Chi + (size_t)rowA * Ntot + col)     = pack_h2(v0, v1);
            *(uint32_t*)(Chi + (size_t)(rowA+8) * Ntot + col) = pack_h2(v2, v3);
        }
    }
}

// logits: fp16 1-pass; fp16 out + fused row stats. gridDim.z selects branch.
__global__ void __launch_bounds__(128, 2) hmma_logits_kernel(
        const __half* __restrict__ A0, const __half* __restrict__ A1,
        const __half* __restrict__ B0, const __half* __restrict__ B1,
        const float* __restrict__ bias0, const float* __restrict__ bias1,
        __half* __restrict__ C0, __half* __restrict__ C1,
        float* __restrict__ rs_, float* __restrict__ rss_, uint32_t* __restrict__ rmx_,
        int K, int Ntot) {
    extern __shared__ char smem[];
    const uint32_t sb = smem_u32(smem);
    const int tid = threadIdx.x;
    const int wid = tid >> 5, lid = tid & 31;
    const int wm = wid & 1, wn = wid >> 1;          // 2 M x 2 N
    const int mBase = blockIdx.x * 128;
    const int nBase = blockIdx.y * 128;
    const int z = blockIdx.z;

    const __half* A   = z ? A1 : A0;
    const __half* Bw  = z ? B1 : B0;
    const float* bias = z ? bias1 : bias0;
    __half* Cf        = z ? C1 : C0;
    float* rs         = rs_  + z * Rr;
    float* rss        = rss_ + z * Rr;
    uint32_t* rmx     = rmx_ + z * Rr;

    const int NC = K / 32;          // single pass

    float acc[4][8][4];
#pragma unroll
    for (int i = 0; i < 4; i++)
#pragma unroll
        for (int j = 0; j < 8; j++)
#pragma unroll
            for (int q = 0; q < 4; q++) acc[i][j][q] = 0.f;

    auto load_tile = [&](int c, int s) {
        int kof = c * 32;
        uint32_t ab = sb + s * STAGEB;
        uint32_t bb = ab + ABYTES;
#pragma unroll
        for (int i = 0; i < 4; i++) {
            int id = tid + i * 128;
            int row = id >> 2, q = id & 3;
            CP_ASYNC16(ab + row*ROWB + q*16,
                       A + (size_t)(mBase + row) * K + kof + q*8);
        }
#pragma unroll
        for (int i = 0; i < 4; i++) {
            int id = tid + i * 128;
            int row = id >> 2, q = id & 3;
            CP_ASYNC16(bb + row*ROWB + q*16,
                       Bw + (size_t)(nBase + row) * K + kof + q*8);
        }
    };

#pragma unroll
    for (int s = 0; s < STAGES - 1; s++) { load_tile(s, s); CP_COMMIT(); }

    const int aRow = (lid & 7) + ((lid >> 3) & 1) * 8;
    const int aKb  = (lid >> 4) * 16;
    const int bRow = (lid & 7) + ((lid >> 4) & 1) * 8;
    const int bKb  = ((lid >> 3) & 1) * 16;

    for (int c = 0; c < NC; c++) {
        CP_WAIT(STAGES - 2);
        __syncthreads();
        if (c + STAGES - 1 < NC) load_tile(c + STAGES - 1, (c + STAGES - 1) % STAGES);
        CP_COMMIT();

        uint32_t ab = sb + (c % STAGES) * STAGEB;
        uint32_t bb = ab + ABYTES;
#pragma unroll
        for (int ks = 0; ks < 2; ks++) {
            uint32_t afr[4][4], bfr[4][4];
#pragma unroll
            for (int i = 0; i < 4; i++)
                ldmx4(afr[i], ab + (wm*64 + i*16 + aRow)*ROWB + ks*32 + aKb);
#pragma unroll
            for (int t = 0; t < 4; t++)
                ldmx4(bfr[t], bb + (wn*64 + t*16 + bRow)*ROWB + ks*32 + bKb);
#pragma unroll
            for (int i = 0; i < 4; i++)
#pragma unroll
                for (int j = 0; j < 8; j++)
                    mma_f16(acc[i][j], afr[i], bfr[j >> 1] + (j & 1) * 2);
        }
    }
    CP_WAIT(0);

    const int r0 = lid >> 2;
    const int c0 = (lid & 3) * 2;
    float ps[8], pq[8], pm[8];
#pragma unroll
    for (int t = 0; t < 8; t++) { ps[t] = 0.f; pq[t] = 0.f; pm[t] = -3.4e38f; }

#pragma unroll
    for (int i = 0; i < 4; i++) {
#pragma unroll
        for (int j = 0; j < 8; j++) {
            int col = nBase + wn*64 + j*8 + c0;
            int rowA = mBase + wm*64 + i*16 + r0;
            float2 bv = *(const float2*)(bias + col);
            float v0 = acc[i][j][0] + bv.x, v1 = acc[i][j][1] + bv.y;
            float v2 = acc[i][j][2] + bv.x, v3 = acc[i][j][3] + bv.y;
            STG_CS32(Cf + (size_t)rowA * Ntot + col,       pack_h2(v0, v1));
            STG_CS32(Cf + (size_t)(rowA + 8) * Ntot + col, pack_h2(v2, v3));
            ps[2*i]   += v0 + v1;  pq[2*i]   += v0*v0 + v1*v1;
            pm[2*i]    = fmaxf(pm[2*i], fmaxf(v0, v1));
            ps[2*i+1] += v2 + v3;  pq[2*i+1] += v2*v2 + v3*v3;
            pm[2*i+1]  = fmaxf(pm[2*i+1], fmaxf(v2, v3));
        }
    }
#pragma unroll
    for (int t = 0; t < 8; t++) {
#pragma unroll
        for (int m = 1; m <= 2; m <<= 1) {
            ps[t] += __shfl_xor_sync(0xffffffffu, ps[t], m);
            pq[t] += __shfl_xor_sync(0xffffffffu, pq[t], m);
            pm[t]  = fmaxf(pm[t], __shfl_xor_sync(0xffffffffu, pm[t], m));
        }
    }
    if ((lid & 3) == 0) {
#pragma unroll
        for (int t = 0; t < 8; t++) {
            int row = mBase + wm*64 + (t >> 1)*16 + r0 + (t & 1)*8;
            atomicAdd(rs + row, ps[t]);
            atomicAdd(rss + row, pq[t]);
            atomicMax(rmx + row, fenc(pm[t]));
        }
    }
}

// ======================= fp32 SGEMM (small u GEMM only) ====================
#define BM 128
#define BNs 128
#define BKs 8
__global__ void __launch_bounds__(256) sgemm_kernel(
        const float* __restrict__ A, const float* __restrict__ Bm,
        float* __restrict__ C, int K, int N) {
    __shared__ float As[BKs][BM];
    __shared__ float Bs2[BKs][BNs];
    int tid = threadIdx.x;
    int tx = tid & 15, ty = tid >> 4;
    int mBase = blockIdx.y * BM, nBase = blockIdx.x * BNs;
    int aM = tid >> 1, aK = (tid & 1) * 4;
    int bK = tid >> 5, bN = (tid & 31) * 4;
    const float* Aptr = A + (size_t)(mBase + aM) * K + aK;
    const float* Bptr = Bm + (size_t)bK * N + nBase + bN;
    float acc[8][8];
#pragma unroll
    for (int i = 0; i < 8; i++)
#pragma unroll
        for (int j = 0; j < 8; j++) acc[i][j] = 0.f;
    for (int kt = 0; kt < K; kt += BKs) {
        float4 av = *(const float4*)Aptr;  Aptr += BKs;
        float4 bv = *(const float4*)Bptr;  Bptr += (size_t)BKs * N;
        As[aK+0][aM] = av.x; As[aK+1][aM] = av.y;
        As[aK+2][aM] = av.z; As[aK+3][aM] = av.w;
        *(float4*)&Bs2[bK][bN] = bv;
        __syncthreads();
        float ar[8], br[8];
#pragma unroll
        for (int k = 0; k < BKs; k++) {
#pragma unroll
            for (int i = 0; i < 8; i++) ar[i] = As[k][ty*8 + i];
#pragma unroll
            for (int j = 0; j < 8; j++) br[j] = Bs2[k][tx*8 + j];
#pragma unroll
            for (int i = 0; i < 8; i++)
#pragma unroll
                for (int j = 0; j < 8; j++)
                    acc[i][j] = fmaf(ar[i], br[j], acc[i][j]);
        }
        __syncthreads();
    }
#pragma unroll
    for (int i = 0; i < 8; i++) {
        float* Crow = C + (size_t)(mBase + ty*8 + i) * N + nBase + tx*8;
#pragma unroll
        for (int j = 0; j < 8; j++) Crow[j] = acc[i][j];
    }
}

// ======================= gate / mix ========================================
__global__ void gate_finalize_kernel(const float* __restrict__ gw,
                                     const float* __restrict__ gb) {
    int r = blockIdx.x * blockDim.x + threadIdx.x;
    if (r >= Rr) return;
    const float inv = 1.f / (float)Vv;
    float mean0 = g_rs[0][r] * inv;
    float std0  = sqrtf(fmaxf(g_rss[0][r] * inv - mean0*mean0, 0.f));
    float max0  = fdec(g_rmx[0][r]);
    float mean1 = g_rs[1][r] * inv;
    float std1  = sqrtf(fmaxf(g_rss[1][r] * inv - mean1*mean1, 0.f));
    float max1  = fdec(g_rmx[1][r]);
    float z = gb[0] + gw[0]*mean0 + gw[1]*max0 + gw[2]*std0
                    + gw[3]*mean1 + gw[4]*max1 + gw[5]*std1;
    g_gate[r] = 1.f / (1.f + expf(-z));
}

__global__ void mix_kernel(float* __restrict__ out) {
    int r = blockIdx.y;
    int c4 = blockIdx.x * blockDim.x + threadIdx.x;   // 4 cols / thread
    if (c4 >= Vv/4) return;
    size_t i2 = (size_t)r * (Vv/2) + (size_t)c4 * 2;
    float g = g_gate[r], og = 1.f - g;
    __half2 a0 = ((const __half2*)g_lin)[i2], a1 = ((const __half2*)g_lin)[i2+1];
    __half2 b0 = ((const __half2*)g_loc)[i2], b1 = ((const __half2*)g_loc)[i2+1];
    float4 o;
    o.x = g*__half2float(a0.x) + og*__half2float(b0.x);
    o.y = g*__half2float(a0.y) + og*__half2float(b0.y);
    o.z = g*__half2float(a1.x) + og*__half2float(b1.x);
    o.w = g*__half2float(a1.y) + og*__half2float(b1.y);
    ((float4*)out)[(size_t)r * (Vv/4) + c4] = o;
}

// ======================= launch ============================================
extern "C" void kernel_launch(void* const* d_in, const int* in_sizes, int n_in,
                              void* d_out, int out_size) {
    const int*   tokens  = (const int*)  d_in[0];
    const float* emb     = (const float*)d_in[1];
    const float* in_proj = (const float*)d_in[2];
    const float* decays  = (const float*)d_in[3];
    const float* w1      = (const float*)d_in[4];
    const float* b1      = (const float*)d_in[5];
    const float* w2      = (const float*)d_in[6];
    const float* b2      = (const float*)d_in[7];
    const float* lw1     = (const float*)d_in[8];
    const float* lb1     = (const float*)d_in[9];
    const float* lw2     = (const float*)d_in[10];
    const float* lb2     = (const float*)d_in[11];
    const float* gate_w  = (const float*)d_in[12];
    const float* gate_b  = (const float*)d_in[13];
    float* out = (float*)d_out;

    float *gx, *gu, *grs, *grss;
    uint32_t* grmx;
    cudaGetSymbolAddress((void**)&gx,   g_x);
    cudaGetSymbolAddress((void**)&gu,   g_u);
    cudaGetSymbolAddress((void**)&grs,  g_rs);
    cudaGetSymbolAddress((void**)&grss, g_rss);
    cudaGetSymbolAddress((void**)&grmx, g_rmx);
    __half *glin, *gloc, *gfeat, *glocin, *w1t, *lw1t, *hh, *h2h, *w2t, *lw2t;
    cudaGetSymbolAddress((void**)&glin,   g_lin);
    cudaGetSymbolAddress((void**)&gloc,   g_loc);
    cudaGetSymbolAddress((void**)&gfeat,  g_feat);
    cudaGetSymbolAddress((void**)&glocin, g_locin);
    cudaGetSymbolAddress((void**)&w1t,    g_w1t);
    cudaGetSymbolAddress((void**)&lw1t,   g_lw1t);
    cudaGetSymbolAddress((void**)&hh,     g_h);
    cudaGetSymbolAddress((void**)&h2h,    g_h2);
    cudaGetSymbolAddress((void**)&w2t,    g_w2t);
    cudaGetSymbolAddress((void**)&lw2t,   g_lw2t);

    constexpr int SMEMB = STAGES * STAGEB;   // 61440
    cudaFuncSetAttribute(hmma_hidden_kernel, cudaFuncAttributeMaxDynamicSharedMemorySize, SMEMB);
    cudaFuncSetAttribute(hmma_logits_kernel, cudaFuncAttributeMaxDynamicSharedMemorySize, SMEMB);

    // 1) embedding gather (+ feat cols M..)
    gather_embed_kernel<<<Rr, Dd>>>(tokens, emb);
    // 2) u = x @ in_proj
    sgemm_kernel<<<dim3(Mm/BNs, Rr/BM), 256>>>(gx, in_proj, gu, Dd, Mm);
    // 3) decay scan -> feat cols 0..M
    scan_kernel<<<Bb, Mm>>>(decays);
    // 4) window build -> fp16
    build_loc_kernel<<<(Rr*Ww*Dd + 255)/256, 256>>>();
    // 5) weight conversions (all single fp16)
    wtconv_f16_kernel<<<dim3(HLh/32, F1/32),  256>>>(w1,  w1t,  F1,  HLh);
    wtconv_f16_kernel<<<dim3(HCh/32, F2/32),  256>>>(lw1, lw1t, F2,  HCh);
    wtconv_f16_kernel<<<dim3(Vv/32, HLh/32), 256>>>(w2,  w2t,  HLh, Vv);
    wtconv_f16_kernel<<<dim3(Vv/32, HCh/32), 256>>>(lw2, lw2t, HCh, Vv);
    // 6) init stats accumulators
    init_stats_kernel<<<(2*Rr + 255)/256, 256>>>();
    // 7) h = relu(feat @ w1 + b1) -> fp16  (1-pass)
    hmma_hidden_kernel<<<dim3(Rr/128, HLh/128), 128, SMEMB>>>(
        gfeat, w1t, b1, hh, F1, HLh);
    // 8) h2 = relu(loc @ lw1 + lb1) -> fp16
    hmma_hidden_kernel<<<dim3(Rr/128, HCh/128), 128, SMEMB>>>(
        glocin, lw1t, lb1, h2h, F2, HCh);
    // 9+10) both logits GEMMs in one launch (z = branch), fused stats
    hmma_logits_kernel<<<dim3(Rr/128, Vv/128, 2), 128, SMEMB>>>(
        hh, h2h, w2t, lw2t, b2, lb2, glin, gloc,
        grs, grss, grmx, HLh, Vv);
    // 11) gate, mix
    gate_finalize_kernel<<<(Rr + 255)/256, 256>>>(gate_w, gate_b);
    mix_kernel<<<dim3((Vv/4 + 255)/256, Rr), 256>>>(out);
}